// round 9
// baseline (speedup 1.0000x reference)
#include <cuda_runtime.h>
#include <math.h>

#define NDOM 4
#define SQRT2F 1.41421356237309515f
#define EPS_REEIG_F 1e-4f
#define EPS_VAR_F 1e-5f

#define MAXB 32768
#define NB_MAX 1024
#define WPB 8            // warps per block
#define MPW 4            // matrices per warp
#define MPB (WPB*MPW)    // 32 matrices per block

#define LDC 20           // column stride (floats) for col-major matrices
#define SW_PS20 5        // per-sample 20x20 (k_center)
#define SW_AVG20 3       // averaged-output 20x20 (k_logsum) — averaging attenuates truncation
#define SW_PS15 5        // per-sample 15x15 (k_head)
#define SW_AVG15 4       // averaged-output 15x15 (k_bimap)
#define SW_SMALL 7

#define NSPLIT 64        // sample splits for domain reduction
#define NCHUNK 4         // 128-float element chunks (covers 400)

// ---------------- device scratch (static, allowed) ----------------
__device__ float g_V2[(size_t)MAXB * 400];   // k_logsum: per-sample L; later: eigenvectors of centered matrices
__device__ float g_lw2[(size_t)MAXB * 20];   // log-eigenvalues of centered matrices
__device__ float g_Y[(size_t)MAXB * 240];    // BiMap outputs, rows padded to 16
__device__ float g_part2[(size_t)NCHUNK * NSPLIT * NDOM * 128];
__device__ float g_partCnt[NSPLIT * NDOM];
__device__ float g_partN[NB_MAX * NDOM];
__device__ float g_partLY[NB_MAX * 225];
__device__ float g_cnt[NDOM];
__device__ float g_Ginv[NDOM * 400];
__device__ float g_scale[NDOM];
__device__ float g_Gb16[240];                // 15x16 padded

// ---------------- per-warp workspace ----------------
struct WarpWS {
    __align__(16) float A[400];   // col-major, LDC=20
    __align__(16) float V[400];   // col-major, LDC=20
    __align__(16) float4 prm[12]; // (c, s, p, q) packed
    float aux[24];
};

// round-robin tournament pair (circle method), players 0..NS-1, NS even
__device__ __forceinline__ void pair_pq(int k, int r, int M, int& p, int& q) {
    p = (k == 0) ? 0 : (1 + (k - 1 + r) % M);
    q = 1 + (M - 1 - k + r) % M;
}

// Warp-cooperative two-sided Jacobi, column-major A (stride LDC), V columns = eigenvectors.
// Single-pass 2x2 tile update fused with V column rotations in ONE indexed loop:
// all NT tile items and NP*CH V-chunk items are mutually independent within a round,
// so packing them together raises lane utilization (n=20: 6 slots -> 5).
// N odd uses NS=N+1 with a zero dummy row/col (caller zero-pads A row/col N).
template<int N, int SWEEPS>
__device__ void jacobi_cm(WarpWS* w, int lane) {
    constexpr int NS  = (N + 1) & ~1;
    constexpr int M   = NS - 1;
    constexpr int NP  = NS / 2;
    constexpr int NT  = NP * NP;
    constexpr int CH  = NS / 4;    // float4 chunks per V column
    constexpr int TOT = NT + NP * CH;
    float* A = w->A;
    float* V = w->V;
    float4* prm = w->prm;

    for (int i = lane; i < NS * LDC; i += 32) V[i] = 0.0f;
    __syncwarp();
    if (lane < NS) V[lane * LDC + lane] = 1.0f;
    __syncwarp();

    for (int sw = 0; sw < SWEEPS; sw++)
    for (int r = 0; r < M; r++) {
        // ---- rotation parameters (NP disjoint pairs) ----
        if (lane < NP) {
            int p, q; pair_pq(lane, r, M, p, q);
            float apq = A[q * LDC + p];
            float c = 1.0f, s = 0.0f;
            if (fabsf(apq) > 1e-38f) {
                float app = A[p * LDC + p];
                float aqq = A[q * LDC + q];
                float tau = (aqq - app) / (2.0f * apq);
                float den = fabsf(tau) + sqrtf(fmaf(tau, tau, 1.0f));
                float tt  = (tau >= 0.0f ? 1.0f : -1.0f) / den;
                c = rsqrtf(fmaf(tt, tt, 1.0f));
                s = tt * c;
            }
            prm[lane] = make_float4(c, s, __int_as_float(p), __int_as_float(q));
        }
        __syncwarp();
        // ---- fused work loop: A-tile updates (idx < NT) + V rotations (rest) ----
        #pragma unroll
        for (int t = 0; t < (TOT + 31) / 32; t++) {
            int idx = lane + 32 * t;
            if (idx < NT) {
                int ki = idx / NP, kj = idx - ki * NP;
                float4 pi4 = prm[ki], pj4 = prm[kj];
                float ci = pi4.x, si = pi4.y;
                int pi = __float_as_int(pi4.z), qi = __float_as_int(pi4.w);
                float cj = pj4.x, sj = pj4.y;
                int pj = __float_as_int(pj4.z), qj = __float_as_int(pj4.w);
                float a00 = A[pj * LDC + pi], a01 = A[qj * LDC + pi];
                float a10 = A[pj * LDC + qi], a11 = A[qj * LDC + qi];
                float r00 = fmaf(ci, a00, -si * a10), r10 = fmaf(si, a00, ci * a10);
                float r01 = fmaf(ci, a01, -si * a11), r11 = fmaf(si, a01, ci * a11);
                A[pj * LDC + pi] = fmaf(cj, r00, -sj * r01);
                A[qj * LDC + pi] = fmaf(sj, r00,  cj * r01);
                A[pj * LDC + qi] = fmaf(cj, r10, -sj * r11);
                A[qj * LDC + qi] = fmaf(sj, r10,  cj * r11);
            } else if (idx < TOT) {
                int vidx = idx - NT;
                int k = vidx / CH, ch = vidx - k * CH;
                float4 pr = prm[k];
                float c = pr.x, s = pr.y;
                int p = __float_as_int(pr.z), q = __float_as_int(pr.w);
                float4 vp = *(reinterpret_cast<float4*>(V + p * LDC) + ch);
                float4 vq = *(reinterpret_cast<float4*>(V + q * LDC) + ch);
                float4 np, nq;
                np.x = fmaf(c, vp.x, -s * vq.x); nq.x = fmaf(s, vp.x, c * vq.x);
                np.y = fmaf(c, vp.y, -s * vq.y); nq.y = fmaf(s, vp.y, c * vq.y);
                np.z = fmaf(c, vp.z, -s * vq.z); nq.z = fmaf(s, vp.z, c * vq.z);
                np.w = fmaf(c, vp.w, -s * vq.w); nq.w = fmaf(s, vp.w, c * vq.w);
                *(reinterpret_cast<float4*>(V + p * LDC) + ch) = np;
                *(reinterpret_cast<float4*>(V + q * LDC) + ch) = nq;
            }
        }
        __syncwarp();
    }
}

// ---------- float4 dot / axpy helpers ----------
__device__ __forceinline__ float dot20(const float* row, const float* g) {
    const float4* r4 = (const float4*)row;
    float a = 0.0f;
    #pragma unroll
    for (int t = 0; t < 5; t++) {
        float4 x = r4[t];
        a = fmaf(x.x, g[4*t+0], a); a = fmaf(x.y, g[4*t+1], a);
        a = fmaf(x.z, g[4*t+2], a); a = fmaf(x.w, g[4*t+3], a);
    }
    return a;
}
__device__ __forceinline__ float dot16(const float* row, const float* g) {
    const float4* r4 = (const float4*)row;
    float a = 0.0f;
    #pragma unroll
    for (int t = 0; t < 4; t++) {
        float4 x = r4[t];
        a = fmaf(x.x, g[4*t+0], a); a = fmaf(x.y, g[4*t+1], a);
        a = fmaf(x.z, g[4*t+2], a); a = fmaf(x.w, g[4*t+3], a);
    }
    return a;
}
__device__ __forceinline__ void axpy20(float u, const float* col, float* l) {
    const float4* c4 = (const float4*)col;
    #pragma unroll
    for (int t = 0; t < 5; t++) {
        float4 x = c4[t];
        l[4*t+0] = fmaf(u, x.x, l[4*t+0]); l[4*t+1] = fmaf(u, x.y, l[4*t+1]);
        l[4*t+2] = fmaf(u, x.z, l[4*t+2]); l[4*t+3] = fmaf(u, x.w, l[4*t+3]);
    }
}
__device__ __forceinline__ void axpy16(float u, const float* col, float* l) {
    const float4* c4 = (const float4*)col;
    #pragma unroll
    for (int t = 0; t < 4; t++) {
        float4 x = c4[t];
        l[4*t+0] = fmaf(u, x.x, l[4*t+0]); l[4*t+1] = fmaf(u, x.y, l[4*t+1]);
        l[4*t+2] = fmaf(u, x.z, l[4*t+2]); l[4*t+3] = fmaf(u, x.w, l[4*t+3]);
    }
}

// scalar recompose for tiny kernels: Out[i*N+j] = sum_k V[i,k] fw[k] V[j,k]
template<int N>
__device__ __forceinline__ void recompose_cm(const float* V, const float* fw,
                                             float* Out, int lane) {
    #pragma unroll
    for (int t = 0; t < (N * N + 31) / 32; t++) {
        int idx = lane + 32 * t;
        if (idx < N * N) {
            int i = idx / N, j = idx - i * N;
            float acc = 0.0f;
            #pragma unroll
            for (int k = 0; k < N; k++)
                acc = fmaf(V[k * LDC + i] * fw[k], V[k * LDC + j], acc);
            Out[idx] = acc;
        }
    }
}

// ============ K1: per-sample logm(X) -> g_V2 (as L scratch) ============
__global__ void __launch_bounds__(256) k_logsum(const float* __restrict__ X, int B) {
    __shared__ WarpWS ws[WPB];
    int tid = threadIdx.x, warp = tid >> 5, lane = tid & 31;
    WarpWS* w = &ws[warp];
    for (int m = 0; m < MPW; m++) {
        int b = ((int)blockIdx.x * WPB + warp) * MPW + m;
        if (b >= B) continue;
        const float4* Xb4 = (const float4*)(X + (size_t)b * 400);
        for (int idx = lane; idx < 100; idx += 32) ((float4*)w->A)[idx] = Xb4[idx];
        __syncwarp();
        jacobi_cm<20, SW_AVG20>(w, lane);
        if (lane < 20) w->aux[lane] = logf(w->A[lane * LDC + lane]);
        __syncwarp();
        if (lane < 20) {
            float rv[20];
            #pragma unroll
            for (int k = 0; k < 20; k++) rv[k] = w->aux[k] * w->V[k * LDC + lane];
            float l[20];
            #pragma unroll
            for (int i = 0; i < 20; i++) l[i] = 0.0f;
            #pragma unroll
            for (int k = 0; k < 20; k++) axpy20(rv[k], w->V + k * LDC, l);
            float4* Lb = (float4*)(g_V2 + (size_t)b * 400 + lane * 20);
            #pragma unroll
            for (int t = 0; t < 5; t++)
                Lb[t] = make_float4(l[4*t], l[4*t+1], l[4*t+2], l[4*t+3]);
        }
        __syncwarp();
    }
}

// ===== K1b: deterministic domain-segmented sum of L over samples =====
__global__ void __launch_bounds__(256) kr_dsum(const int* __restrict__ dom, int B) {
    int warp = threadIdx.x >> 5, lane = threadIdx.x & 31;
    int c = blockIdx.x & 3;                    // element chunk
    int split = ((int)blockIdx.x >> 2) * 8 + warp;
    int per = (B + NSPLIT - 1) / NSPLIT;
    int b0 = split * per, b1 = b0 + per;
    if (b1 > B) b1 = B;
    int e = c * 128 + lane * 4;
    bool valid = e < 400;
    float4 a0 = make_float4(0,0,0,0), a1 = a0, a2 = a0, a3 = a0;
    int cnt0 = 0, cnt1 = 0, cnt2 = 0, cnt3 = 0;
    for (int b = b0; b < b1; b++) {
        int d = dom[b];
        float4 v = make_float4(0,0,0,0);
        if (valid) v = *(const float4*)(g_V2 + (size_t)b * 400 + e);
        if (d == 0)      { a0.x += v.x; a0.y += v.y; a0.z += v.z; a0.w += v.w; cnt0++; }
        else if (d == 1) { a1.x += v.x; a1.y += v.y; a1.z += v.z; a1.w += v.w; cnt1++; }
        else if (d == 2) { a2.x += v.x; a2.y += v.y; a2.z += v.z; a2.w += v.w; cnt2++; }
        else             { a3.x += v.x; a3.y += v.y; a3.z += v.z; a3.w += v.w; cnt3++; }
    }
    if (valid) {
        size_t base = (((size_t)c * NSPLIT + split) * NDOM) * 128 + lane * 4;
        *(float4*)(g_part2 + base + 0 * 128) = a0;
        *(float4*)(g_part2 + base + 1 * 128) = a1;
        *(float4*)(g_part2 + base + 2 * 128) = a2;
        *(float4*)(g_part2 + base + 3 * 128) = a3;
    }
    if (c == 0 && lane == 0) {
        g_partCnt[split * NDOM + 0] = (float)cnt0;
        g_partCnt[split * NDOM + 1] = (float)cnt1;
        g_partCnt[split * NDOM + 2] = (float)cnt2;
        g_partCnt[split * NDOM + 3] = (float)cnt3;
    }
}

// ============ K2: reduce partials -> meanL, counts; Ginv[d] = V e^{-w/2} Vt ============
__global__ void __launch_bounds__(256) k_ginv() {
    __shared__ WarpWS ws[4];
    __shared__ float meanL[NDOM * 400];
    int tid = threadIdx.x;
    if (tid < NDOM) {
        float c = 0.0f;
        for (int sp = 0; sp < NSPLIT; sp++) c += g_partCnt[sp * NDOM + tid];
        g_cnt[tid] = c;
    }
    for (int out = tid; out < NDOM * 400; out += 256) {
        int d = out / 400, e = out - d * 400;
        int c = e >> 7, i = e & 127;
        float s = 0.0f;
        for (int sp = 0; sp < NSPLIT; sp++)
            s += g_part2[(((size_t)c * NSPLIT + sp) * NDOM + d) * 128 + i];
        meanL[out] = s;
    }
    __syncthreads();
    int warp = tid >> 5, lane = tid & 31;
    if (warp < 4) {
        int d = warp;
        float inv = 1.0f / g_cnt[d];
        WarpWS* w = &ws[warp];
        for (int idx = lane; idx < 400; idx += 32)
            w->A[idx] = meanL[d * 400 + idx] * inv;
        __syncwarp();
        jacobi_cm<20, SW_SMALL>(w, lane);
        if (lane < 20) w->aux[lane] = expf(-0.5f * w->A[lane * LDC + lane]);
        __syncwarp();
        recompose_cm<20>(w->V, w->aux, g_Ginv + d * 400, lane);
    }
}

// ====== K3: M = Gi X Gi, eigh -> store V,logw; per-domain sum ||logM||^2 ======
__global__ void __launch_bounds__(256) k_center(const float* __restrict__ X,
                                                const int* __restrict__ dom, int B) {
    __shared__ float Gi[NDOM * 400];
    __shared__ float nrmAcc[WPB][NDOM];
    __shared__ WarpWS ws[WPB];
    int tid = threadIdx.x, warp = tid >> 5, lane = tid & 31;
    for (int idx = tid; idx < NDOM * 400; idx += 256) Gi[idx] = g_Ginv[idx];
    if (tid < WPB * NDOM) ((float*)nrmAcc)[tid] = 0.0f;
    __syncthreads();
    WarpWS* w = &ws[warp];
    for (int m = 0; m < MPW; m++) {
        int b = ((int)blockIdx.x * WPB + warp) * MPW + m;
        if (b < B) {
            int d = dom[b];
            const float* G = Gi + d * 400;
            const float4* Xb4 = (const float4*)(X + (size_t)b * 400);
            for (int idx = lane; idx < 100; idx += 32)
                ((float4*)w->V)[idx] = Xb4[idx];          // X into V (broadcast source)
            __syncwarp();
            float res[20];
            if (lane < 20) {
                float g[20];
                #pragma unroll
                for (int k = 0; k < 20; k++) g[k] = G[k * 20 + lane];
                float y[20];
                #pragma unroll
                for (int i = 0; i < 20; i++) y[i] = dot20(w->V + i * 20, g);   // X row broadcast
                #pragma unroll
                for (int i = 0; i < 20; i++) res[i] = dot20(G + i * 20, y);    // G row broadcast
            }
            __syncwarp();    // all X reads done before jacobi clobbers V
            if (lane < 20) {
                float4* Ac = (float4*)(w->A + lane * LDC);
                #pragma unroll
                for (int t = 0; t < 5; t++)
                    Ac[t] = make_float4(res[4*t], res[4*t+1], res[4*t+2], res[4*t+3]);
            }
            jacobi_cm<20, SW_PS20>(w, lane);
            if (lane < 20) w->aux[lane] = logf(w->A[lane * LDC + lane]);
            __syncwarp();
            float4* gV4 = (float4*)(g_V2 + (size_t)b * 400);
            for (int idx = lane; idx < 100; idx += 32) gV4[idx] = ((float4*)w->V)[idx];
            if (lane < 20) g_lw2[(size_t)b * 20 + lane] = w->aux[lane];
            float v = (lane < 20) ? w->aux[lane] * w->aux[lane] : 0.0f;
            #pragma unroll
            for (int off = 16; off; off >>= 1) v += __shfl_down_sync(0xffffffffu, v, off);
            if (lane == 0) nrmAcc[warp][d] += v;
        }
    }
    __syncthreads();
    if (tid == 0) {
        float sums[NDOM] = {0.f, 0.f, 0.f, 0.f};
        for (int t = 0; t < WPB; t++)
            for (int d = 0; d < NDOM; d++) sums[d] += nrmAcc[t][d];
        for (int d = 0; d < NDOM; d++) g_partN[blockIdx.x * NDOM + d] = sums[d];
    }
}

// ============ K4: scale[d] = s / sqrt(sig2 + eps) ============
__global__ void __launch_bounds__(128) k_scale(const float* __restrict__ sptr, int NB) {
    int warp = threadIdx.x >> 5, lane = threadIdx.x & 31;
    int d = warp;
    float nsum = 0.0f;
    for (int b = lane; b < NB; b += 32) nsum += g_partN[b * NDOM + d];
    #pragma unroll
    for (int off = 16; off; off >>= 1) nsum += __shfl_down_sync(0xffffffffu, nsum, off);
    if (lane == 0) {
        float sig2 = nsum / g_cnt[d];
        g_scale[d] = sptr[0] / sqrtf(sig2 + EPS_VAR_F);
    }
}

// ====== K5: Xn via eigenbasis reuse, Y = Wt Xn W, store Y, sum logm(Y) ======
__global__ void __launch_bounds__(256) k_bimap(const float* __restrict__ Wb,
                                               const int* __restrict__ dom, int B) {
    __shared__ float Ws16[320];          // 20x16 padded W_bimap
    __shared__ float accW[WPB * 240];    // per-warp LY accumulators (15x16 padded)
    __shared__ WarpWS ws[WPB];
    int tid = threadIdx.x, warp = tid >> 5, lane = tid & 31;
    for (int idx = tid; idx < 320; idx += 256) {
        int i = idx >> 4, o = idx & 15;
        Ws16[idx] = (o < 15) ? Wb[i * 15 + o] : 0.0f;
    }
    __syncthreads();
    WarpWS* w = &ws[warp];
    float la[15];
    #pragma unroll
    for (int i = 0; i < 15; i++) la[i] = 0.0f;

    for (int m = 0; m < MPW; m++) {
        int b = ((int)blockIdx.x * WPB + warp) * MPW + m;
        if (b >= B) continue;
        int d = dom[b];
        float sc = g_scale[d];
        const float* gV = g_V2 + (size_t)b * 400;
        float c[16];
        if (lane < 20) {
            float ej = expf(0.5f * sc * g_lw2[(size_t)b * 20 + lane]);
            float z[20];
            const float4* col4 = (const float4*)(gV + lane * 20);
            #pragma unroll
            for (int t = 0; t < 5; t++) {
                float4 v = col4[t];
                z[4*t+0] = v.x * ej; z[4*t+1] = v.y * ej;
                z[4*t+2] = v.z * ej; z[4*t+3] = v.w * ej;
            }
            // C[o][lane] = sum_i W[i][o] z[i]  (broadcast W rows, 16-wide)
            #pragma unroll
            for (int o = 0; o < 16; o++) c[o] = 0.0f;
            #pragma unroll
            for (int i = 0; i < 20; i++) axpy16(z[i], Ws16 + i * 16, c);
        }
        __syncwarp();
        if (lane < 20) {
            #pragma unroll
            for (int o = 0; o < 15; o++) w->V[o * 20 + lane] = c[o];  // C rows contiguous
        }
        __syncwarp();
        float y[16];
        if (lane < 15) {                        // Y[:,lane] = C C^T column
            float cp[20];
            const float4* row4 = (const float4*)(w->V + lane * 20);
            #pragma unroll
            for (int t = 0; t < 5; t++) {
                float4 v = row4[t];
                cp[4*t+0] = v.x; cp[4*t+1] = v.y; cp[4*t+2] = v.z; cp[4*t+3] = v.w;
            }
            #pragma unroll
            for (int o = 0; o < 15; o++) y[o] = dot20(w->V + o * 20, cp);
            y[15] = 0.0f;
        }
        __syncwarp();                           // all C reads done before stores/jacobi
        if (lane < 15) {
            float4* Ac = (float4*)(w->A + lane * LDC);
            float4* gY4 = (float4*)(g_Y + (size_t)b * 240 + lane * 16);
            #pragma unroll
            for (int t = 0; t < 4; t++) {
                float4 v = make_float4(y[4*t], y[4*t+1], y[4*t+2], y[4*t+3]);
                Ac[t] = v;
                gY4[t] = v;
            }
        } else if (lane == 15) {
            float4* Ac = (float4*)(w->A + 15 * LDC);
            #pragma unroll
            for (int t = 0; t < 4; t++) Ac[t] = make_float4(0, 0, 0, 0);
        }
        jacobi_cm<15, SW_AVG15>(w, lane);
        if (lane < 15) w->aux[lane] = logf(w->A[lane * LDC + lane]);
        __syncwarp();
        if (lane < 15) {
            float rv[15];
            #pragma unroll
            for (int k = 0; k < 15; k++) rv[k] = w->aux[k] * w->V[k * LDC + lane];
            float l[16];
            #pragma unroll
            for (int i = 0; i < 16; i++) l[i] = 0.0f;
            #pragma unroll
            for (int k = 0; k < 15; k++) axpy16(rv[k], w->V + k * LDC, l);
            #pragma unroll
            for (int i = 0; i < 15; i++) la[i] += l[i];
        }
        __syncwarp();
    }
    if (lane < 15) {
        #pragma unroll
        for (int i = 0; i < 15; i++) accW[warp * 240 + i * 16 + lane] = la[i];
    }
    __syncthreads();
    for (int idx = tid; idx < 225; idx += 256) {
        int i = idx / 15, j = idx - i * 15;
        float s = 0.0f;
        #pragma unroll
        for (int wp = 0; wp < WPB; wp++) s += accW[wp * 240 + i * 16 + j];
        g_partLY[(size_t)blockIdx.x * 225 + idx] = s;
    }
}

// ============ K6: meanLY -> Gb = V e^{-w/2} Vt (padded 15x16) ============
__global__ void __launch_bounds__(256) k_gb(int B, int NB) {
    __shared__ float meanLY[225];
    __shared__ WarpWS ws0;
    int tid = threadIdx.x, warp = tid >> 5, lane = tid & 31;
    float invB = 1.0f / (float)B;
    for (int out = warp; out < 225; out += 8) {
        float s = 0.0f;
        for (int b = lane; b < NB; b += 32) s += g_partLY[(size_t)b * 225 + out];
        #pragma unroll
        for (int off = 16; off; off >>= 1) s += __shfl_down_sync(0xffffffffu, s, off);
        if (lane == 0) meanLY[out] = s * invB;
    }
    __syncthreads();
    if (warp == 0) {
        for (int idx = lane; idx < 320; idx += 32) ws0.A[idx] = 0.0f;
        __syncwarp();
        for (int idx = lane; idx < 225; idx += 32) {
            int i = idx / 15, j = idx - i * 15;
            ws0.A[j * LDC + i] = meanLY[idx];
        }
        __syncwarp();
        jacobi_cm<15, SW_SMALL>(&ws0, lane);
        if (lane < 15) ws0.aux[lane] = expf(-0.5f * ws0.A[lane * LDC + lane]);
        __syncwarp();
        // padded recompose into g_Gb16
        for (int t = 0; t < 8; t++) {
            int idx = lane + 32 * t;
            if (idx < 240) {
                int i = idx >> 4, j = idx & 15;
                float acc = 0.0f;
                if (j < 15) {
                    #pragma unroll
                    for (int k = 0; k < 15; k++)
                        acc = fmaf(ws0.V[k * LDC + i] * ws0.aux[k], ws0.V[k * LDC + j], acc);
                }
                g_Gb16[idx] = acc;
            }
        }
    }
}

// ====== K7: Yn = Gb Y Gb, eigh, fused ReEig+LogEig+vec+classifier ======
__global__ void __launch_bounds__(256) k_head(const float* __restrict__ Wl,
                                              float* __restrict__ out, int B) {
    __shared__ float Gbs[240];
    __shared__ float Wf[4 * 240];   // symmetric-expanded classifier
    __shared__ WarpWS ws[WPB];
    int tid = threadIdx.x, warp = tid >> 5, lane = tid & 31;
    for (int i = tid; i < 240; i += 256) Gbs[i] = g_Gb16[i];
    for (int idx = tid; idx < 960; idx += 256) {
        int cc = idx / 240, rem = idx - cc * 240;
        int i = rem >> 4, j = rem & 15;
        float v = 0.0f;
        if (i < 15 && j < 15) {
            if (i == j) v = Wl[cc * 120 + i];
            else {
                int a = min(i, j), b2 = max(i, j);
                int off = a * 14 - a * (a - 1) / 2 + (b2 - a - 1);
                v = Wl[cc * 120 + 15 + off] * (SQRT2F * 0.5f);
            }
        }
        Wf[idx] = v;
    }
    __syncthreads();
    WarpWS* w = &ws[warp];
    for (int m = 0; m < MPW; m++) {
        int b = ((int)blockIdx.x * WPB + warp) * MPW + m;
        if (b >= B) continue;
        const float4* gY4 = (const float4*)(g_Y + (size_t)b * 240);
        for (int idx = lane; idx < 60; idx += 32) ((float4*)w->V)[idx] = gY4[idx];
        __syncwarp();
        float res[16];
        if (lane < 15) {
            float g[16];
            #pragma unroll
            for (int k = 0; k < 15; k++) g[k] = Gbs[k * 16 + lane];
            g[15] = 0.0f;
            float y[16];
            #pragma unroll
            for (int i = 0; i < 15; i++) y[i] = dot16(w->V + i * 16, g);
            y[15] = 0.0f;
            #pragma unroll
            for (int i = 0; i < 15; i++) res[i] = dot16(Gbs + i * 16, y);
            res[15] = 0.0f;
        }
        __syncwarp();    // Y reads done before jacobi clobbers V
        if (lane < 15) {
            float4* Ac = (float4*)(w->A + lane * LDC);
            #pragma unroll
            for (int t = 0; t < 4; t++)
                Ac[t] = make_float4(res[4*t], res[4*t+1], res[4*t+2], res[4*t+3]);
        } else if (lane == 15) {
            float4* Ac = (float4*)(w->A + 15 * LDC);
            #pragma unroll
            for (int t = 0; t < 4; t++) Ac[t] = make_float4(0, 0, 0, 0);
        }
        jacobi_cm<15, SW_PS15>(w, lane);
        if (lane < 15) w->aux[lane] = logf(fmaxf(w->A[lane * LDC + lane], EPS_REEIG_F));
        __syncwarp();
        float o0 = 0.f, o1 = 0.f, o2 = 0.f, o3 = 0.f;
        if (lane < 15) {
            float rv[15];
            #pragma unroll
            for (int k = 0; k < 15; k++) rv[k] = w->aux[k] * w->V[k * LDC + lane];
            float l[16];
            #pragma unroll
            for (int i = 0; i < 16; i++) l[i] = 0.0f;
            #pragma unroll
            for (int k = 0; k < 15; k++) axpy16(rv[k], w->V + k * LDC, l);
            // out[c] = sum_ij Wf[c][i][j] Lf[i][j]; this lane contributes column j=lane
            #pragma unroll
            for (int i = 0; i < 15; i++) {
                float li = l[i];
                o0 = fmaf(Wf[0 * 240 + i * 16 + lane], li, o0);
                o1 = fmaf(Wf[1 * 240 + i * 16 + lane], li, o1);
                o2 = fmaf(Wf[2 * 240 + i * 16 + lane], li, o2);
                o3 = fmaf(Wf[3 * 240 + i * 16 + lane], li, o3);
            }
        }
        #pragma unroll
        for (int off = 16; off; off >>= 1) {
            o0 += __shfl_down_sync(0xffffffffu, o0, off);
            o1 += __shfl_down_sync(0xffffffffu, o1, off);
            o2 += __shfl_down_sync(0xffffffffu, o2, off);
            o3 += __shfl_down_sync(0xffffffffu, o3, off);
        }
        if (lane == 0) {
            float* ob = out + (size_t)b * 4;
            ob[0] = o0; ob[1] = o1; ob[2] = o2; ob[3] = o3;
        }
        __syncwarp();
    }
}

extern "C" void kernel_launch(void* const* d_in, const int* in_sizes, int n_in,
                              void* d_out, int out_size) {
    const float* X   = (const float*)d_in[0];
    const int*   dom = (const int*)d_in[1];
    const float* s   = (const float*)d_in[2];
    const float* Wb  = (const float*)d_in[3];
    const float* Wl  = (const float*)d_in[4];
    float* out = (float*)d_out;
    int B = in_sizes[0] / 400;
    if (B > MAXB) B = MAXB;
    int NB = (B + MPB - 1) / MPB;
    if (NB > NB_MAX) NB = NB_MAX;

    k_logsum<<<NB, 256>>>(X, B);
    kr_dsum<<<NCHUNK * (NSPLIT / 8), 256>>>(dom, B);
    k_ginv<<<1, 256>>>();
    k_center<<<NB, 256>>>(X, dom, B);
    k_scale<<<1, 128>>>(s, NB);
    k_bimap<<<NB, 256>>>(Wb, dom, B);
    k_gb<<<1, 256>>>(B, NB);
    k_head<<<NB, 256>>>(Wl, out, B);
}

// round 10
// speedup vs baseline: 1.0154x; 1.0154x over previous
#include <cuda_runtime.h>
#include <math.h>

#define NDOM 4
#define SQRT2F 1.41421356237309515f
#define EPS_REEIG_F 1e-4f
#define EPS_VAR_F 1e-5f

#define MAXB 32768
#define NB_MAX 1024
#define WPB 8            // warps per block
#define MPW 4            // matrices per warp
#define MPB (WPB*MPW)    // 32 matrices per block

#define LDC 20           // column stride (floats) for col-major matrices
#define SW_PS20 5        // per-sample 20x20 (k_center)
#define SW_AVG20 3       // averaged-output 20x20 (k_logsum)
#define SW_PS15 5        // per-sample 15x15 (k_head)
#define SW_AVG15 4       // averaged-output 15x15 (k_bimap)
#define SW_SMALL 7

#define NSPLIT 64        // sample splits for domain reduction
#define NCHUNK 4         // 128-float element chunks (covers 400)

#define FULLM 0xffffffffu

// ---------------- device scratch (static, allowed) ----------------
__device__ float g_V2[(size_t)MAXB * 400];   // k_logsum: per-sample L; later: eigenvectors of centered matrices
__device__ float g_lw2[(size_t)MAXB * 20];   // log-eigenvalues of centered matrices
__device__ float g_Y[(size_t)MAXB * 240];    // BiMap outputs, rows padded to 16
__device__ float g_part2[(size_t)NCHUNK * NSPLIT * NDOM * 128];
__device__ float g_partCnt[NSPLIT * NDOM];
__device__ float g_partN[NB_MAX * NDOM];
__device__ float g_partLY[NB_MAX * 225];
__device__ float g_cnt[NDOM];
__device__ float g_Ginv[NDOM * 400];
__device__ float g_scale[NDOM];
__device__ float g_Gb16[240];                // 15x16 padded

// ---------------- per-warp workspace ----------------
struct WarpWS {
    __align__(16) float A[400];     // col-major, LDC=20
    __align__(16) float V[400];     // col-major, LDC=20 (written once post-Jacobi)
    __align__(16) float4 prm[12];   // per-PAIR (c, s, p, q) for tile pass
    __align__(16) float4 cinfo[20]; // per-COLUMN (c, b=±s, partner, pad) for V shfl pass
    float aux[24];
};

// round-robin tournament pair (circle method), players 0..NS-1, NS even
__device__ __forceinline__ void pair_pq(int k, int r, int M, int& p, int& q) {
    p = (k == 0) ? 0 : (1 + (k - 1 + r) % M);
    q = 1 + (M - 1 - k + r) % M;
}

// Warp-cooperative two-sided Jacobi.
//   A: smem col-major (LDC), updated by disjoint 2x2 tile pass (unchanged).
//   V: REGISTER-RESIDENT — lane j owns eigenvector column j (v[NS], static indices).
//      Per round: pairwise column exchange via SHFL.IDX + FMA rotation. Zero L1 traffic.
//      Spilled to w->V (col-major, LDC) once at the end.
// N odd uses NS=N+1 with a zero dummy row/col (caller zero-pads A row/col N);
// the dummy pair always gets c=1,s=0 so column N stays e_N.
template<int N, int SWEEPS>
__device__ void jacobi_cm(WarpWS* w, int lane) {
    constexpr int NS = (N + 1) & ~1;
    constexpr int M  = NS - 1;
    constexpr int NP = NS / 2;
    constexpr int NT = NP * NP;
    float* A = w->A;
    float4* prm = w->prm;
    float4* cinfo = w->cinfo;

    // register eigenvector column: v = e_lane
    float v[NS];
    #pragma unroll
    for (int i = 0; i < NS; i++) v[i] = (i == lane) ? 1.0f : 0.0f;

    for (int sw = 0; sw < SWEEPS; sw++)
    for (int r = 0; r < M; r++) {
        // ---- rotation parameters (NP disjoint pairs) ----
        if (lane < NP) {
            int p, q; pair_pq(lane, r, M, p, q);
            float apq = A[q * LDC + p];
            float c = 1.0f, s = 0.0f;
            if (fabsf(apq) > 1e-38f) {
                float app = A[p * LDC + p];
                float aqq = A[q * LDC + q];
                float tau = (aqq - app) / (2.0f * apq);
                float den = fabsf(tau) + sqrtf(fmaf(tau, tau, 1.0f));
                float tt  = (tau >= 0.0f ? 1.0f : -1.0f) / den;
                c = rsqrtf(fmaf(tt, tt, 1.0f));
                s = tt * c;
            }
            prm[lane] = make_float4(c, s, __int_as_float(p), __int_as_float(q));
            // per-column records: col p: v' = c*own + (-s)*recv ; col q: v' = c*own + s*recv
            cinfo[p] = make_float4(c, -s, __int_as_float(q), 0.0f);
            cinfo[q] = make_float4(c,  s, __int_as_float(p), 0.0f);
        }
        __syncwarp();
        // per-lane column params for the V update
        float4 ci = cinfo[(lane < NS) ? lane : 0];
        float cc = (lane < NS) ? ci.x : 1.0f;
        float bb = (lane < NS) ? ci.y : 0.0f;
        int  prt = (lane < NS) ? __float_as_int(ci.z) : lane;
        // ---- one-pass tile update: A <- J^T A J  (disjoint 2x2 tiles) ----
        #pragma unroll
        for (int t = 0; t < (NT + 31) / 32; t++) {
            int idx = lane + 32 * t;
            if (idx < NT) {
                int ki = idx / NP, kj = idx - ki * NP;
                float4 pi4 = prm[ki], pj4 = prm[kj];
                float ci_ = pi4.x, si = pi4.y;
                int pi = __float_as_int(pi4.z), qi = __float_as_int(pi4.w);
                float cj = pj4.x, sj = pj4.y;
                int pj = __float_as_int(pj4.z), qj = __float_as_int(pj4.w);
                float a00 = A[pj * LDC + pi], a01 = A[qj * LDC + pi];
                float a10 = A[pj * LDC + qi], a11 = A[qj * LDC + qi];
                float r00 = fmaf(ci_, a00, -si * a10), r10 = fmaf(si, a00, ci_ * a10);
                float r01 = fmaf(ci_, a01, -si * a11), r11 = fmaf(si, a01, ci_ * a11);
                A[pj * LDC + pi] = fmaf(cj, r00, -sj * r01);
                A[qj * LDC + pi] = fmaf(sj, r00,  cj * r01);
                A[pj * LDC + qi] = fmaf(cj, r10, -sj * r11);
                A[qj * LDC + qi] = fmaf(sj, r10,  cj * r11);
            }
        }
        // ---- V rotation in registers: exchange partner column via shuffle ----
        #pragma unroll
        for (int i = 0; i < NS; i++) {
            float rv = __shfl_sync(FULLM, v[i], prt);
            v[i] = fmaf(cc, v[i], bb * rv);
        }
        __syncwarp();
    }

    // spill register columns to smem V (col-major, stride LDC) for readers
    if (lane < NS) {
        float4* Vc = (float4*)(w->V + lane * LDC);
        #pragma unroll
        for (int t = 0; t < NS / 4; t++)
            Vc[t] = make_float4(v[4*t], v[4*t+1], v[4*t+2], v[4*t+3]);
    }
    __syncwarp();
}

// ---------- float4 dot / axpy helpers ----------
__device__ __forceinline__ float dot20(const float* row, const float* g) {
    const float4* r4 = (const float4*)row;
    float a = 0.0f;
    #pragma unroll
    for (int t = 0; t < 5; t++) {
        float4 x = r4[t];
        a = fmaf(x.x, g[4*t+0], a); a = fmaf(x.y, g[4*t+1], a);
        a = fmaf(x.z, g[4*t+2], a); a = fmaf(x.w, g[4*t+3], a);
    }
    return a;
}
__device__ __forceinline__ float dot16(const float* row, const float* g) {
    const float4* r4 = (const float4*)row;
    float a = 0.0f;
    #pragma unroll
    for (int t = 0; t < 4; t++) {
        float4 x = r4[t];
        a = fmaf(x.x, g[4*t+0], a); a = fmaf(x.y, g[4*t+1], a);
        a = fmaf(x.z, g[4*t+2], a); a = fmaf(x.w, g[4*t+3], a);
    }
    return a;
}
__device__ __forceinline__ void axpy20(float u, const float* col, float* l) {
    const float4* c4 = (const float4*)col;
    #pragma unroll
    for (int t = 0; t < 5; t++) {
        float4 x = c4[t];
        l[4*t+0] = fmaf(u, x.x, l[4*t+0]); l[4*t+1] = fmaf(u, x.y, l[4*t+1]);
        l[4*t+2] = fmaf(u, x.z, l[4*t+2]); l[4*t+3] = fmaf(u, x.w, l[4*t+3]);
    }
}
__device__ __forceinline__ void axpy16(float u, const float* col, float* l) {
    const float4* c4 = (const float4*)col;
    #pragma unroll
    for (int t = 0; t < 4; t++) {
        float4 x = c4[t];
        l[4*t+0] = fmaf(u, x.x, l[4*t+0]); l[4*t+1] = fmaf(u, x.y, l[4*t+1]);
        l[4*t+2] = fmaf(u, x.z, l[4*t+2]); l[4*t+3] = fmaf(u, x.w, l[4*t+3]);
    }
}

// scalar recompose for tiny kernels: Out[i*N+j] = sum_k V[i,k] fw[k] V[j,k]
template<int N>
__device__ __forceinline__ void recompose_cm(const float* V, const float* fw,
                                             float* Out, int lane) {
    #pragma unroll
    for (int t = 0; t < (N * N + 31) / 32; t++) {
        int idx = lane + 32 * t;
        if (idx < N * N) {
            int i = idx / N, j = idx - i * N;
            float acc = 0.0f;
            #pragma unroll
            for (int k = 0; k < N; k++)
                acc = fmaf(V[k * LDC + i] * fw[k], V[k * LDC + j], acc);
            Out[idx] = acc;
        }
    }
}

// ============ K1: per-sample logm(X) -> g_V2 (as L scratch) ============
__global__ void __launch_bounds__(256) k_logsum(const float* __restrict__ X, int B) {
    __shared__ WarpWS ws[WPB];
    int tid = threadIdx.x, warp = tid >> 5, lane = tid & 31;
    WarpWS* w = &ws[warp];
    for (int m = 0; m < MPW; m++) {
        int b = ((int)blockIdx.x * WPB + warp) * MPW + m;
        if (b >= B) continue;
        const float4* Xb4 = (const float4*)(X + (size_t)b * 400);
        for (int idx = lane; idx < 100; idx += 32) ((float4*)w->A)[idx] = Xb4[idx];
        __syncwarp();
        jacobi_cm<20, SW_AVG20>(w, lane);
        if (lane < 20) w->aux[lane] = logf(w->A[lane * LDC + lane]);
        __syncwarp();
        if (lane < 20) {
            float rv[20];
            #pragma unroll
            for (int k = 0; k < 20; k++) rv[k] = w->aux[k] * w->V[k * LDC + lane];
            float l[20];
            #pragma unroll
            for (int i = 0; i < 20; i++) l[i] = 0.0f;
            #pragma unroll
            for (int k = 0; k < 20; k++) axpy20(rv[k], w->V + k * LDC, l);
            float4* Lb = (float4*)(g_V2 + (size_t)b * 400 + lane * 20);
            #pragma unroll
            for (int t = 0; t < 5; t++)
                Lb[t] = make_float4(l[4*t], l[4*t+1], l[4*t+2], l[4*t+3]);
        }
        __syncwarp();
    }
}

// ===== K1b: deterministic domain-segmented sum of L over samples =====
__global__ void __launch_bounds__(256) kr_dsum(const int* __restrict__ dom, int B) {
    int warp = threadIdx.x >> 5, lane = threadIdx.x & 31;
    int c = blockIdx.x & 3;                    // element chunk
    int split = ((int)blockIdx.x >> 2) * 8 + warp;
    int per = (B + NSPLIT - 1) / NSPLIT;
    int b0 = split * per, b1 = b0 + per;
    if (b1 > B) b1 = B;
    int e = c * 128 + lane * 4;
    bool valid = e < 400;
    float4 a0 = make_float4(0,0,0,0), a1 = a0, a2 = a0, a3 = a0;
    int cnt0 = 0, cnt1 = 0, cnt2 = 0, cnt3 = 0;
    for (int b = b0; b < b1; b++) {
        int d = dom[b];
        float4 v = make_float4(0,0,0,0);
        if (valid) v = *(const float4*)(g_V2 + (size_t)b * 400 + e);
        if (d == 0)      { a0.x += v.x; a0.y += v.y; a0.z += v.z; a0.w += v.w; cnt0++; }
        else if (d == 1) { a1.x += v.x; a1.y += v.y; a1.z += v.z; a1.w += v.w; cnt1++; }
        else if (d == 2) { a2.x += v.x; a2.y += v.y; a2.z += v.z; a2.w += v.w; cnt2++; }
        else             { a3.x += v.x; a3.y += v.y; a3.z += v.z; a3.w += v.w; cnt3++; }
    }
    if (valid) {
        size_t base = (((size_t)c * NSPLIT + split) * NDOM) * 128 + lane * 4;
        *(float4*)(g_part2 + base + 0 * 128) = a0;
        *(float4*)(g_part2 + base + 1 * 128) = a1;
        *(float4*)(g_part2 + base + 2 * 128) = a2;
        *(float4*)(g_part2 + base + 3 * 128) = a3;
    }
    if (c == 0 && lane == 0) {
        g_partCnt[split * NDOM + 0] = (float)cnt0;
        g_partCnt[split * NDOM + 1] = (float)cnt1;
        g_partCnt[split * NDOM + 2] = (float)cnt2;
        g_partCnt[split * NDOM + 3] = (float)cnt3;
    }
}

// ============ K2: reduce partials -> meanL, counts; Ginv[d] = V e^{-w/2} Vt ============
__global__ void __launch_bounds__(256) k_ginv() {
    __shared__ WarpWS ws[4];
    __shared__ float meanL[NDOM * 400];
    int tid = threadIdx.x;
    if (tid < NDOM) {
        float c = 0.0f;
        for (int sp = 0; sp < NSPLIT; sp++) c += g_partCnt[sp * NDOM + tid];
        g_cnt[tid] = c;
    }
    for (int out = tid; out < NDOM * 400; out += 256) {
        int d = out / 400, e = out - d * 400;
        int c = e >> 7, i = e & 127;
        float s = 0.0f;
        for (int sp = 0; sp < NSPLIT; sp++)
            s += g_part2[(((size_t)c * NSPLIT + sp) * NDOM + d) * 128 + i];
        meanL[out] = s;
    }
    __syncthreads();
    int warp = tid >> 5, lane = tid & 31;
    if (warp < 4) {
        int d = warp;
        float inv = 1.0f / g_cnt[d];
        WarpWS* w = &ws[warp];
        for (int idx = lane; idx < 400; idx += 32)
            w->A[idx] = meanL[d * 400 + idx] * inv;
        __syncwarp();
        jacobi_cm<20, SW_SMALL>(w, lane);
        if (lane < 20) w->aux[lane] = expf(-0.5f * w->A[lane * LDC + lane]);
        __syncwarp();
        recompose_cm<20>(w->V, w->aux, g_Ginv + d * 400, lane);
    }
}

// ====== K3: M = Gi X Gi, eigh -> store V,logw; per-domain sum ||logM||^2 ======
__global__ void __launch_bounds__(256) k_center(const float* __restrict__ X,
                                                const int* __restrict__ dom, int B) {
    __shared__ float Gi[NDOM * 400];
    __shared__ float nrmAcc[WPB][NDOM];
    __shared__ WarpWS ws[WPB];
    int tid = threadIdx.x, warp = tid >> 5, lane = tid & 31;
    for (int idx = tid; idx < NDOM * 400; idx += 256) Gi[idx] = g_Ginv[idx];
    if (tid < WPB * NDOM) ((float*)nrmAcc)[tid] = 0.0f;
    __syncthreads();
    WarpWS* w = &ws[warp];
    for (int m = 0; m < MPW; m++) {
        int b = ((int)blockIdx.x * WPB + warp) * MPW + m;
        if (b < B) {
            int d = dom[b];
            const float* G = Gi + d * 400;
            const float4* Xb4 = (const float4*)(X + (size_t)b * 400);
            for (int idx = lane; idx < 100; idx += 32)
                ((float4*)w->V)[idx] = Xb4[idx];          // X into V (broadcast source)
            __syncwarp();
            float res[20];
            if (lane < 20) {
                float g[20];
                #pragma unroll
                for (int k = 0; k < 20; k++) g[k] = G[k * 20 + lane];
                float y[20];
                #pragma unroll
                for (int i = 0; i < 20; i++) y[i] = dot20(w->V + i * 20, g);   // X row broadcast
                #pragma unroll
                for (int i = 0; i < 20; i++) res[i] = dot20(G + i * 20, y);    // G row broadcast
            }
            __syncwarp();    // all X reads done before jacobi clobbers V
            if (lane < 20) {
                float4* Ac = (float4*)(w->A + lane * LDC);
                #pragma unroll
                for (int t = 0; t < 5; t++)
                    Ac[t] = make_float4(res[4*t], res[4*t+1], res[4*t+2], res[4*t+3]);
            }
            jacobi_cm<20, SW_PS20>(w, lane);
            if (lane < 20) w->aux[lane] = logf(w->A[lane * LDC + lane]);
            __syncwarp();
            float4* gV4 = (float4*)(g_V2 + (size_t)b * 400);
            for (int idx = lane; idx < 100; idx += 32) gV4[idx] = ((float4*)w->V)[idx];
            if (lane < 20) g_lw2[(size_t)b * 20 + lane] = w->aux[lane];
            float v = (lane < 20) ? w->aux[lane] * w->aux[lane] : 0.0f;
            #pragma unroll
            for (int off = 16; off; off >>= 1) v += __shfl_down_sync(FULLM, v, off);
            if (lane == 0) nrmAcc[warp][d] += v;
        }
    }
    __syncthreads();
    if (tid == 0) {
        float sums[NDOM] = {0.f, 0.f, 0.f, 0.f};
        for (int t = 0; t < WPB; t++)
            for (int d = 0; d < NDOM; d++) sums[d] += nrmAcc[t][d];
        for (int d = 0; d < NDOM; d++) g_partN[blockIdx.x * NDOM + d] = sums[d];
    }
}

// ============ K4: scale[d] = s / sqrt(sig2 + eps) ============
__global__ void __launch_bounds__(128) k_scale(const float* __restrict__ sptr, int NB) {
    int warp = threadIdx.x >> 5, lane = threadIdx.x & 31;
    int d = warp;
    float nsum = 0.0f;
    for (int b = lane; b < NB; b += 32) nsum += g_partN[b * NDOM + d];
    #pragma unroll
    for (int off = 16; off; off >>= 1) nsum += __shfl_down_sync(FULLM, nsum, off);
    if (lane == 0) {
        float sig2 = nsum / g_cnt[d];
        g_scale[d] = sptr[0] / sqrtf(sig2 + EPS_VAR_F);
    }
}

// ====== K5: Xn via eigenbasis reuse, Y = Wt Xn W, store Y, sum logm(Y) ======
__global__ void __launch_bounds__(256) k_bimap(const float* __restrict__ Wb,
                                               const int* __restrict__ dom, int B) {
    __shared__ float Ws16[320];          // 20x16 padded W_bimap
    __shared__ float accW[WPB * 240];    // per-warp LY accumulators (15x16 padded)
    __shared__ WarpWS ws[WPB];
    int tid = threadIdx.x, warp = tid >> 5, lane = tid & 31;
    for (int idx = tid; idx < 320; idx += 256) {
        int i = idx >> 4, o = idx & 15;
        Ws16[idx] = (o < 15) ? Wb[i * 15 + o] : 0.0f;
    }
    __syncthreads();
    WarpWS* w = &ws[warp];
    float la[15];
    #pragma unroll
    for (int i = 0; i < 15; i++) la[i] = 0.0f;

    for (int m = 0; m < MPW; m++) {
        int b = ((int)blockIdx.x * WPB + warp) * MPW + m;
        if (b >= B) continue;
        int d = dom[b];
        float sc = g_scale[d];
        const float* gV = g_V2 + (size_t)b * 400;
        float c[16];
        if (lane < 20) {
            float ej = expf(0.5f * sc * g_lw2[(size_t)b * 20 + lane]);
            float z[20];
            const float4* col4 = (const float4*)(gV + lane * 20);
            #pragma unroll
            for (int t = 0; t < 5; t++) {
                float4 v = col4[t];
                z[4*t+0] = v.x * ej; z[4*t+1] = v.y * ej;
                z[4*t+2] = v.z * ej; z[4*t+3] = v.w * ej;
            }
            // C[o][lane] = sum_i W[i][o] z[i]  (broadcast W rows, 16-wide)
            #pragma unroll
            for (int o = 0; o < 16; o++) c[o] = 0.0f;
            #pragma unroll
            for (int i = 0; i < 20; i++) axpy16(z[i], Ws16 + i * 16, c);
        }
        __syncwarp();
        if (lane < 20) {
            #pragma unroll
            for (int o = 0; o < 15; o++) w->V[o * 20 + lane] = c[o];  // C rows contiguous
        }
        __syncwarp();
        float y[16];
        if (lane < 15) {                        // Y[:,lane] = C C^T column
            float cp[20];
            const float4* row4 = (const float4*)(w->V + lane * 20);
            #pragma unroll
            for (int t = 0; t < 5; t++) {
                float4 v = row4[t];
                cp[4*t+0] = v.x; cp[4*t+1] = v.y; cp[4*t+2] = v.z; cp[4*t+3] = v.w;
            }
            #pragma unroll
            for (int o = 0; o < 15; o++) y[o] = dot20(w->V + o * 20, cp);
            y[15] = 0.0f;
        }
        __syncwarp();                           // all C reads done before stores/jacobi
        if (lane < 15) {
            float4* Ac = (float4*)(w->A + lane * LDC);
            float4* gY4 = (float4*)(g_Y + (size_t)b * 240 + lane * 16);
            #pragma unroll
            for (int t = 0; t < 4; t++) {
                float4 v = make_float4(y[4*t], y[4*t+1], y[4*t+2], y[4*t+3]);
                Ac[t] = v;
                gY4[t] = v;
            }
        } else if (lane == 15) {
            float4* Ac = (float4*)(w->A + 15 * LDC);
            #pragma unroll
            for (int t = 0; t < 4; t++) Ac[t] = make_float4(0, 0, 0, 0);
        }
        jacobi_cm<15, SW_AVG15>(w, lane);
        if (lane < 15) w->aux[lane] = logf(w->A[lane * LDC + lane]);
        __syncwarp();
        if (lane < 15) {
            float rv[15];
            #pragma unroll
            for (int k = 0; k < 15; k++) rv[k] = w->aux[k] * w->V[k * LDC + lane];
            float l[16];
            #pragma unroll
            for (int i = 0; i < 16; i++) l[i] = 0.0f;
            #pragma unroll
            for (int k = 0; k < 15; k++) axpy16(rv[k], w->V + k * LDC, l);
            #pragma unroll
            for (int i = 0; i < 15; i++) la[i] += l[i];
        }
        __syncwarp();
    }
    if (lane < 15) {
        #pragma unroll
        for (int i = 0; i < 15; i++) accW[warp * 240 + i * 16 + lane] = la[i];
    }
    __syncthreads();
    for (int idx = tid; idx < 225; idx += 256) {
        int i = idx / 15, j = idx - i * 15;
        float s = 0.0f;
        #pragma unroll
        for (int wp = 0; wp < WPB; wp++) s += accW[wp * 240 + i * 16 + j];
        g_partLY[(size_t)blockIdx.x * 225 + idx] = s;
    }
}

// ============ K6: meanLY -> Gb = V e^{-w/2} Vt (padded 15x16) ============
__global__ void __launch_bounds__(256) k_gb(int B, int NB) {
    __shared__ float meanLY[225];
    __shared__ WarpWS ws0;
    int tid = threadIdx.x, warp = tid >> 5, lane = tid & 31;
    float invB = 1.0f / (float)B;
    for (int out = warp; out < 225; out += 8) {
        float s = 0.0f;
        for (int b = lane; b < NB; b += 32) s += g_partLY[(size_t)b * 225 + out];
        #pragma unroll
        for (int off = 16; off; off >>= 1) s += __shfl_down_sync(FULLM, s, off);
        if (lane == 0) meanLY[out] = s * invB;
    }
    __syncthreads();
    if (warp == 0) {
        for (int idx = lane; idx < 320; idx += 32) ws0.A[idx] = 0.0f;
        __syncwarp();
        for (int idx = lane; idx < 225; idx += 32) {
            int i = idx / 15, j = idx - i * 15;
            ws0.A[j * LDC + i] = meanLY[idx];
        }
        __syncwarp();
        jacobi_cm<15, SW_SMALL>(&ws0, lane);
        if (lane < 15) ws0.aux[lane] = expf(-0.5f * ws0.A[lane * LDC + lane]);
        __syncwarp();
        // padded recompose into g_Gb16
        for (int t = 0; t < 8; t++) {
            int idx = lane + 32 * t;
            if (idx < 240) {
                int i = idx >> 4, j = idx & 15;
                float acc = 0.0f;
                if (j < 15) {
                    #pragma unroll
                    for (int k = 0; k < 15; k++)
                        acc = fmaf(ws0.V[k * LDC + i] * ws0.aux[k], ws0.V[k * LDC + j], acc);
                }
                g_Gb16[idx] = acc;
            }
        }
    }
}

// ====== K7: Yn = Gb Y Gb, eigh, fused ReEig+LogEig+vec+classifier ======
__global__ void __launch_bounds__(256) k_head(const float* __restrict__ Wl,
                                              float* __restrict__ out, int B) {
    __shared__ float Gbs[240];
    __shared__ float Wf[4 * 240];   // symmetric-expanded classifier
    __shared__ WarpWS ws[WPB];
    int tid = threadIdx.x, warp = tid >> 5, lane = tid & 31;
    for (int i = tid; i < 240; i += 256) Gbs[i] = g_Gb16[i];
    for (int idx = tid; idx < 960; idx += 256) {
        int cc = idx / 240, rem = idx - cc * 240;
        int i = rem >> 4, j = rem & 15;
        float v = 0.0f;
        if (i < 15 && j < 15) {
            if (i == j) v = Wl[cc * 120 + i];
            else {
                int a = min(i, j), b2 = max(i, j);
                int off = a * 14 - a * (a - 1) / 2 + (b2 - a - 1);
                v = Wl[cc * 120 + 15 + off] * (SQRT2F * 0.5f);
            }
        }
        Wf[idx] = v;
    }
    __syncthreads();
    WarpWS* w = &ws[warp];
    for (int m = 0; m < MPW; m++) {
        int b = ((int)blockIdx.x * WPB + warp) * MPW + m;
        if (b >= B) continue;
        const float4* gY4 = (const float4*)(g_Y + (size_t)b * 240);
        for (int idx = lane; idx < 60; idx += 32) ((float4*)w->V)[idx] = gY4[idx];
        __syncwarp();
        float res[16];
        if (lane < 15) {
            float g[16];
            #pragma unroll
            for (int k = 0; k < 15; k++) g[k] = Gbs[k * 16 + lane];
            g[15] = 0.0f;
            float y[16];
            #pragma unroll
            for (int i = 0; i < 15; i++) y[i] = dot16(w->V + i * 16, g);
            y[15] = 0.0f;
            #pragma unroll
            for (int i = 0; i < 15; i++) res[i] = dot16(Gbs + i * 16, y);
            res[15] = 0.0f;
        }
        __syncwarp();    // Y reads done before jacobi clobbers V
        if (lane < 15) {
            float4* Ac = (float4*)(w->A + lane * LDC);
            #pragma unroll
            for (int t = 0; t < 4; t++)
                Ac[t] = make_float4(res[4*t], res[4*t+1], res[4*t+2], res[4*t+3]);
        } else if (lane == 15) {
            float4* Ac = (float4*)(w->A + 15 * LDC);
            #pragma unroll
            for (int t = 0; t < 4; t++) Ac[t] = make_float4(0, 0, 0, 0);
        }
        jacobi_cm<15, SW_PS15>(w, lane);
        if (lane < 15) w->aux[lane] = logf(fmaxf(w->A[lane * LDC + lane], EPS_REEIG_F));
        __syncwarp();
        float o0 = 0.f, o1 = 0.f, o2 = 0.f, o3 = 0.f;
        if (lane < 15) {
            float rv[15];
            #pragma unroll
            for (int k = 0; k < 15; k++) rv[k] = w->aux[k] * w->V[k * LDC + lane];
            float l[16];
            #pragma unroll
            for (int i = 0; i < 16; i++) l[i] = 0.0f;
            #pragma unroll
            for (int k = 0; k < 15; k++) axpy16(rv[k], w->V + k * LDC, l);
            // out[c] = sum_ij Wf[c][i][j] Lf[i][j]; this lane contributes column j=lane
            #pragma unroll
            for (int i = 0; i < 15; i++) {
                float li = l[i];
                o0 = fmaf(Wf[0 * 240 + i * 16 + lane], li, o0);
                o1 = fmaf(Wf[1 * 240 + i * 16 + lane], li, o1);
                o2 = fmaf(Wf[2 * 240 + i * 16 + lane], li, o2);
                o3 = fmaf(Wf[3 * 240 + i * 16 + lane], li, o3);
            }
        }
        #pragma unroll
        for (int off = 16; off; off >>= 1) {
            o0 += __shfl_down_sync(FULLM, o0, off);
            o1 += __shfl_down_sync(FULLM, o1, off);
            o2 += __shfl_down_sync(FULLM, o2, off);
            o3 += __shfl_down_sync(FULLM, o3, off);
        }
        if (lane == 0) {
            float* ob = out + (size_t)b * 4;
            ob[0] = o0; ob[1] = o1; ob[2] = o2; ob[3] = o3;
        }
        __syncwarp();
    }
}

extern "C" void kernel_launch(void* const* d_in, const int* in_sizes, int n_in,
                              void* d_out, int out_size) {
    const float* X   = (const float*)d_in[0];
    const int*   dom = (const int*)d_in[1];
    const float* s   = (const float*)d_in[2];
    const float* Wb  = (const float*)d_in[3];
    const float* Wl  = (const float*)d_in[4];
    float* out = (float*)d_out;
    int B = in_sizes[0] / 400;
    if (B > MAXB) B = MAXB;
    int NB = (B + MPB - 1) / MPB;
    if (NB > NB_MAX) NB = NB_MAX;

    k_logsum<<<NB, 256>>>(X, B);
    kr_dsum<<<NCHUNK * (NSPLIT / 8), 256>>>(dom, B);
    k_ginv<<<1, 256>>>();
    k_center<<<NB, 256>>>(X, dom, B);
    k_scale<<<1, 128>>>(s, NB);
    k_bimap<<<NB, 256>>>(Wb, dom, B);
    k_gb<<<1, 256>>>(B, NB);
    k_head<<<NB, 256>>>(Wl, out, B);
}

// round 11
// speedup vs baseline: 1.0809x; 1.0645x over previous
#include <cuda_runtime.h>
#include <math.h>

#define NDOM 4
#define SQRT2F 1.41421356237309515f
#define EPS_REEIG_F 1e-4f
#define EPS_VAR_F 1e-5f

#define MAXB 32768
#define NB_MAX 1024
#define WPB 8            // warps per block
#define MPW 4            // matrices per warp
#define MPB (WPB*MPW)    // 32 matrices per block

#define LDC 20           // column stride (floats) for col-major matrices
#define SW_PS20 5        // per-sample 20x20 (k_center)
#define SW_AVG20 3       // averaged-output 20x20 (k_logsum)
#define SW_PS15 5        // per-sample 15x15 (k_head)
#define SW_AVG15 4       // averaged-output 15x15 (k_bimap)
#define SW_SMALL 7

#define NSPLIT 64        // sample splits for domain reduction
#define NCHUNK 4         // 128-float element chunks (covers 400)

#define FULLM 0xffffffffu
#define HSTRIDE 336      // per-half float offset in PairWS.buf (336 mod 32 = 16 -> bank split)

// ---------------- device scratch (static, allowed) ----------------
__device__ float g_V2[(size_t)MAXB * 400];   // k_logsum: per-sample L; later: eigenvectors of centered matrices
__device__ float g_lw2[(size_t)MAXB * 20];   // log-eigenvalues of centered matrices
__device__ float g_Y[(size_t)MAXB * 240];    // BiMap outputs, rows padded to 16
__device__ float g_part2[(size_t)NCHUNK * NSPLIT * NDOM * 128];
__device__ float g_partCnt[NSPLIT * NDOM];
__device__ float g_partN[NB_MAX * NDOM];
__device__ float g_partLY[NB_MAX * 225];
__device__ float g_cnt[NDOM];
__device__ float g_Ginv[NDOM * 400];
__device__ float g_scale[NDOM];
__device__ float g_Gb16[240];                // 15x16 padded

// ---------------- per-warp workspaces ----------------
struct WarpWS {
    __align__(16) float A[400];     // col-major, LDC=20
    __align__(16) float V[400];     // col-major, LDC=20 (written once post-Jacobi)
    __align__(16) float4 prm[12];   // per-PAIR (c, s, p, q) for tile pass
    __align__(16) float4 cinfo[20]; // per-COLUMN (c, b=±s, partner, pad) for V shfl pass
    float aux[24];
};

// paired 15x15 workspace: two matrices per warp (half = lane>>4)
struct PairWS {
    __align__(16) float buf[2 * HSTRIDE]; // per half: Y (240) -> A (16 cols x 20) -> V spill
    __align__(16) float4 prm[16];         // per half 8 pairs; reused as aux (32 floats) after jacobi
};

// round-robin tournament pair (circle method), players 0..NS-1, NS even
__device__ __forceinline__ void pair_pq(int k, int r, int M, int& p, int& q) {
    p = (k == 0) ? 0 : (1 + (k - 1 + r) % M);
    q = 1 + (M - 1 - k + r) % M;
}

// Warp-cooperative two-sided Jacobi (single matrix, used for n=20 and tiny kernels).
//   A: smem col-major (LDC), disjoint 2x2 tile pass.
//   V: register-resident, lane j owns column j; SHFL exchange per round; spilled at end.
template<int N, int SWEEPS>
__device__ void jacobi_cm(WarpWS* w, int lane) {
    constexpr int NS = (N + 1) & ~1;
    constexpr int M  = NS - 1;
    constexpr int NP = NS / 2;
    constexpr int NT = NP * NP;
    float* A = w->A;
    float4* prm = w->prm;
    float4* cinfo = w->cinfo;

    float v[NS];
    #pragma unroll
    for (int i = 0; i < NS; i++) v[i] = (i == lane) ? 1.0f : 0.0f;

    for (int sw = 0; sw < SWEEPS; sw++)
    for (int r = 0; r < M; r++) {
        if (lane < NP) {
            int p, q; pair_pq(lane, r, M, p, q);
            float apq = A[q * LDC + p];
            float c = 1.0f, s = 0.0f;
            if (fabsf(apq) > 1e-38f) {
                float app = A[p * LDC + p];
                float aqq = A[q * LDC + q];
                float tau = (aqq - app) / (2.0f * apq);
                float den = fabsf(tau) + sqrtf(fmaf(tau, tau, 1.0f));
                float tt  = (tau >= 0.0f ? 1.0f : -1.0f) / den;
                c = rsqrtf(fmaf(tt, tt, 1.0f));
                s = tt * c;
            }
            prm[lane] = make_float4(c, s, __int_as_float(p), __int_as_float(q));
            cinfo[p] = make_float4(c, -s, __int_as_float(q), 0.0f);
            cinfo[q] = make_float4(c,  s, __int_as_float(p), 0.0f);
        }
        __syncwarp();
        float4 ci = cinfo[(lane < NS) ? lane : 0];
        float cc = (lane < NS) ? ci.x : 1.0f;
        float bb = (lane < NS) ? ci.y : 0.0f;
        int  prt = (lane < NS) ? __float_as_int(ci.z) : lane;
        #pragma unroll
        for (int t = 0; t < (NT + 31) / 32; t++) {
            int idx = lane + 32 * t;
            if (idx < NT) {
                int ki = idx / NP, kj = idx - ki * NP;
                float4 pi4 = prm[ki], pj4 = prm[kj];
                float ci_ = pi4.x, si = pi4.y;
                int pi = __float_as_int(pi4.z), qi = __float_as_int(pi4.w);
                float cj = pj4.x, sj = pj4.y;
                int pj = __float_as_int(pj4.z), qj = __float_as_int(pj4.w);
                float a00 = A[pj * LDC + pi], a01 = A[qj * LDC + pi];
                float a10 = A[pj * LDC + qi], a11 = A[qj * LDC + qi];
                float r00 = fmaf(ci_, a00, -si * a10), r10 = fmaf(si, a00, ci_ * a10);
                float r01 = fmaf(ci_, a01, -si * a11), r11 = fmaf(si, a01, ci_ * a11);
                A[pj * LDC + pi] = fmaf(cj, r00, -sj * r01);
                A[qj * LDC + pi] = fmaf(sj, r00,  cj * r01);
                A[pj * LDC + qi] = fmaf(cj, r10, -sj * r11);
                A[qj * LDC + qi] = fmaf(sj, r10,  cj * r11);
            }
        }
        #pragma unroll
        for (int i = 0; i < NS; i++) {
            float rv = __shfl_sync(FULLM, v[i], prt);
            v[i] = fmaf(cc, v[i], bb * rv);
        }
        __syncwarp();
    }

    if (lane < NS) {
        float4* Vc = (float4*)(w->V + lane * LDC);
        #pragma unroll
        for (int t = 0; t < NS / 4; t++)
            Vc[t] = make_float4(v[4*t], v[4*t+1], v[4*t+2], v[4*t+3]);
    }
    __syncwarp();
}

// Paired 15x15 Jacobi: two matrices per warp (half = lane>>4, column = lane&15).
// A at buf + half*HSTRIDE (col stride 20, 16 cols, dummy col/row 15 zero).
// V register-resident per half; diag -> prm region (as aux); V spilled OVER A region.
template<int SWEEPS>
__device__ void jacobi_pair15(PairWS* w, int lane) {
    constexpr int MP = 15, NPP = 8;
    int half = lane >> 4, l16 = lane & 15;
    float* A = w->buf + half * HSTRIDE;
    float4* prmh = w->prm + half * 8;

    float v[16];
    #pragma unroll
    for (int i = 0; i < 16; i++) v[i] = (i == l16) ? 1.0f : 0.0f;

    for (int sw = 0; sw < SWEEPS; sw++)
    for (int r = 0; r < MP; r++) {
        // ---- params: 16 lanes (8 per half) ----
        if (l16 < NPP) {
            int p, q; pair_pq(l16, r, MP, p, q);
            float apq = A[q * LDC + p];
            float c = 1.0f, s = 0.0f;
            if (fabsf(apq) > 1e-38f) {
                float app = A[p * LDC + p];
                float aqq = A[q * LDC + q];
                float tau = (aqq - app) / (2.0f * apq);
                float den = fabsf(tau) + sqrtf(fmaf(tau, tau, 1.0f));
                float tt  = (tau >= 0.0f ? 1.0f : -1.0f) / den;
                c = rsqrtf(fmaf(tt, tt, 1.0f));
                s = tt * c;
            }
            prmh[l16] = make_float4(c, s, __int_as_float(p), __int_as_float(q));
        }
        __syncwarp();
        // ---- analytic partner/role for column l16 ----
        int k, prt; float sgn;
        if (l16 == 0) {
            k = 0; prt = 1 + (MP - 1 + r) % MP; sgn = -1.0f;            // role p
        } else {
            int j = l16 - 1 - r; j %= MP; if (j < 0) j += MP;
            int kp = j + 1;
            if (kp <= NPP - 1) {                                        // role p of pair kp
                k = kp; prt = 1 + (MP - 1 - k + r) % MP; sgn = -1.0f;
            } else {                                                    // role q
                k = (MP + r - l16) % MP;
                prt = (k == 0) ? 0 : 1 + (k - 1 + r) % MP;
                sgn = 1.0f;
            }
        }
        float4 pk = prmh[k];
        float cc = pk.x, bb = sgn * pk.y;
        int src = (half << 4) | prt;
        // ---- tile pass: 128 tiles over both halves ----
        #pragma unroll
        for (int t = 0; t < 4; t++) {
            int idx = lane + 32 * t;
            int h2 = idx >> 6, tile = idx & 63;
            int ki = tile >> 3, kj = tile & 7;
            const float4* prr = w->prm + h2 * 8;
            float* Ah = w->buf + h2 * HSTRIDE;
            float4 pi4 = prr[ki], pj4 = prr[kj];
            float ci_ = pi4.x, si = pi4.y;
            int pi = __float_as_int(pi4.z), qi = __float_as_int(pi4.w);
            float cj = pj4.x, sj = pj4.y;
            int pj = __float_as_int(pj4.z), qj = __float_as_int(pj4.w);
            float a00 = Ah[pj * LDC + pi], a01 = Ah[qj * LDC + pi];
            float a10 = Ah[pj * LDC + qi], a11 = Ah[qj * LDC + qi];
            float r00 = fmaf(ci_, a00, -si * a10), r10 = fmaf(si, a00, ci_ * a10);
            float r01 = fmaf(ci_, a01, -si * a11), r11 = fmaf(si, a01, ci_ * a11);
            Ah[pj * LDC + pi] = fmaf(cj, r00, -sj * r01);
            Ah[qj * LDC + pi] = fmaf(sj, r00,  cj * r01);
            Ah[pj * LDC + qi] = fmaf(cj, r10, -sj * r11);
            Ah[qj * LDC + qi] = fmaf(sj, r10,  cj * r11);
        }
        // ---- V rotation (all 32 lanes useful) ----
        #pragma unroll
        for (int i = 0; i < 16; i++) {
            float rv = __shfl_sync(FULLM, v[i], src);
            v[i] = fmaf(cc, v[i], bb * rv);
        }
        __syncwarp();
    }

    // diag -> aux (reuse prm memory), then spill V over A region
    float dg = A[l16 * LDC + l16];
    __syncwarp();
    float* auxp = (float*)w->prm;
    auxp[half * 16 + l16] = dg;
    float4* Vc = (float4*)(A + l16 * LDC);
    #pragma unroll
    for (int t = 0; t < 4; t++)
        Vc[t] = make_float4(v[4*t], v[4*t+1], v[4*t+2], v[4*t+3]);
    __syncwarp();
}

// ---------- float4 dot / axpy helpers ----------
__device__ __forceinline__ float dot20(const float* row, const float* g) {
    const float4* r4 = (const float4*)row;
    float a = 0.0f;
    #pragma unroll
    for (int t = 0; t < 5; t++) {
        float4 x = r4[t];
        a = fmaf(x.x, g[4*t+0], a); a = fmaf(x.y, g[4*t+1], a);
        a = fmaf(x.z, g[4*t+2], a); a = fmaf(x.w, g[4*t+3], a);
    }
    return a;
}
__device__ __forceinline__ float dot16(const float* row, const float* g) {
    const float4* r4 = (const float4*)row;
    float a = 0.0f;
    #pragma unroll
    for (int t = 0; t < 4; t++) {
        float4 x = r4[t];
        a = fmaf(x.x, g[4*t+0], a); a = fmaf(x.y, g[4*t+1], a);
        a = fmaf(x.z, g[4*t+2], a); a = fmaf(x.w, g[4*t+3], a);
    }
    return a;
}
__device__ __forceinline__ void axpy20(float u, const float* col, float* l) {
    const float4* c4 = (const float4*)col;
    #pragma unroll
    for (int t = 0; t < 5; t++) {
        float4 x = c4[t];
        l[4*t+0] = fmaf(u, x.x, l[4*t+0]); l[4*t+1] = fmaf(u, x.y, l[4*t+1]);
        l[4*t+2] = fmaf(u, x.z, l[4*t+2]); l[4*t+3] = fmaf(u, x.w, l[4*t+3]);
    }
}
__device__ __forceinline__ void axpy16(float u, const float* col, float* l) {
    const float4* c4 = (const float4*)col;
    #pragma unroll
    for (int t = 0; t < 4; t++) {
        float4 x = c4[t];
        l[4*t+0] = fmaf(u, x.x, l[4*t+0]); l[4*t+1] = fmaf(u, x.y, l[4*t+1]);
        l[4*t+2] = fmaf(u, x.z, l[4*t+2]); l[4*t+3] = fmaf(u, x.w, l[4*t+3]);
    }
}

// scalar recompose for tiny kernels: Out[i*N+j] = sum_k V[i,k] fw[k] V[j,k]
template<int N>
__device__ __forceinline__ void recompose_cm(const float* V, const float* fw,
                                             float* Out, int lane) {
    #pragma unroll
    for (int t = 0; t < (N * N + 31) / 32; t++) {
        int idx = lane + 32 * t;
        if (idx < N * N) {
            int i = idx / N, j = idx - i * N;
            float acc = 0.0f;
            #pragma unroll
            for (int k = 0; k < N; k++)
                acc = fmaf(V[k * LDC + i] * fw[k], V[k * LDC + j], acc);
            Out[idx] = acc;
        }
    }
}

// ============ K1: per-sample logm(X) -> g_V2 (as L scratch) ============
__global__ void __launch_bounds__(256) k_logsum(const float* __restrict__ X, int B) {
    __shared__ WarpWS ws[WPB];
    int tid = threadIdx.x, warp = tid >> 5, lane = tid & 31;
    WarpWS* w = &ws[warp];
    for (int m = 0; m < MPW; m++) {
        int b = ((int)blockIdx.x * WPB + warp) * MPW + m;
        if (b >= B) continue;
        const float4* Xb4 = (const float4*)(X + (size_t)b * 400);
        for (int idx = lane; idx < 100; idx += 32) ((float4*)w->A)[idx] = Xb4[idx];
        __syncwarp();
        jacobi_cm<20, SW_AVG20>(w, lane);
        if (lane < 20) w->aux[lane] = logf(w->A[lane * LDC + lane]);
        __syncwarp();
        if (lane < 20) {
            float rv[20];
            #pragma unroll
            for (int k = 0; k < 20; k++) rv[k] = w->aux[k] * w->V[k * LDC + lane];
            float l[20];
            #pragma unroll
            for (int i = 0; i < 20; i++) l[i] = 0.0f;
            #pragma unroll
            for (int k = 0; k < 20; k++) axpy20(rv[k], w->V + k * LDC, l);
            float4* Lb = (float4*)(g_V2 + (size_t)b * 400 + lane * 20);
            #pragma unroll
            for (int t = 0; t < 5; t++)
                Lb[t] = make_float4(l[4*t], l[4*t+1], l[4*t+2], l[4*t+3]);
        }
        __syncwarp();
    }
}

// ===== K1b: deterministic domain-segmented sum of L over samples =====
__global__ void __launch_bounds__(256) kr_dsum(const int* __restrict__ dom, int B) {
    int warp = threadIdx.x >> 5, lane = threadIdx.x & 31;
    int c = blockIdx.x & 3;
    int split = ((int)blockIdx.x >> 2) * 8 + warp;
    int per = (B + NSPLIT - 1) / NSPLIT;
    int b0 = split * per, b1 = b0 + per;
    if (b1 > B) b1 = B;
    int e = c * 128 + lane * 4;
    bool valid = e < 400;
    float4 a0 = make_float4(0,0,0,0), a1 = a0, a2 = a0, a3 = a0;
    int cnt0 = 0, cnt1 = 0, cnt2 = 0, cnt3 = 0;
    for (int b = b0; b < b1; b++) {
        int d = dom[b];
        float4 v = make_float4(0,0,0,0);
        if (valid) v = *(const float4*)(g_V2 + (size_t)b * 400 + e);
        if (d == 0)      { a0.x += v.x; a0.y += v.y; a0.z += v.z; a0.w += v.w; cnt0++; }
        else if (d == 1) { a1.x += v.x; a1.y += v.y; a1.z += v.z; a1.w += v.w; cnt1++; }
        else if (d == 2) { a2.x += v.x; a2.y += v.y; a2.z += v.z; a2.w += v.w; cnt2++; }
        else             { a3.x += v.x; a3.y += v.y; a3.z += v.z; a3.w += v.w; cnt3++; }
    }
    if (valid) {
        size_t base = (((size_t)c * NSPLIT + split) * NDOM) * 128 + lane * 4;
        *(float4*)(g_part2 + base + 0 * 128) = a0;
        *(float4*)(g_part2 + base + 1 * 128) = a1;
        *(float4*)(g_part2 + base + 2 * 128) = a2;
        *(float4*)(g_part2 + base + 3 * 128) = a3;
    }
    if (c == 0 && lane == 0) {
        g_partCnt[split * NDOM + 0] = (float)cnt0;
        g_partCnt[split * NDOM + 1] = (float)cnt1;
        g_partCnt[split * NDOM + 2] = (float)cnt2;
        g_partCnt[split * NDOM + 3] = (float)cnt3;
    }
}

// ============ K2: reduce partials -> meanL, counts; Ginv[d] = V e^{-w/2} Vt ============
__global__ void __launch_bounds__(256) k_ginv() {
    __shared__ WarpWS ws[4];
    __shared__ float meanL[NDOM * 400];
    int tid = threadIdx.x;
    if (tid < NDOM) {
        float c = 0.0f;
        for (int sp = 0; sp < NSPLIT; sp++) c += g_partCnt[sp * NDOM + tid];
        g_cnt[tid] = c;
    }
    for (int out = tid; out < NDOM * 400; out += 256) {
        int d = out / 400, e = out - d * 400;
        int c = e >> 7, i = e & 127;
        float s = 0.0f;
        for (int sp = 0; sp < NSPLIT; sp++)
            s += g_part2[(((size_t)c * NSPLIT + sp) * NDOM + d) * 128 + i];
        meanL[out] = s;
    }
    __syncthreads();
    int warp = tid >> 5, lane = tid & 31;
    if (warp < 4) {
        int d = warp;
        float inv = 1.0f / g_cnt[d];
        WarpWS* w = &ws[warp];
        for (int idx = lane; idx < 400; idx += 32)
            w->A[idx] = meanL[d * 400 + idx] * inv;
        __syncwarp();
        jacobi_cm<20, SW_SMALL>(w, lane);
        if (lane < 20) w->aux[lane] = expf(-0.5f * w->A[lane * LDC + lane]);
        __syncwarp();
        recompose_cm<20>(w->V, w->aux, g_Ginv + d * 400, lane);
    }
}

// ====== K3: M = Gi X Gi, eigh -> store V,logw; per-domain sum ||logM||^2 ======
__global__ void __launch_bounds__(256) k_center(const float* __restrict__ X,
                                                const int* __restrict__ dom, int B) {
    __shared__ float Gi[NDOM * 400];
    __shared__ float nrmAcc[WPB][NDOM];
    __shared__ WarpWS ws[WPB];
    int tid = threadIdx.x, warp = tid >> 5, lane = tid & 31;
    for (int idx = tid; idx < NDOM * 400; idx += 256) Gi[idx] = g_Ginv[idx];
    if (tid < WPB * NDOM) ((float*)nrmAcc)[tid] = 0.0f;
    __syncthreads();
    WarpWS* w = &ws[warp];
    for (int m = 0; m < MPW; m++) {
        int b = ((int)blockIdx.x * WPB + warp) * MPW + m;
        if (b < B) {
            int d = dom[b];
            const float* G = Gi + d * 400;
            const float4* Xb4 = (const float4*)(X + (size_t)b * 400);
            for (int idx = lane; idx < 100; idx += 32)
                ((float4*)w->V)[idx] = Xb4[idx];
            __syncwarp();
            float res[20];
            if (lane < 20) {
                float g[20];
                #pragma unroll
                for (int k = 0; k < 20; k++) g[k] = G[k * 20 + lane];
                float y[20];
                #pragma unroll
                for (int i = 0; i < 20; i++) y[i] = dot20(w->V + i * 20, g);
                #pragma unroll
                for (int i = 0; i < 20; i++) res[i] = dot20(G + i * 20, y);
            }
            __syncwarp();
            if (lane < 20) {
                float4* Ac = (float4*)(w->A + lane * LDC);
                #pragma unroll
                for (int t = 0; t < 5; t++)
                    Ac[t] = make_float4(res[4*t], res[4*t+1], res[4*t+2], res[4*t+3]);
            }
            jacobi_cm<20, SW_PS20>(w, lane);
            if (lane < 20) w->aux[lane] = logf(w->A[lane * LDC + lane]);
            __syncwarp();
            float4* gV4 = (float4*)(g_V2 + (size_t)b * 400);
            for (int idx = lane; idx < 100; idx += 32) gV4[idx] = ((float4*)w->V)[idx];
            if (lane < 20) g_lw2[(size_t)b * 20 + lane] = w->aux[lane];
            float v = (lane < 20) ? w->aux[lane] * w->aux[lane] : 0.0f;
            #pragma unroll
            for (int off = 16; off; off >>= 1) v += __shfl_down_sync(FULLM, v, off);
            if (lane == 0) nrmAcc[warp][d] += v;
        }
    }
    __syncthreads();
    if (tid == 0) {
        float sums[NDOM] = {0.f, 0.f, 0.f, 0.f};
        for (int t = 0; t < WPB; t++)
            for (int d = 0; d < NDOM; d++) sums[d] += nrmAcc[t][d];
        for (int d = 0; d < NDOM; d++) g_partN[blockIdx.x * NDOM + d] = sums[d];
    }
}

// ============ K4: scale[d] = s / sqrt(sig2 + eps) ============
__global__ void __launch_bounds__(128) k_scale(const float* __restrict__ sptr, int NB) {
    int warp = threadIdx.x >> 5, lane = threadIdx.x & 31;
    int d = warp;
    float nsum = 0.0f;
    for (int b = lane; b < NB; b += 32) nsum += g_partN[b * NDOM + d];
    #pragma unroll
    for (int off = 16; off; off >>= 1) nsum += __shfl_down_sync(FULLM, nsum, off);
    if (lane == 0) {
        float sig2 = nsum / g_cnt[d];
        g_scale[d] = sptr[0] / sqrtf(sig2 + EPS_VAR_F);
    }
}

// ====== K5: Xn via eigenbasis reuse, Y = Wt Xn W, store Y, sum logm(Y) ======
__global__ void __launch_bounds__(256) k_bimap(const float* __restrict__ Wb,
                                               const int* __restrict__ dom, int B) {
    __shared__ float Ws16[320];
    __shared__ float accW[WPB * 240];
    __shared__ WarpWS ws[WPB];
    int tid = threadIdx.x, warp = tid >> 5, lane = tid & 31;
    for (int idx = tid; idx < 320; idx += 256) {
        int i = idx >> 4, o = idx & 15;
        Ws16[idx] = (o < 15) ? Wb[i * 15 + o] : 0.0f;
    }
    __syncthreads();
    WarpWS* w = &ws[warp];
    float la[15];
    #pragma unroll
    for (int i = 0; i < 15; i++) la[i] = 0.0f;

    for (int m = 0; m < MPW; m++) {
        int b = ((int)blockIdx.x * WPB + warp) * MPW + m;
        if (b >= B) continue;
        int d = dom[b];
        float sc = g_scale[d];
        const float* gV = g_V2 + (size_t)b * 400;
        float c[16];
        if (lane < 20) {
            float ej = expf(0.5f * sc * g_lw2[(size_t)b * 20 + lane]);
            float z[20];
            const float4* col4 = (const float4*)(gV + lane * 20);
            #pragma unroll
            for (int t = 0; t < 5; t++) {
                float4 v = col4[t];
                z[4*t+0] = v.x * ej; z[4*t+1] = v.y * ej;
                z[4*t+2] = v.z * ej; z[4*t+3] = v.w * ej;
            }
            #pragma unroll
            for (int o = 0; o < 16; o++) c[o] = 0.0f;
            #pragma unroll
            for (int i = 0; i < 20; i++) axpy16(z[i], Ws16 + i * 16, c);
        }
        __syncwarp();
        if (lane < 20) {
            #pragma unroll
            for (int o = 0; o < 15; o++) w->V[o * 20 + lane] = c[o];
        }
        __syncwarp();
        float y[16];
        if (lane < 15) {
            float cp[20];
            const float4* row4 = (const float4*)(w->V + lane * 20);
            #pragma unroll
            for (int t = 0; t < 5; t++) {
                float4 v = row4[t];
                cp[4*t+0] = v.x; cp[4*t+1] = v.y; cp[4*t+2] = v.z; cp[4*t+3] = v.w;
            }
            #pragma unroll
            for (int o = 0; o < 15; o++) y[o] = dot20(w->V + o * 20, cp);
            y[15] = 0.0f;
        }
        __syncwarp();
        if (lane < 15) {
            float4* Ac = (float4*)(w->A + lane * LDC);
            float4* gY4 = (float4*)(g_Y + (size_t)b * 240 + lane * 16);
            #pragma unroll
            for (int t = 0; t < 4; t++) {
                float4 v = make_float4(y[4*t], y[4*t+1], y[4*t+2], y[4*t+3]);
                Ac[t] = v;
                gY4[t] = v;
            }
        } else if (lane == 15) {
            float4* Ac = (float4*)(w->A + 15 * LDC);
            #pragma unroll
            for (int t = 0; t < 4; t++) Ac[t] = make_float4(0, 0, 0, 0);
        }
        jacobi_cm<15, SW_AVG15>(w, lane);
        if (lane < 15) w->aux[lane] = logf(w->A[lane * LDC + lane]);
        __syncwarp();
        if (lane < 15) {
            float rv[15];
            #pragma unroll
            for (int k = 0; k < 15; k++) rv[k] = w->aux[k] * w->V[k * LDC + lane];
            float l[16];
            #pragma unroll
            for (int i = 0; i < 16; i++) l[i] = 0.0f;
            #pragma unroll
            for (int k = 0; k < 15; k++) axpy16(rv[k], w->V + k * LDC, l);
            #pragma unroll
            for (int i = 0; i < 15; i++) la[i] += l[i];
        }
        __syncwarp();
    }
    if (lane < 15) {
        #pragma unroll
        for (int i = 0; i < 15; i++) accW[warp * 240 + i * 16 + lane] = la[i];
    }
    __syncthreads();
    for (int idx = tid; idx < 225; idx += 256) {
        int i = idx / 15, j = idx - i * 15;
        float s = 0.0f;
        #pragma unroll
        for (int wp = 0; wp < WPB; wp++) s += accW[wp * 240 + i * 16 + j];
        g_partLY[(size_t)blockIdx.x * 225 + idx] = s;
    }
}

// ============ K6: meanLY -> Gb = V e^{-w/2} Vt (padded 15x16) ============
__global__ void __launch_bounds__(256) k_gb(int B, int NB) {
    __shared__ float meanLY[225];
    __shared__ WarpWS ws0;
    int tid = threadIdx.x, warp = tid >> 5, lane = tid & 31;
    float invB = 1.0f / (float)B;
    for (int out = warp; out < 225; out += 8) {
        float s = 0.0f;
        for (int b = lane; b < NB; b += 32) s += g_partLY[(size_t)b * 225 + out];
        #pragma unroll
        for (int off = 16; off; off >>= 1) s += __shfl_down_sync(FULLM, s, off);
        if (lane == 0) meanLY[out] = s * invB;
    }
    __syncthreads();
    if (warp == 0) {
        for (int idx = lane; idx < 320; idx += 32) ws0.A[idx] = 0.0f;
        __syncwarp();
        for (int idx = lane; idx < 225; idx += 32) {
            int i = idx / 15, j = idx - i * 15;
            ws0.A[j * LDC + i] = meanLY[idx];
        }
        __syncwarp();
        jacobi_cm<15, SW_SMALL>(&ws0, lane);
        if (lane < 15) ws0.aux[lane] = expf(-0.5f * ws0.A[lane * LDC + lane]);
        __syncwarp();
        for (int t = 0; t < 8; t++) {
            int idx = lane + 32 * t;
            if (idx < 240) {
                int i = idx >> 4, j = idx & 15;
                float acc = 0.0f;
                if (j < 15) {
                    #pragma unroll
                    for (int k = 0; k < 15; k++)
                        acc = fmaf(ws0.V[k * LDC + i] * ws0.aux[k], ws0.V[k * LDC + j], acc);
                }
                g_Gb16[idx] = acc;
            }
        }
    }
}

// ====== K7 (PAIRED): Yn = Gb Y Gb, eigh, fused ReEig+LogEig+vec+classifier ======
// Two samples per warp: half = lane>>4 owns its own sample end-to-end.
__global__ void __launch_bounds__(256) k_head(const float* __restrict__ Wl,
                                              float* __restrict__ out, int B) {
    __shared__ float Gbs[240];
    __shared__ float Wf[4 * 240];
    __shared__ PairWS ws[WPB];
    int tid = threadIdx.x, warp = tid >> 5, lane = tid & 31;
    int half = lane >> 4, l16 = lane & 15;
    for (int i = tid; i < 240; i += 256) Gbs[i] = g_Gb16[i];
    for (int idx = tid; idx < 960; idx += 256) {
        int cc = idx / 240, rem = idx - cc * 240;
        int i = rem >> 4, j = rem & 15;
        float v = 0.0f;
        if (i < 15 && j < 15) {
            if (i == j) v = Wl[cc * 120 + i];
            else {
                int a = min(i, j), b2 = max(i, j);
                int off = a * 14 - a * (a - 1) / 2 + (b2 - a - 1);
                v = Wl[cc * 120 + 15 + off] * (SQRT2F * 0.5f);
            }
        }
        Wf[idx] = v;
    }
    __syncthreads();
    PairWS* w = &ws[warp];
    float* bufh = w->buf + half * HSTRIDE;
    int base = ((int)blockIdx.x * WPB + warp) * MPW;

    for (int mp = 0; mp < MPW / 2; mp++) {
        int b = base + mp * 2 + half;           // this half's sample
        bool active = (b < B);
        // load Y (240 floats per half) into bufh
        if (active) {
            const float4* gY4 = (const float4*)(g_Y + (size_t)b * 240);
            for (int idx = l16; idx < 60; idx += 16) ((float4*)bufh)[idx] = gY4[idx];
        } else {
            for (int idx = l16; idx < 60; idx += 16) ((float4*)bufh)[idx] = make_float4(0,0,0,0);
        }
        __syncwarp();
        // res[:,l16] = Gb (Y (Gb[:,l16]))
        float res[16];
        if (l16 < 15) {
            float g[16];
            #pragma unroll
            for (int k = 0; k < 15; k++) g[k] = Gbs[k * 16 + l16];
            g[15] = 0.0f;
            float y[16];
            #pragma unroll
            for (int i = 0; i < 15; i++) y[i] = dot16(bufh + i * 16, g);
            y[15] = 0.0f;
            #pragma unroll
            for (int i = 0; i < 15; i++) res[i] = dot16(Gbs + i * 16, y);
            res[15] = 0.0f;
        }
        __syncwarp();   // Y reads done before A overwrites buf
        // store A (col l16, stride 20); dummy col 15 zeroed by l16==15 lanes
        {
            float4* Ac = (float4*)(bufh + l16 * LDC);
            if (l16 < 15) {
                #pragma unroll
                for (int t = 0; t < 4; t++)
                    Ac[t] = make_float4(res[4*t], res[4*t+1], res[4*t+2], res[4*t+3]);
            } else {
                #pragma unroll
                for (int t = 0; t < 4; t++) Ac[t] = make_float4(0, 0, 0, 0);
            }
        }
        jacobi_pair15<SW_PS15>(w, lane);        // diag -> (float*)w->prm, V spilled into bufh
        float* auxp = (float*)w->prm;
        auxp[half * 16 + l16] = logf(fmaxf(auxp[half * 16 + l16], EPS_REEIG_F));
        __syncwarp();
        // fused recompose + classifier
        float o0 = 0.f, o1 = 0.f, o2 = 0.f, o3 = 0.f;
        if (l16 < 15) {
            const float* aux = auxp + half * 16;
            float rv[15];
            #pragma unroll
            for (int k = 0; k < 15; k++) rv[k] = aux[k] * bufh[k * LDC + l16];
            float l[16];
            #pragma unroll
            for (int i = 0; i < 16; i++) l[i] = 0.0f;
            #pragma unroll
            for (int k = 0; k < 15; k++) axpy16(rv[k], bufh + k * LDC, l);
            #pragma unroll
            for (int i = 0; i < 15; i++) {
                float li = l[i];
                o0 = fmaf(Wf[0 * 240 + i * 16 + l16], li, o0);
                o1 = fmaf(Wf[1 * 240 + i * 16 + l16], li, o1);
                o2 = fmaf(Wf[2 * 240 + i * 16 + l16], li, o2);
                o3 = fmaf(Wf[3 * 240 + i * 16 + l16], li, o3);
            }
        }
        // per-half tree reduce (offsets stay within the 16-lane half for the writer lanes)
        #pragma unroll
        for (int off = 8; off; off >>= 1) {
            o0 += __shfl_down_sync(FULLM, o0, off);
            o1 += __shfl_down_sync(FULLM, o1, off);
            o2 += __shfl_down_sync(FULLM, o2, off);
            o3 += __shfl_down_sync(FULLM, o3, off);
        }
        if (l16 == 0 && active) {
            float* ob = out + (size_t)b * 4;
            ob[0] = o0; ob[1] = o1; ob[2] = o2; ob[3] = o3;
        }
        __syncwarp();
    }
}

extern "C" void kernel_launch(void* const* d_in, const int* in_sizes, int n_in,
                              void* d_out, int out_size) {
    const float* X   = (const float*)d_in[0];
    const int*   dom = (const int*)d_in[1];
    const float* s   = (const float*)d_in[2];
    const float* Wb  = (const float*)d_in[3];
    const float* Wl  = (const float*)d_in[4];
    float* out = (float*)d_out;
    int B = in_sizes[0] / 400;
    if (B > MAXB) B = MAXB;
    int NB = (B + MPB - 1) / MPB;
    if (NB > NB_MAX) NB = NB_MAX;

    k_logsum<<<NB, 256>>>(X, B);
    kr_dsum<<<NCHUNK * (NSPLIT / 8), 256>>>(dom, B);
    k_ginv<<<1, 256>>>();
    k_center<<<NB, 256>>>(X, dom, B);
    k_scale<<<1, 128>>>(s, NB);
    k_bimap<<<NB, 256>>>(Wb, dom, B);
    k_gb<<<1, 256>>>(B, NB);
    k_head<<<NB, 256>>>(Wl, out, B);
}

// round 12
// speedup vs baseline: 1.1469x; 1.0610x over previous
#include <cuda_runtime.h>
#include <math.h>

#define NDOM 4
#define SQRT2F 1.41421356237309515f
#define EPS_REEIG_F 1e-4f
#define EPS_VAR_F 1e-5f

#define MAXB 32768
#define NB_MAX 1024
#define WPB 8            // warps per block
#define MPW 4            // matrices per warp
#define MPB (WPB*MPW)    // 32 matrices per block

#define LDC 20           // column stride (floats) for col-major matrices
#define SW_PS20 5        // per-sample 20x20 (k_center)
#define SW_AVG20 3       // averaged-output 20x20 (k_logsum)
#define SW_PS15 5        // per-sample 15x15 (k_head)
#define SW_AVG15 4       // averaged-output 15x15 (k_bimap)
#define SW_SMALL 7

#define NSPLIT 64        // sample splits for domain reduction
#define NCHUNK 4         // 128-float element chunks (covers 400)

#define FULLM 0xffffffffu
#define HSTRIDE 336      // per-half float offset in PairWS.buf (336 mod 32 = 16 -> bank split)

// ---------------- device scratch (static, allowed) ----------------
__device__ float g_V2[(size_t)MAXB * 400];   // k_logsum: per-sample L; later: eigenvectors of centered matrices
__device__ float g_lw2[(size_t)MAXB * 20];   // log-eigenvalues of centered matrices
__device__ float g_Y[(size_t)MAXB * 240];    // BiMap outputs, rows padded to 16
__device__ float g_part2[(size_t)NCHUNK * NSPLIT * NDOM * 128];
__device__ float g_partCnt[NSPLIT * NDOM];
__device__ float g_partN[NB_MAX * NDOM];
__device__ float g_partLY[NB_MAX * 225];
__device__ float g_cnt[NDOM];
__device__ float g_Ginv[NDOM * 400];
__device__ float g_scale[NDOM];
__device__ float g_Gb16[240];                // 15x16 padded

// ---------------- per-warp workspaces ----------------
struct WarpWS {
    __align__(16) float A[400];     // col-major, LDC=20
    __align__(16) float V[400];     // col-major, LDC=20 (written once post-Jacobi)
    __align__(16) float4 prm[12];   // per-PAIR (c, s, p, q) for tile pass
    __align__(16) float4 cinfo[20]; // per-COLUMN (c, b=±s, partner, pad) for V shfl pass
    float aux[24];
};

// paired 15x15 workspace: two matrices per warp (half = lane>>4)
struct PairWS {
    __align__(16) float buf[2 * HSTRIDE]; // per half: scratch (C or Y) -> A (16 cols x 20) -> V spill
    __align__(16) float4 prm[16];         // per half 8 pairs; reused as aux (32 floats) after jacobi
};

// round-robin tournament pair (circle method), players 0..NS-1, NS even
__device__ __forceinline__ void pair_pq(int k, int r, int M, int& p, int& q) {
    p = (k == 0) ? 0 : (1 + (k - 1 + r) % M);
    q = 1 + (M - 1 - k + r) % M;
}

// Warp-cooperative two-sided Jacobi (single matrix, used for n=20 and tiny kernels).
//   A: smem col-major (LDC), disjoint 2x2 tile pass.
//   V: register-resident, lane j owns column j; SHFL exchange per round; spilled at end.
template<int N, int SWEEPS>
__device__ void jacobi_cm(WarpWS* w, int lane) {
    constexpr int NS = (N + 1) & ~1;
    constexpr int M  = NS - 1;
    constexpr int NP = NS / 2;
    constexpr int NT = NP * NP;
    float* A = w->A;
    float4* prm = w->prm;
    float4* cinfo = w->cinfo;

    float v[NS];
    #pragma unroll
    for (int i = 0; i < NS; i++) v[i] = (i == lane) ? 1.0f : 0.0f;

    for (int sw = 0; sw < SWEEPS; sw++)
    for (int r = 0; r < M; r++) {
        if (lane < NP) {
            int p, q; pair_pq(lane, r, M, p, q);
            float apq = A[q * LDC + p];
            float c = 1.0f, s = 0.0f;
            if (fabsf(apq) > 1e-38f) {
                float app = A[p * LDC + p];
                float aqq = A[q * LDC + q];
                float tau = (aqq - app) / (2.0f * apq);
                float den = fabsf(tau) + sqrtf(fmaf(tau, tau, 1.0f));
                float tt  = (tau >= 0.0f ? 1.0f : -1.0f) / den;
                c = rsqrtf(fmaf(tt, tt, 1.0f));
                s = tt * c;
            }
            prm[lane] = make_float4(c, s, __int_as_float(p), __int_as_float(q));
            cinfo[p] = make_float4(c, -s, __int_as_float(q), 0.0f);
            cinfo[q] = make_float4(c,  s, __int_as_float(p), 0.0f);
        }
        __syncwarp();
        float4 ci = cinfo[(lane < NS) ? lane : 0];
        float cc = (lane < NS) ? ci.x : 1.0f;
        float bb = (lane < NS) ? ci.y : 0.0f;
        int  prt = (lane < NS) ? __float_as_int(ci.z) : lane;
        #pragma unroll
        for (int t = 0; t < (NT + 31) / 32; t++) {
            int idx = lane + 32 * t;
            if (idx < NT) {
                int ki = idx / NP, kj = idx - ki * NP;
                float4 pi4 = prm[ki], pj4 = prm[kj];
                float ci_ = pi4.x, si = pi4.y;
                int pi = __float_as_int(pi4.z), qi = __float_as_int(pi4.w);
                float cj = pj4.x, sj = pj4.y;
                int pj = __float_as_int(pj4.z), qj = __float_as_int(pj4.w);
                float a00 = A[pj * LDC + pi], a01 = A[qj * LDC + pi];
                float a10 = A[pj * LDC + qi], a11 = A[qj * LDC + qi];
                float r00 = fmaf(ci_, a00, -si * a10), r10 = fmaf(si, a00, ci_ * a10);
                float r01 = fmaf(ci_, a01, -si * a11), r11 = fmaf(si, a01, ci_ * a11);
                A[pj * LDC + pi] = fmaf(cj, r00, -sj * r01);
                A[qj * LDC + pi] = fmaf(sj, r00,  cj * r01);
                A[pj * LDC + qi] = fmaf(cj, r10, -sj * r11);
                A[qj * LDC + qi] = fmaf(sj, r10,  cj * r11);
            }
        }
        #pragma unroll
        for (int i = 0; i < NS; i++) {
            float rv = __shfl_sync(FULLM, v[i], prt);
            v[i] = fmaf(cc, v[i], bb * rv);
        }
        __syncwarp();
    }

    if (lane < NS) {
        float4* Vc = (float4*)(w->V + lane * LDC);
        #pragma unroll
        for (int t = 0; t < NS / 4; t++)
            Vc[t] = make_float4(v[4*t], v[4*t+1], v[4*t+2], v[4*t+3]);
    }
    __syncwarp();
}

// Paired 15x15 Jacobi: two matrices per warp (half = lane>>4, column = lane&15).
// A at buf + half*HSTRIDE (col stride 20, 16 cols, dummy col/row 15 zero).
// V register-resident per half; diag -> prm region (as aux); V spilled OVER A region.
template<int SWEEPS>
__device__ void jacobi_pair15(PairWS* w, int lane) {
    constexpr int MP = 15, NPP = 8;
    int half = lane >> 4, l16 = lane & 15;
    float* A = w->buf + half * HSTRIDE;
    float4* prmh = w->prm + half * 8;

    float v[16];
    #pragma unroll
    for (int i = 0; i < 16; i++) v[i] = (i == l16) ? 1.0f : 0.0f;

    for (int sw = 0; sw < SWEEPS; sw++)
    for (int r = 0; r < MP; r++) {
        // ---- params: 16 lanes (8 per half) ----
        if (l16 < NPP) {
            int p, q; pair_pq(l16, r, MP, p, q);
            float apq = A[q * LDC + p];
            float c = 1.0f, s = 0.0f;
            if (fabsf(apq) > 1e-38f) {
                float app = A[p * LDC + p];
                float aqq = A[q * LDC + q];
                float tau = (aqq - app) / (2.0f * apq);
                float den = fabsf(tau) + sqrtf(fmaf(tau, tau, 1.0f));
                float tt  = (tau >= 0.0f ? 1.0f : -1.0f) / den;
                c = rsqrtf(fmaf(tt, tt, 1.0f));
                s = tt * c;
            }
            prmh[l16] = make_float4(c, s, __int_as_float(p), __int_as_float(q));
        }
        __syncwarp();
        // ---- analytic partner/role for column l16 ----
        int k, prt; float sgn;
        if (l16 == 0) {
            k = 0; prt = 1 + (MP - 1 + r) % MP; sgn = -1.0f;            // role p
        } else {
            int j = l16 - 1 - r; j %= MP; if (j < 0) j += MP;
            int kp = j + 1;
            if (kp <= NPP - 1) {                                        // role p of pair kp
                k = kp; prt = 1 + (MP - 1 - k + r) % MP; sgn = -1.0f;
            } else {                                                    // role q
                k = (MP + r - l16) % MP;
                prt = (k == 0) ? 0 : 1 + (k - 1 + r) % MP;
                sgn = 1.0f;
            }
        }
        float4 pk = prmh[k];
        float cc = pk.x, bb = sgn * pk.y;
        int src = (half << 4) | prt;
        // ---- tile pass: 128 tiles over both halves ----
        #pragma unroll
        for (int t = 0; t < 4; t++) {
            int idx = lane + 32 * t;
            int h2 = idx >> 6, tile = idx & 63;
            int ki = tile >> 3, kj = tile & 7;
            const float4* prr = w->prm + h2 * 8;
            float* Ah = w->buf + h2 * HSTRIDE;
            float4 pi4 = prr[ki], pj4 = prr[kj];
            float ci_ = pi4.x, si = pi4.y;
            int pi = __float_as_int(pi4.z), qi = __float_as_int(pi4.w);
            float cj = pj4.x, sj = pj4.y;
            int pj = __float_as_int(pj4.z), qj = __float_as_int(pj4.w);
            float a00 = Ah[pj * LDC + pi], a01 = Ah[qj * LDC + pi];
            float a10 = Ah[pj * LDC + qi], a11 = Ah[qj * LDC + qi];
            float r00 = fmaf(ci_, a00, -si * a10), r10 = fmaf(si, a00, ci_ * a10);
            float r01 = fmaf(ci_, a01, -si * a11), r11 = fmaf(si, a01, ci_ * a11);
            Ah[pj * LDC + pi] = fmaf(cj, r00, -sj * r01);
            Ah[qj * LDC + pi] = fmaf(sj, r00,  cj * r01);
            Ah[pj * LDC + qi] = fmaf(cj, r10, -sj * r11);
            Ah[qj * LDC + qi] = fmaf(sj, r10,  cj * r11);
        }
        // ---- V rotation (all 32 lanes useful) ----
        #pragma unroll
        for (int i = 0; i < 16; i++) {
            float rv = __shfl_sync(FULLM, v[i], src);
            v[i] = fmaf(cc, v[i], bb * rv);
        }
        __syncwarp();
    }

    // diag -> aux (reuse prm memory), then spill V over A region
    float dg = A[l16 * LDC + l16];
    __syncwarp();
    float* auxp = (float*)w->prm;
    auxp[half * 16 + l16] = dg;
    float4* Vc = (float4*)(A + l16 * LDC);
    #pragma unroll
    for (int t = 0; t < 4; t++)
        Vc[t] = make_float4(v[4*t], v[4*t+1], v[4*t+2], v[4*t+3]);
    __syncwarp();
}

// ---------- float4 dot / axpy helpers ----------
__device__ __forceinline__ float dot20(const float* row, const float* g) {
    const float4* r4 = (const float4*)row;
    float a = 0.0f;
    #pragma unroll
    for (int t = 0; t < 5; t++) {
        float4 x = r4[t];
        a = fmaf(x.x, g[4*t+0], a); a = fmaf(x.y, g[4*t+1], a);
        a = fmaf(x.z, g[4*t+2], a); a = fmaf(x.w, g[4*t+3], a);
    }
    return a;
}
__device__ __forceinline__ float dot16(const float* row, const float* g) {
    const float4* r4 = (const float4*)row;
    float a = 0.0f;
    #pragma unroll
    for (int t = 0; t < 4; t++) {
        float4 x = r4[t];
        a = fmaf(x.x, g[4*t+0], a); a = fmaf(x.y, g[4*t+1], a);
        a = fmaf(x.z, g[4*t+2], a); a = fmaf(x.w, g[4*t+3], a);
    }
    return a;
}
__device__ __forceinline__ void axpy20(float u, const float* col, float* l) {
    const float4* c4 = (const float4*)col;
    #pragma unroll
    for (int t = 0; t < 5; t++) {
        float4 x = c4[t];
        l[4*t+0] = fmaf(u, x.x, l[4*t+0]); l[4*t+1] = fmaf(u, x.y, l[4*t+1]);
        l[4*t+2] = fmaf(u, x.z, l[4*t+2]); l[4*t+3] = fmaf(u, x.w, l[4*t+3]);
    }
}
__device__ __forceinline__ void axpy16(float u, const float* col, float* l) {
    const float4* c4 = (const float4*)col;
    #pragma unroll
    for (int t = 0; t < 4; t++) {
        float4 x = c4[t];
        l[4*t+0] = fmaf(u, x.x, l[4*t+0]); l[4*t+1] = fmaf(u, x.y, l[4*t+1]);
        l[4*t+2] = fmaf(u, x.z, l[4*t+2]); l[4*t+3] = fmaf(u, x.w, l[4*t+3]);
    }
}

// scalar recompose for tiny kernels: Out[i*N+j] = sum_k V[i,k] fw[k] V[j,k]
template<int N>
__device__ __forceinline__ void recompose_cm(const float* V, const float* fw,
                                             float* Out, int lane) {
    #pragma unroll
    for (int t = 0; t < (N * N + 31) / 32; t++) {
        int idx = lane + 32 * t;
        if (idx < N * N) {
            int i = idx / N, j = idx - i * N;
            float acc = 0.0f;
            #pragma unroll
            for (int k = 0; k < N; k++)
                acc = fmaf(V[k * LDC + i] * fw[k], V[k * LDC + j], acc);
            Out[idx] = acc;
        }
    }
}

// ============ K1: per-sample logm(X) -> g_V2 (as L scratch) ============
__global__ void __launch_bounds__(256) k_logsum(const float* __restrict__ X, int B) {
    __shared__ WarpWS ws[WPB];
    int tid = threadIdx.x, warp = tid >> 5, lane = tid & 31;
    WarpWS* w = &ws[warp];
    for (int m = 0; m < MPW; m++) {
        int b = ((int)blockIdx.x * WPB + warp) * MPW + m;
        if (b >= B) continue;
        const float4* Xb4 = (const float4*)(X + (size_t)b * 400);
        for (int idx = lane; idx < 100; idx += 32) ((float4*)w->A)[idx] = Xb4[idx];
        __syncwarp();
        jacobi_cm<20, SW_AVG20>(w, lane);
        if (lane < 20) w->aux[lane] = logf(w->A[lane * LDC + lane]);
        __syncwarp();
        if (lane < 20) {
            float rv[20];
            #pragma unroll
            for (int k = 0; k < 20; k++) rv[k] = w->aux[k] * w->V[k * LDC + lane];
            float l[20];
            #pragma unroll
            for (int i = 0; i < 20; i++) l[i] = 0.0f;
            #pragma unroll
            for (int k = 0; k < 20; k++) axpy20(rv[k], w->V + k * LDC, l);
            float4* Lb = (float4*)(g_V2 + (size_t)b * 400 + lane * 20);
            #pragma unroll
            for (int t = 0; t < 5; t++)
                Lb[t] = make_float4(l[4*t], l[4*t+1], l[4*t+2], l[4*t+3]);
        }
        __syncwarp();
    }
}

// ===== K1b: deterministic domain-segmented sum of L over samples =====
__global__ void __launch_bounds__(256) kr_dsum(const int* __restrict__ dom, int B) {
    int warp = threadIdx.x >> 5, lane = threadIdx.x & 31;
    int c = blockIdx.x & 3;
    int split = ((int)blockIdx.x >> 2) * 8 + warp;
    int per = (B + NSPLIT - 1) / NSPLIT;
    int b0 = split * per, b1 = b0 + per;
    if (b1 > B) b1 = B;
    int e = c * 128 + lane * 4;
    bool valid = e < 400;
    float4 a0 = make_float4(0,0,0,0), a1 = a0, a2 = a0, a3 = a0;
    int cnt0 = 0, cnt1 = 0, cnt2 = 0, cnt3 = 0;
    for (int b = b0; b < b1; b++) {
        int d = dom[b];
        float4 v = make_float4(0,0,0,0);
        if (valid) v = *(const float4*)(g_V2 + (size_t)b * 400 + e);
        if (d == 0)      { a0.x += v.x; a0.y += v.y; a0.z += v.z; a0.w += v.w; cnt0++; }
        else if (d == 1) { a1.x += v.x; a1.y += v.y; a1.z += v.z; a1.w += v.w; cnt1++; }
        else if (d == 2) { a2.x += v.x; a2.y += v.y; a2.z += v.z; a2.w += v.w; cnt2++; }
        else             { a3.x += v.x; a3.y += v.y; a3.z += v.z; a3.w += v.w; cnt3++; }
    }
    if (valid) {
        size_t base = (((size_t)c * NSPLIT + split) * NDOM) * 128 + lane * 4;
        *(float4*)(g_part2 + base + 0 * 128) = a0;
        *(float4*)(g_part2 + base + 1 * 128) = a1;
        *(float4*)(g_part2 + base + 2 * 128) = a2;
        *(float4*)(g_part2 + base + 3 * 128) = a3;
    }
    if (c == 0 && lane == 0) {
        g_partCnt[split * NDOM + 0] = (float)cnt0;
        g_partCnt[split * NDOM + 1] = (float)cnt1;
        g_partCnt[split * NDOM + 2] = (float)cnt2;
        g_partCnt[split * NDOM + 3] = (float)cnt3;
    }
}

// ============ K2: reduce partials -> meanL, counts; Ginv[d] = V e^{-w/2} Vt ============
__global__ void __launch_bounds__(256) k_ginv() {
    __shared__ WarpWS ws[4];
    __shared__ float meanL[NDOM * 400];
    int tid = threadIdx.x;
    if (tid < NDOM) {
        float c = 0.0f;
        for (int sp = 0; sp < NSPLIT; sp++) c += g_partCnt[sp * NDOM + tid];
        g_cnt[tid] = c;
    }
    for (int out = tid; out < NDOM * 400; out += 256) {
        int d = out / 400, e = out - d * 400;
        int c = e >> 7, i = e & 127;
        float s = 0.0f;
        for (int sp = 0; sp < NSPLIT; sp++)
            s += g_part2[(((size_t)c * NSPLIT + sp) * NDOM + d) * 128 + i];
        meanL[out] = s;
    }
    __syncthreads();
    int warp = tid >> 5, lane = tid & 31;
    if (warp < 4) {
        int d = warp;
        float inv = 1.0f / g_cnt[d];
        WarpWS* w = &ws[warp];
        for (int idx = lane; idx < 400; idx += 32)
            w->A[idx] = meanL[d * 400 + idx] * inv;
        __syncwarp();
        jacobi_cm<20, SW_SMALL>(w, lane);
        if (lane < 20) w->aux[lane] = expf(-0.5f * w->A[lane * LDC + lane]);
        __syncwarp();
        recompose_cm<20>(w->V, w->aux, g_Ginv + d * 400, lane);
    }
}

// ====== K3: M = Gi X Gi, eigh -> store V,logw; per-domain sum ||logM||^2 ======
__global__ void __launch_bounds__(256) k_center(const float* __restrict__ X,
                                                const int* __restrict__ dom, int B) {
    __shared__ float Gi[NDOM * 400];
    __shared__ float nrmAcc[WPB][NDOM];
    __shared__ WarpWS ws[WPB];
    int tid = threadIdx.x, warp = tid >> 5, lane = tid & 31;
    for (int idx = tid; idx < NDOM * 400; idx += 256) Gi[idx] = g_Ginv[idx];
    if (tid < WPB * NDOM) ((float*)nrmAcc)[tid] = 0.0f;
    __syncthreads();
    WarpWS* w = &ws[warp];
    for (int m = 0; m < MPW; m++) {
        int b = ((int)blockIdx.x * WPB + warp) * MPW + m;
        if (b < B) {
            int d = dom[b];
            const float* G = Gi + d * 400;
            const float4* Xb4 = (const float4*)(X + (size_t)b * 400);
            for (int idx = lane; idx < 100; idx += 32)
                ((float4*)w->V)[idx] = Xb4[idx];
            __syncwarp();
            float res[20];
            if (lane < 20) {
                float g[20];
                #pragma unroll
                for (int k = 0; k < 20; k++) g[k] = G[k * 20 + lane];
                float y[20];
                #pragma unroll
                for (int i = 0; i < 20; i++) y[i] = dot20(w->V + i * 20, g);
                #pragma unroll
                for (int i = 0; i < 20; i++) res[i] = dot20(G + i * 20, y);
            }
            __syncwarp();
            if (lane < 20) {
                float4* Ac = (float4*)(w->A + lane * LDC);
                #pragma unroll
                for (int t = 0; t < 5; t++)
                    Ac[t] = make_float4(res[4*t], res[4*t+1], res[4*t+2], res[4*t+3]);
            }
            jacobi_cm<20, SW_PS20>(w, lane);
            if (lane < 20) w->aux[lane] = logf(w->A[lane * LDC + lane]);
            __syncwarp();
            float4* gV4 = (float4*)(g_V2 + (size_t)b * 400);
            for (int idx = lane; idx < 100; idx += 32) gV4[idx] = ((float4*)w->V)[idx];
            if (lane < 20) g_lw2[(size_t)b * 20 + lane] = w->aux[lane];
            float v = (lane < 20) ? w->aux[lane] * w->aux[lane] : 0.0f;
            #pragma unroll
            for (int off = 16; off; off >>= 1) v += __shfl_down_sync(FULLM, v, off);
            if (lane == 0) nrmAcc[warp][d] += v;
        }
    }
    __syncthreads();
    if (tid == 0) {
        float sums[NDOM] = {0.f, 0.f, 0.f, 0.f};
        for (int t = 0; t < WPB; t++)
            for (int d = 0; d < NDOM; d++) sums[d] += nrmAcc[t][d];
        for (int d = 0; d < NDOM; d++) g_partN[blockIdx.x * NDOM + d] = sums[d];
    }
}

// ============ K4: scale[d] = s / sqrt(sig2 + eps) ============
__global__ void __launch_bounds__(128) k_scale(const float* __restrict__ sptr, int NB) {
    int warp = threadIdx.x >> 5, lane = threadIdx.x & 31;
    int d = warp;
    float nsum = 0.0f;
    for (int b = lane; b < NB; b += 32) nsum += g_partN[b * NDOM + d];
    #pragma unroll
    for (int off = 16; off; off >>= 1) nsum += __shfl_down_sync(FULLM, nsum, off);
    if (lane == 0) {
        float sig2 = nsum / g_cnt[d];
        g_scale[d] = sptr[0] / sqrtf(sig2 + EPS_VAR_F);
    }
}

// ====== K5 (PAIRED eigh): Xn via eigenbasis reuse, Y = Wt Xn W, store Y, sum logm(Y) ======
// Y construction runs full-warp per sample (needs 20 lanes); the 15x15 eigh and
// logm-recompose run PAIRED (two samples per warp, half = lane>>4).
__global__ void __launch_bounds__(256) k_bimap(const float* __restrict__ Wb,
                                               const int* __restrict__ dom, int B) {
    __shared__ float Ws16[320];              // 20x16 padded W_bimap
    __shared__ float accW[WPB * 2 * 240];    // per warp-half LY accumulators (15x16 padded)
    __shared__ PairWS ws[WPB];
    int tid = threadIdx.x, warp = tid >> 5, lane = tid & 31;
    int half = lane >> 4, l16 = lane & 15;
    for (int idx = tid; idx < 320; idx += 256) {
        int i = idx >> 4, o = idx & 15;
        Ws16[idx] = (o < 15) ? Wb[i * 15 + o] : 0.0f;
    }
    __syncthreads();
    PairWS* w = &ws[warp];
    float* bufh = w->buf + half * HSTRIDE;
    int base = ((int)blockIdx.x * WPB + warp) * MPW;
    float la[15];
    #pragma unroll
    for (int i = 0; i < 15; i++) la[i] = 0.0f;

    for (int mp = 0; mp < MPW / 2; mp++) {
        // ---- Y construction: two samples sequentially, full warp each ----
        for (int h = 0; h < 2; h++) {
            int b = base + mp * 2 + h;
            float* bh = w->buf + h * HSTRIDE;
            if (b < B) {
                int d = dom[b];
                float sc = g_scale[d];
                const float* gV = g_V2 + (size_t)b * 400;
                float c[16];
                if (lane < 20) {
                    float ej = expf(0.5f * sc * g_lw2[(size_t)b * 20 + lane]);
                    float z[20];
                    const float4* col4 = (const float4*)(gV + lane * 20);
                    #pragma unroll
                    for (int t = 0; t < 5; t++) {
                        float4 v = col4[t];
                        z[4*t+0] = v.x * ej; z[4*t+1] = v.y * ej;
                        z[4*t+2] = v.z * ej; z[4*t+3] = v.w * ej;
                    }
                    #pragma unroll
                    for (int o = 0; o < 16; o++) c[o] = 0.0f;
                    #pragma unroll
                    for (int i = 0; i < 20; i++) axpy16(z[i], Ws16 + i * 16, c);
                }
                __syncwarp();
                if (lane < 20) {
                    #pragma unroll
                    for (int o = 0; o < 15; o++) bh[o * 20 + lane] = c[o];  // C rows contiguous
                }
                __syncwarp();
                float y[16];
                if (lane < 15) {                 // Y[:,lane] = C C^T column
                    float cp[20];
                    const float4* row4 = (const float4*)(bh + lane * 20);
                    #pragma unroll
                    for (int t = 0; t < 5; t++) {
                        float4 v = row4[t];
                        cp[4*t+0] = v.x; cp[4*t+1] = v.y; cp[4*t+2] = v.z; cp[4*t+3] = v.w;
                    }
                    #pragma unroll
                    for (int o = 0; o < 15; o++) y[o] = dot20(bh + o * 20, cp);
                    y[15] = 0.0f;
                }
                __syncwarp();                    // all C reads done before A overwrites
                if (lane < 15) {
                    float4* Ac = (float4*)(bh + lane * LDC);
                    float4* gY4 = (float4*)(g_Y + (size_t)b * 240 + lane * 16);
                    #pragma unroll
                    for (int t = 0; t < 4; t++) {
                        float4 v = make_float4(y[4*t], y[4*t+1], y[4*t+2], y[4*t+3]);
                        Ac[t] = v;
                        gY4[t] = v;
                    }
                } else if (lane == 15) {
                    float4* Ac = (float4*)(bh + 15 * LDC);
                    #pragma unroll
                    for (int t = 0; t < 4; t++) Ac[t] = make_float4(0, 0, 0, 0);
                }
            } else {
                for (int idx = lane; idx < 320; idx += 32) bh[idx] = 0.0f;
            }
            __syncwarp();
        }
        // ---- paired eigh on both halves ----
        jacobi_pair15<SW_AVG15>(w, lane);        // diag -> (float*)w->prm, V spilled into buf
        int bsel = base + mp * 2 + half;
        bool act = (bsel < B);
        float* auxp = (float*)w->prm;
        float dg = auxp[half * 16 + l16];
        auxp[half * 16 + l16] = act ? logf(dg) : 0.0f;
        __syncwarp();
        // ---- paired logm recompose + LY accumulation ----
        if (l16 < 15 && act) {
            const float* aux = auxp + half * 16;
            float rv[15];
            #pragma unroll
            for (int k = 0; k < 15; k++) rv[k] = aux[k] * bufh[k * LDC + l16];
            float l[16];
            #pragma unroll
            for (int i = 0; i < 16; i++) l[i] = 0.0f;
            #pragma unroll
            for (int k = 0; k < 15; k++) axpy16(rv[k], bufh + k * LDC, l);
            #pragma unroll
            for (int i = 0; i < 15; i++) la[i] += l[i];
        }
        __syncwarp();
    }
    if (l16 < 15) {
        float* dst = accW + (warp * 2 + half) * 240;
        #pragma unroll
        for (int i = 0; i < 15; i++) dst[i * 16 + l16] = la[i];
    }
    __syncthreads();
    for (int idx = tid; idx < 225; idx += 256) {
        int i = idx / 15, j = idx - i * 15;
        float s = 0.0f;
        #pragma unroll
        for (int wp = 0; wp < WPB * 2; wp++) s += accW[wp * 240 + i * 16 + j];
        g_partLY[(size_t)blockIdx.x * 225 + idx] = s;
    }
}

// ============ K6: meanLY -> Gb = V e^{-w/2} Vt (padded 15x16) ============
__global__ void __launch_bounds__(256) k_gb(int B, int NB) {
    __shared__ float meanLY[225];
    __shared__ WarpWS ws0;
    int tid = threadIdx.x, warp = tid >> 5, lane = tid & 31;
    float invB = 1.0f / (float)B;
    for (int out = warp; out < 225; out += 8) {
        float s = 0.0f;
        for (int b = lane; b < NB; b += 32) s += g_partLY[(size_t)b * 225 + out];
        #pragma unroll
        for (int off = 16; off; off >>= 1) s += __shfl_down_sync(FULLM, s, off);
        if (lane == 0) meanLY[out] = s * invB;
    }
    __syncthreads();
    if (warp == 0) {
        for (int idx = lane; idx < 320; idx += 32) ws0.A[idx] = 0.0f;
        __syncwarp();
        for (int idx = lane; idx < 225; idx += 32) {
            int i = idx / 15, j = idx - i * 15;
            ws0.A[j * LDC + i] = meanLY[idx];
        }
        __syncwarp();
        jacobi_cm<15, SW_SMALL>(&ws0, lane);
        if (lane < 15) ws0.aux[lane] = expf(-0.5f * ws0.A[lane * LDC + lane]);
        __syncwarp();
        for (int t = 0; t < 8; t++) {
            int idx = lane + 32 * t;
            if (idx < 240) {
                int i = idx >> 4, j = idx & 15;
                float acc = 0.0f;
                if (j < 15) {
                    #pragma unroll
                    for (int k = 0; k < 15; k++)
                        acc = fmaf(ws0.V[k * LDC + i] * ws0.aux[k], ws0.V[k * LDC + j], acc);
                }
                g_Gb16[idx] = acc;
            }
        }
    }
}

// ====== K7 (PAIRED): Yn = Gb Y Gb, eigh, fused ReEig+LogEig+vec+classifier ======
__global__ void __launch_bounds__(256) k_head(const float* __restrict__ Wl,
                                              float* __restrict__ out, int B) {
    __shared__ float Gbs[240];
    __shared__ float Wf[4 * 240];
    __shared__ PairWS ws[WPB];
    int tid = threadIdx.x, warp = tid >> 5, lane = tid & 31;
    int half = lane >> 4, l16 = lane & 15;
    for (int i = tid; i < 240; i += 256) Gbs[i] = g_Gb16[i];
    for (int idx = tid; idx < 960; idx += 256) {
        int cc = idx / 240, rem = idx - cc * 240;
        int i = rem >> 4, j = rem & 15;
        float v = 0.0f;
        if (i < 15 && j < 15) {
            if (i == j) v = Wl[cc * 120 + i];
            else {
                int a = min(i, j), b2 = max(i, j);
                int off = a * 14 - a * (a - 1) / 2 + (b2 - a - 1);
                v = Wl[cc * 120 + 15 + off] * (SQRT2F * 0.5f);
            }
        }
        Wf[idx] = v;
    }
    __syncthreads();
    PairWS* w = &ws[warp];
    float* bufh = w->buf + half * HSTRIDE;
    int base = ((int)blockIdx.x * WPB + warp) * MPW;

    for (int mp = 0; mp < MPW / 2; mp++) {
        int b = base + mp * 2 + half;
        bool active = (b < B);
        if (active) {
            const float4* gY4 = (const float4*)(g_Y + (size_t)b * 240);
            for (int idx = l16; idx < 60; idx += 16) ((float4*)bufh)[idx] = gY4[idx];
        } else {
            for (int idx = l16; idx < 60; idx += 16) ((float4*)bufh)[idx] = make_float4(0,0,0,0);
        }
        __syncwarp();
        float res[16];
        if (l16 < 15) {
            float g[16];
            #pragma unroll
            for (int k = 0; k < 15; k++) g[k] = Gbs[k * 16 + l16];
            g[15] = 0.0f;
            float y[16];
            #pragma unroll
            for (int i = 0; i < 15; i++) y[i] = dot16(bufh + i * 16, g);
            y[15] = 0.0f;
            #pragma unroll
            for (int i = 0; i < 15; i++) res[i] = dot16(Gbs + i * 16, y);
            res[15] = 0.0f;
        }
        __syncwarp();
        {
            float4* Ac = (float4*)(bufh + l16 * LDC);
            if (l16 < 15) {
                #pragma unroll
                for (int t = 0; t < 4; t++)
                    Ac[t] = make_float4(res[4*t], res[4*t+1], res[4*t+2], res[4*t+3]);
            } else {
                #pragma unroll
                for (int t = 0; t < 4; t++) Ac[t] = make_float4(0, 0, 0, 0);
            }
        }
        jacobi_pair15<SW_PS15>(w, lane);
        float* auxp = (float*)w->prm;
        auxp[half * 16 + l16] = logf(fmaxf(auxp[half * 16 + l16], EPS_REEIG_F));
        __syncwarp();
        float o0 = 0.f, o1 = 0.f, o2 = 0.f, o3 = 0.f;
        if (l16 < 15) {
            const float* aux = auxp + half * 16;
            float rv[15];
            #pragma unroll
            for (int k = 0; k < 15; k++) rv[k] = aux[k] * bufh[k * LDC + l16];
            float l[16];
            #pragma unroll
            for (int i = 0; i < 16; i++) l[i] = 0.0f;
            #pragma unroll
            for (int k = 0; k < 15; k++) axpy16(rv[k], bufh + k * LDC, l);
            #pragma unroll
            for (int i = 0; i < 15; i++) {
                float li = l[i];
                o0 = fmaf(Wf[0 * 240 + i * 16 + l16], li, o0);
                o1 = fmaf(Wf[1 * 240 + i * 16 + l16], li, o1);
                o2 = fmaf(Wf[2 * 240 + i * 16 + l16], li, o2);
                o3 = fmaf(Wf[3 * 240 + i * 16 + l16], li, o3);
            }
        }
        #pragma unroll
        for (int off = 8; off; off >>= 1) {
            o0 += __shfl_down_sync(FULLM, o0, off);
            o1 += __shfl_down_sync(FULLM, o1, off);
            o2 += __shfl_down_sync(FULLM, o2, off);
            o3 += __shfl_down_sync(FULLM, o3, off);
        }
        if (l16 == 0 && active) {
            float* ob = out + (size_t)b * 4;
            ob[0] = o0; ob[1] = o1; ob[2] = o2; ob[3] = o3;
        }
        __syncwarp();
    }
}

extern "C" void kernel_launch(void* const* d_in, const int* in_sizes, int n_in,
                              void* d_out, int out_size) {
    const float* X   = (const float*)d_in[0];
    const int*   dom = (const int*)d_in[1];
    const float* s   = (const float*)d_in[2];
    const float* Wb  = (const float*)d_in[3];
    const float* Wl  = (const float*)d_in[4];
    float* out = (float*)d_out;
    int B = in_sizes[0] / 400;
    if (B > MAXB) B = MAXB;
    int NB = (B + MPB - 1) / MPB;
    if (NB > NB_MAX) NB = NB_MAX;

    k_logsum<<<NB, 256>>>(X, B);
    kr_dsum<<<NCHUNK * (NSPLIT / 8), 256>>>(dom, B);
    k_ginv<<<1, 256>>>();
    k_center<<<NB, 256>>>(X, dom, B);
    k_scale<<<1, 128>>>(s, NB);
    k_bimap<<<NB, 256>>>(Wb, dom, B);
    k_gb<<<1, 256>>>(B, NB);
    k_head<<<NB, 256>>>(Wl, out, B);
}

// round 13
// speedup vs baseline: 1.1708x; 1.0209x over previous
#include <cuda_runtime.h>
#include <math.h>

#define NDOM 4
#define SQRT2F 1.41421356237309515f
#define EPS_REEIG_F 1e-4f
#define EPS_VAR_F 1e-5f

#define MAXB 32768
#define NB_MAX 1024
#define WPB 8            // warps per block
#define MPW 4            // matrices per warp
#define MPB (WPB*MPW)    // 32 matrices per block

#define LDC 20           // column stride (floats) for col-major matrices
#define SW_PS20 5        // per-sample 20x20 (k_center)
#define SW_AVG20 3       // averaged-output 20x20 (k_logsum)
#define SW_PS15 5        // per-sample 15x15 (k_head)
#define SW_AVG15 4       // averaged-output 15x15 (k_bimap)
#define SW_SMALL 7

#define NSPLIT 64        // sample splits for domain reduction
#define NCHUNK 4         // 128-float element chunks (covers 400)

#define FULLM 0xffffffffu
#define HSTRIDE 336      // per-half float offset in PairWS.buf (336 mod 32 = 16 -> bank split)

// ---------------- device scratch (static, allowed) ----------------
__device__ float g_V2[(size_t)MAXB * 400];   // k_logsum: per-sample L; later: eigenvectors of centered matrices
__device__ float g_lw2[(size_t)MAXB * 20];   // log-eigenvalues of centered matrices
__device__ float g_Y[(size_t)MAXB * 240];    // BiMap outputs, rows padded to 16
__device__ float g_part2[(size_t)NCHUNK * NSPLIT * NDOM * 128];
__device__ float g_partCnt[NSPLIT * NDOM];
__device__ float g_partN[NB_MAX * NDOM];
__device__ float g_partLY[NB_MAX * 225];
__device__ float g_cnt[NDOM];
__device__ float g_Ginv[NDOM * 400];
__device__ float g_scale[NDOM];
__device__ float g_Gb16[240];                // 15x16 padded

// ---------------- per-warp workspaces ----------------
struct WarpWS {
    __align__(16) float A[400];     // col-major, LDC=20
    __align__(16) float V[400];     // col-major, LDC=20 (written once post-Jacobi)
    __align__(16) float4 prm[12];   // per-PAIR (c, s, p, q) for tile pass
    __align__(16) float4 cinfo[20]; // per-COLUMN (c, b=±s, partner, pad) for V shfl pass
    float aux[24];
};

// paired 15x15 workspace: two matrices per warp (half = lane>>4)
struct PairWS {
    __align__(16) float buf[2 * HSTRIDE]; // per half: scratch (C or Y) -> A (16 cols x 20) -> V spill
    __align__(16) float4 prm[16];         // per half 8 pairs; reused as aux (32 floats) after jacobi
};

// round-robin tournament pair (circle method), players 0..NS-1, NS even
__device__ __forceinline__ void pair_pq(int k, int r, int M, int& p, int& q) {
    p = (k == 0) ? 0 : (1 + (k - 1 + r) % M);
    q = 1 + (M - 1 - k + r) % M;
}

// Warp-cooperative two-sided Jacobi (single matrix, used for n=20 and tiny kernels).
//   A: smem col-major (LDC), disjoint 2x2 tile pass.
//   V: register-resident, lane j owns column j; SHFL exchange per round; spilled at end.
template<int N, int SWEEPS>
__device__ void jacobi_cm(WarpWS* w, int lane) {
    constexpr int NS = (N + 1) & ~1;
    constexpr int M  = NS - 1;
    constexpr int NP = NS / 2;
    constexpr int NT = NP * NP;
    float* A = w->A;
    float4* prm = w->prm;
    float4* cinfo = w->cinfo;

    float v[NS];
    #pragma unroll
    for (int i = 0; i < NS; i++) v[i] = (i == lane) ? 1.0f : 0.0f;

    for (int sw = 0; sw < SWEEPS; sw++)
    for (int r = 0; r < M; r++) {
        if (lane < NP) {
            int p, q; pair_pq(lane, r, M, p, q);
            float apq = A[q * LDC + p];
            float c = 1.0f, s = 0.0f;
            if (fabsf(apq) > 1e-38f) {
                float app = A[p * LDC + p];
                float aqq = A[q * LDC + q];
                float tau = (aqq - app) / (2.0f * apq);
                float den = fabsf(tau) + sqrtf(fmaf(tau, tau, 1.0f));
                float tt  = (tau >= 0.0f ? 1.0f : -1.0f) / den;
                c = rsqrtf(fmaf(tt, tt, 1.0f));
                s = tt * c;
            }
            prm[lane] = make_float4(c, s, __int_as_float(p), __int_as_float(q));
            cinfo[p] = make_float4(c, -s, __int_as_float(q), 0.0f);
            cinfo[q] = make_float4(c,  s, __int_as_float(p), 0.0f);
        }
        __syncwarp();
        float4 ci = cinfo[(lane < NS) ? lane : 0];
        float cc = (lane < NS) ? ci.x : 1.0f;
        float bb = (lane < NS) ? ci.y : 0.0f;
        int  prt = (lane < NS) ? __float_as_int(ci.z) : lane;
        #pragma unroll
        for (int t = 0; t < (NT + 31) / 32; t++) {
            int idx = lane + 32 * t;
            if (idx < NT) {
                int ki = idx / NP, kj = idx - ki * NP;
                float4 pi4 = prm[ki], pj4 = prm[kj];
                float ci_ = pi4.x, si = pi4.y;
                int pi = __float_as_int(pi4.z), qi = __float_as_int(pi4.w);
                float cj = pj4.x, sj = pj4.y;
                int pj = __float_as_int(pj4.z), qj = __float_as_int(pj4.w);
                float a00 = A[pj * LDC + pi], a01 = A[qj * LDC + pi];
                float a10 = A[pj * LDC + qi], a11 = A[qj * LDC + qi];
                float r00 = fmaf(ci_, a00, -si * a10), r10 = fmaf(si, a00, ci_ * a10);
                float r01 = fmaf(ci_, a01, -si * a11), r11 = fmaf(si, a01, ci_ * a11);
                A[pj * LDC + pi] = fmaf(cj, r00, -sj * r01);
                A[qj * LDC + pi] = fmaf(sj, r00,  cj * r01);
                A[pj * LDC + qi] = fmaf(cj, r10, -sj * r11);
                A[qj * LDC + qi] = fmaf(sj, r10,  cj * r11);
            }
        }
        #pragma unroll
        for (int i = 0; i < NS; i++) {
            float rv = __shfl_sync(FULLM, v[i], prt);
            v[i] = fmaf(cc, v[i], bb * rv);
        }
        __syncwarp();
    }

    if (lane < NS) {
        float4* Vc = (float4*)(w->V + lane * LDC);
        #pragma unroll
        for (int t = 0; t < NS / 4; t++)
            Vc[t] = make_float4(v[4*t], v[4*t+1], v[4*t+2], v[4*t+3]);
    }
    __syncwarp();
}

// Paired 15x15 Jacobi: two matrices per warp (half = lane>>4, column = lane&15).
template<int SWEEPS>
__device__ void jacobi_pair15(PairWS* w, int lane) {
    constexpr int MP = 15, NPP = 8;
    int half = lane >> 4, l16 = lane & 15;
    float* A = w->buf + half * HSTRIDE;
    float4* prmh = w->prm + half * 8;

    float v[16];
    #pragma unroll
    for (int i = 0; i < 16; i++) v[i] = (i == l16) ? 1.0f : 0.0f;

    for (int sw = 0; sw < SWEEPS; sw++)
    for (int r = 0; r < MP; r++) {
        if (l16 < NPP) {
            int p, q; pair_pq(l16, r, MP, p, q);
            float apq = A[q * LDC + p];
            float c = 1.0f, s = 0.0f;
            if (fabsf(apq) > 1e-38f) {
                float app = A[p * LDC + p];
                float aqq = A[q * LDC + q];
                float tau = (aqq - app) / (2.0f * apq);
                float den = fabsf(tau) + sqrtf(fmaf(tau, tau, 1.0f));
                float tt  = (tau >= 0.0f ? 1.0f : -1.0f) / den;
                c = rsqrtf(fmaf(tt, tt, 1.0f));
                s = tt * c;
            }
            prmh[l16] = make_float4(c, s, __int_as_float(p), __int_as_float(q));
        }
        __syncwarp();
        int k, prt; float sgn;
        if (l16 == 0) {
            k = 0; prt = 1 + (MP - 1 + r) % MP; sgn = -1.0f;
        } else {
            int j = l16 - 1 - r; j %= MP; if (j < 0) j += MP;
            int kp = j + 1;
            if (kp <= NPP - 1) {
                k = kp; prt = 1 + (MP - 1 - k + r) % MP; sgn = -1.0f;
            } else {
                k = (MP + r - l16) % MP;
                prt = (k == 0) ? 0 : 1 + (k - 1 + r) % MP;
                sgn = 1.0f;
            }
        }
        float4 pk = prmh[k];
        float cc = pk.x, bb = sgn * pk.y;
        int src = (half << 4) | prt;
        #pragma unroll
        for (int t = 0; t < 4; t++) {
            int idx = lane + 32 * t;
            int h2 = idx >> 6, tile = idx & 63;
            int ki = tile >> 3, kj = tile & 7;
            const float4* prr = w->prm + h2 * 8;
            float* Ah = w->buf + h2 * HSTRIDE;
            float4 pi4 = prr[ki], pj4 = prr[kj];
            float ci_ = pi4.x, si = pi4.y;
            int pi = __float_as_int(pi4.z), qi = __float_as_int(pi4.w);
            float cj = pj4.x, sj = pj4.y;
            int pj = __float_as_int(pj4.z), qj = __float_as_int(pj4.w);
            float a00 = Ah[pj * LDC + pi], a01 = Ah[qj * LDC + pi];
            float a10 = Ah[pj * LDC + qi], a11 = Ah[qj * LDC + qi];
            float r00 = fmaf(ci_, a00, -si * a10), r10 = fmaf(si, a00, ci_ * a10);
            float r01 = fmaf(ci_, a01, -si * a11), r11 = fmaf(si, a01, ci_ * a11);
            Ah[pj * LDC + pi] = fmaf(cj, r00, -sj * r01);
            Ah[qj * LDC + pi] = fmaf(sj, r00,  cj * r01);
            Ah[pj * LDC + qi] = fmaf(cj, r10, -sj * r11);
            Ah[qj * LDC + qi] = fmaf(sj, r10,  cj * r11);
        }
        #pragma unroll
        for (int i = 0; i < 16; i++) {
            float rv = __shfl_sync(FULLM, v[i], src);
            v[i] = fmaf(cc, v[i], bb * rv);
        }
        __syncwarp();
    }

    float dg = A[l16 * LDC + l16];
    __syncwarp();
    float* auxp = (float*)w->prm;
    auxp[half * 16 + l16] = dg;
    float4* Vc = (float4*)(A + l16 * LDC);
    #pragma unroll
    for (int t = 0; t < 4; t++)
        Vc[t] = make_float4(v[4*t], v[4*t+1], v[4*t+2], v[4*t+3]);
    __syncwarp();
}

// ---------- float4 dot / axpy helpers ----------
__device__ __forceinline__ float dot20(const float* row, const float* g) {
    const float4* r4 = (const float4*)row;
    float a = 0.0f;
    #pragma unroll
    for (int t = 0; t < 5; t++) {
        float4 x = r4[t];
        a = fmaf(x.x, g[4*t+0], a); a = fmaf(x.y, g[4*t+1], a);
        a = fmaf(x.z, g[4*t+2], a); a = fmaf(x.w, g[4*t+3], a);
    }
    return a;
}
__device__ __forceinline__ float dot16(const float* row, const float* g) {
    const float4* r4 = (const float4*)row;
    float a = 0.0f;
    #pragma unroll
    for (int t = 0; t < 4; t++) {
        float4 x = r4[t];
        a = fmaf(x.x, g[4*t+0], a); a = fmaf(x.y, g[4*t+1], a);
        a = fmaf(x.z, g[4*t+2], a); a = fmaf(x.w, g[4*t+3], a);
    }
    return a;
}
__device__ __forceinline__ void axpy20(float u, const float* col, float* l) {
    const float4* c4 = (const float4*)col;
    #pragma unroll
    for (int t = 0; t < 5; t++) {
        float4 x = c4[t];
        l[4*t+0] = fmaf(u, x.x, l[4*t+0]); l[4*t+1] = fmaf(u, x.y, l[4*t+1]);
        l[4*t+2] = fmaf(u, x.z, l[4*t+2]); l[4*t+3] = fmaf(u, x.w, l[4*t+3]);
    }
}
__device__ __forceinline__ void axpy16(float u, const float* col, float* l) {
    const float4* c4 = (const float4*)col;
    #pragma unroll
    for (int t = 0; t < 4; t++) {
        float4 x = c4[t];
        l[4*t+0] = fmaf(u, x.x, l[4*t+0]); l[4*t+1] = fmaf(u, x.y, l[4*t+1]);
        l[4*t+2] = fmaf(u, x.z, l[4*t+2]); l[4*t+3] = fmaf(u, x.w, l[4*t+3]);
    }
}

// scalar recompose for tiny kernels: Out[i*N+j] = sum_k V[i,k] fw[k] V[j,k]
template<int N>
__device__ __forceinline__ void recompose_cm(const float* V, const float* fw,
                                             float* Out, int lane) {
    #pragma unroll
    for (int t = 0; t < (N * N + 31) / 32; t++) {
        int idx = lane + 32 * t;
        if (idx < N * N) {
            int i = idx / N, j = idx - i * N;
            float acc = 0.0f;
            #pragma unroll
            for (int k = 0; k < N; k++)
                acc = fmaf(V[k * LDC + i] * fw[k], V[k * LDC + j], acc);
            Out[idx] = acc;
        }
    }
}

// ============ K1: per-sample logm(X) -> g_V2 (as L scratch) ============
__global__ void __launch_bounds__(256, 3) k_logsum(const float* __restrict__ X, int B) {
    __shared__ WarpWS ws[WPB];
    int tid = threadIdx.x, warp = tid >> 5, lane = tid & 31;
    WarpWS* w = &ws[warp];
    for (int m = 0; m < MPW; m++) {
        int b = ((int)blockIdx.x * WPB + warp) * MPW + m;
        if (b >= B) continue;
        const float4* Xb4 = (const float4*)(X + (size_t)b * 400);
        for (int idx = lane; idx < 100; idx += 32) ((float4*)w->A)[idx] = Xb4[idx];
        __syncwarp();
        jacobi_cm<20, SW_AVG20>(w, lane);
        if (lane < 20) w->aux[lane] = logf(w->A[lane * LDC + lane]);
        __syncwarp();
        if (lane < 20) {
            float l[20];
            #pragma unroll
            for (int i = 0; i < 20; i++) l[i] = 0.0f;
            #pragma unroll
            for (int k = 0; k < 20; k++) {
                float u = w->aux[k] * w->V[k * LDC + lane];   // fused (no rv[] array)
                axpy20(u, w->V + k * LDC, l);
            }
            float4* Lb = (float4*)(g_V2 + (size_t)b * 400 + lane * 20);
            #pragma unroll
            for (int t = 0; t < 5; t++)
                Lb[t] = make_float4(l[4*t], l[4*t+1], l[4*t+2], l[4*t+3]);
        }
        __syncwarp();
    }
}

// ===== K1b: deterministic domain-segmented sum of L over samples =====
__global__ void __launch_bounds__(256) kr_dsum(const int* __restrict__ dom, int B) {
    int warp = threadIdx.x >> 5, lane = threadIdx.x & 31;
    int c = blockIdx.x & 3;
    int split = ((int)blockIdx.x >> 2) * 8 + warp;
    int per = (B + NSPLIT - 1) / NSPLIT;
    int b0 = split * per, b1 = b0 + per;
    if (b1 > B) b1 = B;
    int e = c * 128 + lane * 4;
    bool valid = e < 400;
    float4 a0 = make_float4(0,0,0,0), a1 = a0, a2 = a0, a3 = a0;
    int cnt0 = 0, cnt1 = 0, cnt2 = 0, cnt3 = 0;
    for (int b = b0; b < b1; b++) {
        int d = dom[b];
        float4 v = make_float4(0,0,0,0);
        if (valid) v = *(const float4*)(g_V2 + (size_t)b * 400 + e);
        if (d == 0)      { a0.x += v.x; a0.y += v.y; a0.z += v.z; a0.w += v.w; cnt0++; }
        else if (d == 1) { a1.x += v.x; a1.y += v.y; a1.z += v.z; a1.w += v.w; cnt1++; }
        else if (d == 2) { a2.x += v.x; a2.y += v.y; a2.z += v.z; a2.w += v.w; cnt2++; }
        else             { a3.x += v.x; a3.y += v.y; a3.z += v.z; a3.w += v.w; cnt3++; }
    }
    if (valid) {
        size_t base = (((size_t)c * NSPLIT + split) * NDOM) * 128 + lane * 4;
        *(float4*)(g_part2 + base + 0 * 128) = a0;
        *(float4*)(g_part2 + base + 1 * 128) = a1;
        *(float4*)(g_part2 + base + 2 * 128) = a2;
        *(float4*)(g_part2 + base + 3 * 128) = a3;
    }
    if (c == 0 && lane == 0) {
        g_partCnt[split * NDOM + 0] = (float)cnt0;
        g_partCnt[split * NDOM + 1] = (float)cnt1;
        g_partCnt[split * NDOM + 2] = (float)cnt2;
        g_partCnt[split * NDOM + 3] = (float)cnt3;
    }
}

// ============ K2: reduce partials -> meanL, counts; Ginv[d] = V e^{-w/2} Vt ============
__global__ void __launch_bounds__(256) k_ginv() {
    __shared__ WarpWS ws[4];
    __shared__ float meanL[NDOM * 400];
    int tid = threadIdx.x;
    if (tid < NDOM) {
        float c = 0.0f;
        for (int sp = 0; sp < NSPLIT; sp++) c += g_partCnt[sp * NDOM + tid];
        g_cnt[tid] = c;
    }
    for (int out = tid; out < NDOM * 400; out += 256) {
        int d = out / 400, e = out - d * 400;
        int c = e >> 7, i = e & 127;
        float s = 0.0f;
        for (int sp = 0; sp < NSPLIT; sp++)
            s += g_part2[(((size_t)c * NSPLIT + sp) * NDOM + d) * 128 + i];
        meanL[out] = s;
    }
    __syncthreads();
    int warp = tid >> 5, lane = tid & 31;
    if (warp < 4) {
        int d = warp;
        float inv = 1.0f / g_cnt[d];
        WarpWS* w = &ws[warp];
        for (int idx = lane; idx < 400; idx += 32)
            w->A[idx] = meanL[d * 400 + idx] * inv;
        __syncwarp();
        jacobi_cm<20, SW_SMALL>(w, lane);
        if (lane < 20) w->aux[lane] = expf(-0.5f * w->A[lane * LDC + lane]);
        __syncwarp();
        recompose_cm<20>(w->V, w->aux, g_Ginv + d * 400, lane);
    }
}

// ====== K3: M = Gi X Gi, eigh -> store V,logw; per-domain sum ||logM||^2 ======
__global__ void __launch_bounds__(256, 3) k_center(const float* __restrict__ X,
                                                   const int* __restrict__ dom, int B) {
    __shared__ float Gi[NDOM * 400];
    __shared__ float nrmAcc[WPB][NDOM];
    __shared__ WarpWS ws[WPB];
    int tid = threadIdx.x, warp = tid >> 5, lane = tid & 31;
    for (int idx = tid; idx < NDOM * 400; idx += 256) Gi[idx] = g_Ginv[idx];
    if (tid < WPB * NDOM) ((float*)nrmAcc)[tid] = 0.0f;
    __syncthreads();
    WarpWS* w = &ws[warp];
    for (int m = 0; m < MPW; m++) {
        int b = ((int)blockIdx.x * WPB + warp) * MPW + m;
        if (b < B) {
            int d = dom[b];
            const float* G = Gi + d * 400;
            const float4* Xb4 = (const float4*)(X + (size_t)b * 400);
            for (int idx = lane; idx < 100; idx += 32)
                ((float4*)w->V)[idx] = Xb4[idx];
            __syncwarp();
            float res[20];
            if (lane < 20) {
                float g[20];
                #pragma unroll
                for (int k = 0; k < 20; k++) g[k] = G[k * 20 + lane];
                float y[20];
                #pragma unroll
                for (int i = 0; i < 20; i++) y[i] = dot20(w->V + i * 20, g);
                #pragma unroll
                for (int i = 0; i < 20; i++) res[i] = dot20(G + i * 20, y);
            }
            __syncwarp();
            if (lane < 20) {
                float4* Ac = (float4*)(w->A + lane * LDC);
                #pragma unroll
                for (int t = 0; t < 5; t++)
                    Ac[t] = make_float4(res[4*t], res[4*t+1], res[4*t+2], res[4*t+3]);
            }
            jacobi_cm<20, SW_PS20>(w, lane);
            if (lane < 20) w->aux[lane] = logf(w->A[lane * LDC + lane]);
            __syncwarp();
            float4* gV4 = (float4*)(g_V2 + (size_t)b * 400);
            for (int idx = lane; idx < 100; idx += 32) gV4[idx] = ((float4*)w->V)[idx];
            if (lane < 20) g_lw2[(size_t)b * 20 + lane] = w->aux[lane];
            float v = (lane < 20) ? w->aux[lane] * w->aux[lane] : 0.0f;
            #pragma unroll
            for (int off = 16; off; off >>= 1) v += __shfl_down_sync(FULLM, v, off);
            if (lane == 0) nrmAcc[warp][d] += v;
        }
    }
    __syncthreads();
    if (tid == 0) {
        float sums[NDOM] = {0.f, 0.f, 0.f, 0.f};
        for (int t = 0; t < WPB; t++)
            for (int d = 0; d < NDOM; d++) sums[d] += nrmAcc[t][d];
        for (int d = 0; d < NDOM; d++) g_partN[blockIdx.x * NDOM + d] = sums[d];
    }
}

// ============ K4: scale[d] = s / sqrt(sig2 + eps) ============
__global__ void __launch_bounds__(128) k_scale(const float* __restrict__ sptr, int NB) {
    int warp = threadIdx.x >> 5, lane = threadIdx.x & 31;
    int d = warp;
    float nsum = 0.0f;
    for (int b = lane; b < NB; b += 32) nsum += g_partN[b * NDOM + d];
    #pragma unroll
    for (int off = 16; off; off >>= 1) nsum += __shfl_down_sync(FULLM, nsum, off);
    if (lane == 0) {
        float sig2 = nsum / g_cnt[d];
        g_scale[d] = sptr[0] / sqrtf(sig2 + EPS_VAR_F);
    }
}

// ====== K5 (PAIRED eigh): Xn via eigenbasis reuse, Y = Wt Xn W, store Y, sum logm(Y) ======
__global__ void __launch_bounds__(256) k_bimap(const float* __restrict__ Wb,
                                               const int* __restrict__ dom, int B) {
    __shared__ float Ws16[320];
    __shared__ float accW[WPB * 2 * 240];
    __shared__ PairWS ws[WPB];
    int tid = threadIdx.x, warp = tid >> 5, lane = tid & 31;
    int half = lane >> 4, l16 = lane & 15;
    for (int idx = tid; idx < 320; idx += 256) {
        int i = idx >> 4, o = idx & 15;
        Ws16[idx] = (o < 15) ? Wb[i * 15 + o] : 0.0f;
    }
    __syncthreads();
    PairWS* w = &ws[warp];
    float* bufh = w->buf + half * HSTRIDE;
    int base = ((int)blockIdx.x * WPB + warp) * MPW;
    float la[15];
    #pragma unroll
    for (int i = 0; i < 15; i++) la[i] = 0.0f;

    for (int mp = 0; mp < MPW / 2; mp++) {
        for (int h = 0; h < 2; h++) {
            int b = base + mp * 2 + h;
            float* bh = w->buf + h * HSTRIDE;
            if (b < B) {
                int d = dom[b];
                float sc = g_scale[d];
                const float* gV = g_V2 + (size_t)b * 400;
                float c[16];
                if (lane < 20) {
                    float ej = expf(0.5f * sc * g_lw2[(size_t)b * 20 + lane]);
                    float z[20];
                    const float4* col4 = (const float4*)(gV + lane * 20);
                    #pragma unroll
                    for (int t = 0; t < 5; t++) {
                        float4 v = col4[t];
                        z[4*t+0] = v.x * ej; z[4*t+1] = v.y * ej;
                        z[4*t+2] = v.z * ej; z[4*t+3] = v.w * ej;
                    }
                    #pragma unroll
                    for (int o = 0; o < 16; o++) c[o] = 0.0f;
                    #pragma unroll
                    for (int i = 0; i < 20; i++) axpy16(z[i], Ws16 + i * 16, c);
                }
                __syncwarp();
                if (lane < 20) {
                    #pragma unroll
                    for (int o = 0; o < 15; o++) bh[o * 20 + lane] = c[o];
                }
                __syncwarp();
                float y[16];
                if (lane < 15) {
                    float cp[20];
                    const float4* row4 = (const float4*)(bh + lane * 20);
                    #pragma unroll
                    for (int t = 0; t < 5; t++) {
                        float4 v = row4[t];
                        cp[4*t+0] = v.x; cp[4*t+1] = v.y; cp[4*t+2] = v.z; cp[4*t+3] = v.w;
                    }
                    #pragma unroll
                    for (int o = 0; o < 15; o++) y[o] = dot20(bh + o * 20, cp);
                    y[15] = 0.0f;
                }
                __syncwarp();
                if (lane < 15) {
                    float4* Ac = (float4*)(bh + lane * LDC);
                    float4* gY4 = (float4*)(g_Y + (size_t)b * 240 + lane * 16);
                    #pragma unroll
                    for (int t = 0; t < 4; t++) {
                        float4 v = make_float4(y[4*t], y[4*t+1], y[4*t+2], y[4*t+3]);
                        Ac[t] = v;
                        gY4[t] = v;
                    }
                } else if (lane == 15) {
                    float4* Ac = (float4*)(bh + 15 * LDC);
                    #pragma unroll
                    for (int t = 0; t < 4; t++) Ac[t] = make_float4(0, 0, 0, 0);
                }
            } else {
                for (int idx = lane; idx < 320; idx += 32) bh[idx] = 0.0f;
            }
            __syncwarp();
        }
        jacobi_pair15<SW_AVG15>(w, lane);
        int bsel = base + mp * 2 + half;
        bool act = (bsel < B);
        float* auxp = (float*)w->prm;
        float dg = auxp[half * 16 + l16];
        auxp[half * 16 + l16] = act ? logf(dg) : 0.0f;
        __syncwarp();
        if (l16 < 15 && act) {
            const float* aux = auxp + half * 16;
            float l[16];
            #pragma unroll
            for (int i = 0; i < 16; i++) l[i] = 0.0f;
            #pragma unroll
            for (int k = 0; k < 15; k++) {
                float u = aux[k] * bufh[k * LDC + l16];     // fused
                axpy16(u, bufh + k * LDC, l);
            }
            #pragma unroll
            for (int i = 0; i < 15; i++) la[i] += l[i];
        }
        __syncwarp();
    }
    if (l16 < 15) {
        float* dst = accW + (warp * 2 + half) * 240;
        #pragma unroll
        for (int i = 0; i < 15; i++) dst[i * 16 + l16] = la[i];
    }
    __syncthreads();
    for (int idx = tid; idx < 225; idx += 256) {
        int i = idx / 15, j = idx - i * 15;
        float s = 0.0f;
        #pragma unroll
        for (int wp = 0; wp < WPB * 2; wp++) s += accW[wp * 240 + i * 16 + j];
        g_partLY[(size_t)blockIdx.x * 225 + idx] = s;
    }
}

// ============ K6: meanLY -> Gb = V e^{-w/2} Vt (padded 15x16) ============
__global__ void __launch_bounds__(256) k_gb(int B, int NB) {
    __shared__ float meanLY[225];
    __shared__ WarpWS ws0;
    int tid = threadIdx.x, warp = tid >> 5, lane = tid & 31;
    float invB = 1.0f / (float)B;
    for (int out = warp; out < 225; out += 8) {
        float s = 0.0f;
        for (int b = lane; b < NB; b += 32) s += g_partLY[(size_t)b * 225 + out];
        #pragma unroll
        for (int off = 16; off; off >>= 1) s += __shfl_down_sync(FULLM, s, off);
        if (lane == 0) meanLY[out] = s * invB;
    }
    __syncthreads();
    if (warp == 0) {
        for (int idx = lane; idx < 320; idx += 32) ws0.A[idx] = 0.0f;
        __syncwarp();
        for (int idx = lane; idx < 225; idx += 32) {
            int i = idx / 15, j = idx - i * 15;
            ws0.A[j * LDC + i] = meanLY[idx];
        }
        __syncwarp();
        jacobi_cm<15, SW_SMALL>(&ws0, lane);
        if (lane < 15) ws0.aux[lane] = expf(-0.5f * ws0.A[lane * LDC + lane]);
        __syncwarp();
        for (int t = 0; t < 8; t++) {
            int idx = lane + 32 * t;
            if (idx < 240) {
                int i = idx >> 4, j = idx & 15;
                float acc = 0.0f;
                if (j < 15) {
                    #pragma unroll
                    for (int k = 0; k < 15; k++)
                        acc = fmaf(ws0.V[k * LDC + i] * ws0.aux[k], ws0.V[k * LDC + j], acc);
                }
                g_Gb16[idx] = acc;
            }
        }
    }
}

// ====== K7 (PAIRED): Yn = Gb Y Gb, eigh, fused ReEig+LogEig+vec+classifier ======
__global__ void __launch_bounds__(256) k_head(const float* __restrict__ Wl,
                                              float* __restrict__ out, int B) {
    __shared__ float Gbs[240];
    __shared__ float Wf[4 * 240];
    __shared__ PairWS ws[WPB];
    int tid = threadIdx.x, warp = tid >> 5, lane = tid & 31;
    int half = lane >> 4, l16 = lane & 15;
    for (int i = tid; i < 240; i += 256) Gbs[i] = g_Gb16[i];
    for (int idx = tid; idx < 960; idx += 256) {
        int cc = idx / 240, rem = idx - cc * 240;
        int i = rem >> 4, j = rem & 15;
        float v = 0.0f;
        if (i < 15 && j < 15) {
            if (i == j) v = Wl[cc * 120 + i];
            else {
                int a = min(i, j), b2 = max(i, j);
                int off = a * 14 - a * (a - 1) / 2 + (b2 - a - 1);
                v = Wl[cc * 120 + 15 + off] * (SQRT2F * 0.5f);
            }
        }
        Wf[idx] = v;
    }
    __syncthreads();
    PairWS* w = &ws[warp];
    float* bufh = w->buf + half * HSTRIDE;
    int base = ((int)blockIdx.x * WPB + warp) * MPW;

    for (int mp = 0; mp < MPW / 2; mp++) {
        int b = base + mp * 2 + half;
        bool active = (b < B);
        if (active) {
            const float4* gY4 = (const float4*)(g_Y + (size_t)b * 240);
            for (int idx = l16; idx < 60; idx += 16) ((float4*)bufh)[idx] = gY4[idx];
        } else {
            for (int idx = l16; idx < 60; idx += 16) ((float4*)bufh)[idx] = make_float4(0,0,0,0);
        }
        __syncwarp();
        float res[16];
        if (l16 < 15) {
            float g[16];
            #pragma unroll
            for (int k = 0; k < 15; k++) g[k] = Gbs[k * 16 + l16];
            g[15] = 0.0f;
            float y[16];
            #pragma unroll
            for (int i = 0; i < 15; i++) y[i] = dot16(bufh + i * 16, g);
            y[15] = 0.0f;
            #pragma unroll
            for (int i = 0; i < 15; i++) res[i] = dot16(Gbs + i * 16, y);
            res[15] = 0.0f;
        }
        __syncwarp();
        {
            float4* Ac = (float4*)(bufh + l16 * LDC);
            if (l16 < 15) {
                #pragma unroll
                for (int t = 0; t < 4; t++)
                    Ac[t] = make_float4(res[4*t], res[4*t+1], res[4*t+2], res[4*t+3]);
            } else {
                #pragma unroll
                for (int t = 0; t < 4; t++) Ac[t] = make_float4(0, 0, 0, 0);
            }
        }
        jacobi_pair15<SW_PS15>(w, lane);
        float* auxp = (float*)w->prm;
        auxp[half * 16 + l16] = logf(fmaxf(auxp[half * 16 + l16], EPS_REEIG_F));
        __syncwarp();
        float o0 = 0.f, o1 = 0.f, o2 = 0.f, o3 = 0.f;
        if (l16 < 15) {
            const float* aux = auxp + half * 16;
            float l[16];
            #pragma unroll
            for (int i = 0; i < 16; i++) l[i] = 0.0f;
            #pragma unroll
            for (int k = 0; k < 15; k++) {
                float u = aux[k] * bufh[k * LDC + l16];     // fused
                axpy16(u, bufh + k * LDC, l);
            }
            #pragma unroll
            for (int i = 0; i < 15; i++) {
                float li = l[i];
                o0 = fmaf(Wf[0 * 240 + i * 16 + l16], li, o0);
                o1 = fmaf(Wf[1 * 240 + i * 16 + l16], li, o1);
                o2 = fmaf(Wf[2 * 240 + i * 16 + l16], li, o2);
                o3 = fmaf(Wf[3 * 240 + i * 16 + l16], li, o3);
            }
        }
        #pragma unroll
        for (int off = 8; off; off >>= 1) {
            o0 += __shfl_down_sync(FULLM, o0, off);
            o1 += __shfl_down_sync(FULLM, o1, off);
            o2 += __shfl_down_sync(FULLM, o2, off);
            o3 += __shfl_down_sync(FULLM, o3, off);
        }
        if (l16 == 0 && active) {
            float* ob = out + (size_t)b * 4;
            ob[0] = o0; ob[1] = o1; ob[2] = o2; ob[3] = o3;
        }
        __syncwarp();
    }
}

extern "C" void kernel_launch(void* const* d_in, const int* in_sizes, int n_in,
                              void* d_out, int out_size) {
    const float* X   = (const float*)d_in[0];
    const int*   dom = (const int*)d_in[1];
    const float* s   = (const float*)d_in[2];
    const float* Wb  = (const float*)d_in[3];
    const float* Wl  = (const float*)d_in[4];
    float* out = (float*)d_out;
    int B = in_sizes[0] / 400;
    if (B > MAXB) B = MAXB;
    int NB = (B + MPB - 1) / MPB;
    if (NB > NB_MAX) NB = NB_MAX;

    k_logsum<<<NB, 256>>>(X, B);
    kr_dsum<<<NCHUNK * (NSPLIT / 8), 256>>>(dom, B);
    k_ginv<<<1, 256>>>();
    k_center<<<NB, 256>>>(X, dom, B);
    k_scale<<<1, 128>>>(s, NB);
    k_bimap<<<NB, 256>>>(Wb, dom, B);
    k_gb<<<1, 256>>>(B, NB);
    k_head<<<NB, 256>>>(Wl, out, B);
}

// round 14
// speedup vs baseline: 1.3018x; 1.1119x over previous
#include <cuda_runtime.h>
#include <math.h>

#define NDOM 4
#define SQRT2F 1.41421356237309515f
#define EPS_REEIG_F 1e-4f
#define EPS_VAR_F 1e-5f

#define MAXB 32768
#define NB_MAX 1024
#define WPB 8            // warps per block
#define MPW 4            // matrices per warp
#define MPB (WPB*MPW)    // 32 matrices per block

#define LDC 20           // column stride (floats) for col-major matrices
#define SW_PS20 5        // per-sample 20x20 (k_center)
#define SW_AVG20 3       // averaged-output 20x20 (k_logsum)
#define SW_PS15 5        // per-sample 15x15 (k_head)
#define SW_AVG15 4       // averaged-output 15x15 (k_bimap)
#define SW_SMALL 7

#define NSPLIT 64        // sample splits for domain reduction
#define NCHUNK 4         // 128-float element chunks (covers 400)

#define FULLM 0xffffffffu
#define HSTRIDE 336      // per-half float offset in PairWS.buf (336 mod 32 = 16 -> bank split)

// ---------------- device scratch (static, allowed) ----------------
__device__ float g_V2[(size_t)MAXB * 400];   // k_logsum: per-sample L; later: eigenvectors of centered matrices
__device__ float g_lw2[(size_t)MAXB * 20];   // log-eigenvalues of centered matrices
__device__ float g_Y[(size_t)MAXB * 240];    // BiMap outputs, rows padded to 16
__device__ float g_part2[(size_t)NCHUNK * NSPLIT * NDOM * 128];
__device__ float g_partCnt[NSPLIT * NDOM];
__device__ float g_partN[NB_MAX * NDOM];
__device__ float g_partLY[NB_MAX * 225];
__device__ float g_cnt[NDOM];
__device__ float g_Ginv[NDOM * 400];
__device__ float g_scale[NDOM];
__device__ float g_Gb16[240];                // 15x16 padded

// ---------------- per-warp workspaces ----------------
struct WarpWS {
    __align__(16) float A[400];     // square col-major (LDC) OR triangular (210) for tri solver
    __align__(16) float V[400];     // col-major, LDC=20 (written once post-Jacobi)
    __align__(16) float4 prm[12];   // per-PAIR (c, s, p, q)
    __align__(16) float4 cinfo[20]; // per-COLUMN (c, b=±s, partner, pad) for V shfl pass
    float aux[24];
};

// paired 15x15 workspace: two matrices per warp (half = lane>>4)
struct PairWS {
    __align__(16) float buf[2 * HSTRIDE]; // per half: scratch (C or Y) -> A (16 cols x 20) -> V spill
    __align__(16) float4 prm[16];         // per half 8 pairs; reused as aux (32 floats) after jacobi
};

// round-robin tournament pair (circle method), players 0..NS-1, NS even
__device__ __forceinline__ void pair_pq(int k, int r, int M, int& p, int& q) {
    p = (k == 0) ? 0 : (1 + (k - 1 + r) % M);
    q = 1 + (M - 1 - k + r) % M;
}

// triangular index: entry (a,b) unordered, stored at hi*(hi+1)/2 + lo
__device__ __forceinline__ int TRI(int a, int b) {
    int lo = min(a, b), hi = max(a, b);
    return hi * (hi + 1) / 2 + lo;
}

// decode linear tile index -> (ki,kj) with ki<=kj over NP=10 pairs (55 tiles):
// idx 0..9 diag (ki=kj=idx), 10..54 off-diag row-major upper.
__device__ __forceinline__ void tri_tile_decode(int idx, int& ki, int& kj) {
    ki = -1; kj = -1;
    if (idx < 10) { ki = idx; kj = idx; return; }
    if (idx >= 55) return;
    int t = idx - 10;
    #pragma unroll
    for (int r = 0; r < 9; r++) {
        int len = 9 - r;
        if (t >= 0 && t < len) { ki = r; kj = r + 1 + t; }
        t -= len;
    }
}

// one triangular tile update (diag or off-diag); A is 210-entry packed triangle
__device__ __forceinline__ void tile_tri(float* A, const float4* prm, int ki, int kj) {
    if (ki < 0) return;
    float4 Pi = prm[ki];
    float ci = Pi.x, si = Pi.y;
    int pi = __float_as_int(Pi.z), qi = __float_as_int(Pi.w);
    if (ki == kj) {
        int ipp = pi * (pi + 3) / 2, iqq = qi * (qi + 3) / 2, ipq = TRI(pi, qi);
        float app = A[ipp], apq = A[ipq], aqq = A[iqq];
        float r00 = fmaf(ci, app, -si * apq), r10 = fmaf(si, app, ci * apq);
        float r01 = fmaf(ci, apq, -si * aqq), r11 = fmaf(si, apq, ci * aqq);
        A[ipp] = fmaf(ci, r00, -si * r01);
        A[ipq] = fmaf(si, r00,  ci * r01);
        A[iqq] = fmaf(si, r10,  ci * r11);
    } else {
        float4 Pj = prm[kj];
        float cj = Pj.x, sj = Pj.y;
        int pj = __float_as_int(Pj.z), qj = __float_as_int(Pj.w);
        int i00 = TRI(pi, pj), i01 = TRI(pi, qj), i10 = TRI(qi, pj), i11 = TRI(qi, qj);
        float a00 = A[i00], a01 = A[i01], a10 = A[i10], a11 = A[i11];
        float r00 = fmaf(ci, a00, -si * a10), r10 = fmaf(si, a00, ci * a10);
        float r01 = fmaf(ci, a01, -si * a11), r11 = fmaf(si, a01, ci * a11);
        A[i00] = fmaf(cj, r00, -sj * r01);
        A[i01] = fmaf(sj, r00,  cj * r01);
        A[i10] = fmaf(cj, r10, -sj * r11);
        A[i11] = fmaf(sj, r10,  cj * r11);
    }
}

// Triangular-packed 20x20 Jacobi: A = 210-entry upper triangle in w->A,
// V register-resident (lane<20 owns column), spilled to w->V at end.
// Only tiles ki<=kj processed: 55 tiles, 420 smem ops/round vs 800 square.
template<int SWEEPS>
__device__ void jacobi_tri20(WarpWS* w, int lane) {
    constexpr int M = 19, NP = 10;
    float* A = w->A;
    float4* prm = w->prm;
    float4* cinfo = w->cinfo;

    float v[20];
    #pragma unroll
    for (int i = 0; i < 20; i++) v[i] = (i == lane) ? 1.0f : 0.0f;

    int ki0, kj0, ki1, kj1;
    tri_tile_decode(lane, ki0, kj0);
    tri_tile_decode(lane + 32, ki1, kj1);

    __syncwarp();   // callers' A writes (other lanes) visible before first params read

    for (int sw = 0; sw < SWEEPS; sw++)
    for (int r = 0; r < M; r++) {
        if (lane < NP) {
            int p, q; pair_pq(lane, r, M, p, q);
            float apq = A[TRI(p, q)];
            float c = 1.0f, s = 0.0f;
            if (fabsf(apq) > 1e-38f) {
                float app = A[p * (p + 3) / 2];
                float aqq = A[q * (q + 3) / 2];
                float tau = (aqq - app) / (2.0f * apq);
                float den = fabsf(tau) + sqrtf(fmaf(tau, tau, 1.0f));
                float tt  = (tau >= 0.0f ? 1.0f : -1.0f) / den;
                c = rsqrtf(fmaf(tt, tt, 1.0f));
                s = tt * c;
            }
            prm[lane] = make_float4(c, s, __int_as_float(p), __int_as_float(q));
            cinfo[p] = make_float4(c, -s, __int_as_float(q), 0.0f);
            cinfo[q] = make_float4(c,  s, __int_as_float(p), 0.0f);
        }
        __syncwarp();
        float4 ci = cinfo[(lane < 20) ? lane : 0];
        float cc = (lane < 20) ? ci.x : 1.0f;
        float bb = (lane < 20) ? ci.y : 0.0f;
        int  prt = (lane < 20) ? __float_as_int(ci.z) : lane;
        tile_tri(A, prm, ki0, kj0);
        tile_tri(A, prm, ki1, kj1);
        #pragma unroll
        for (int i = 0; i < 20; i++) {
            float rv = __shfl_sync(FULLM, v[i], prt);
            v[i] = fmaf(cc, v[i], bb * rv);
        }
        __syncwarp();
    }

    if (lane < 20) {
        float4* Vc = (float4*)(w->V + lane * LDC);
        #pragma unroll
        for (int t = 0; t < 5; t++)
            Vc[t] = make_float4(v[4*t], v[4*t+1], v[4*t+2], v[4*t+3]);
    }
    __syncwarp();
}

// Warp-cooperative square Jacobi (tiny kernels: n=20 SMALL, n=15 single).
template<int N, int SWEEPS>
__device__ void jacobi_cm(WarpWS* w, int lane) {
    constexpr int NS = (N + 1) & ~1;
    constexpr int M  = NS - 1;
    constexpr int NP = NS / 2;
    constexpr int NT = NP * NP;
    float* A = w->A;
    float4* prm = w->prm;
    float4* cinfo = w->cinfo;

    float v[NS];
    #pragma unroll
    for (int i = 0; i < NS; i++) v[i] = (i == lane) ? 1.0f : 0.0f;

    for (int sw = 0; sw < SWEEPS; sw++)
    for (int r = 0; r < M; r++) {
        if (lane < NP) {
            int p, q; pair_pq(lane, r, M, p, q);
            float apq = A[q * LDC + p];
            float c = 1.0f, s = 0.0f;
            if (fabsf(apq) > 1e-38f) {
                float app = A[p * LDC + p];
                float aqq = A[q * LDC + q];
                float tau = (aqq - app) / (2.0f * apq);
                float den = fabsf(tau) + sqrtf(fmaf(tau, tau, 1.0f));
                float tt  = (tau >= 0.0f ? 1.0f : -1.0f) / den;
                c = rsqrtf(fmaf(tt, tt, 1.0f));
                s = tt * c;
            }
            prm[lane] = make_float4(c, s, __int_as_float(p), __int_as_float(q));
            cinfo[p] = make_float4(c, -s, __int_as_float(q), 0.0f);
            cinfo[q] = make_float4(c,  s, __int_as_float(p), 0.0f);
        }
        __syncwarp();
        float4 ci = cinfo[(lane < NS) ? lane : 0];
        float cc = (lane < NS) ? ci.x : 1.0f;
        float bb = (lane < NS) ? ci.y : 0.0f;
        int  prt = (lane < NS) ? __float_as_int(ci.z) : lane;
        #pragma unroll
        for (int t = 0; t < (NT + 31) / 32; t++) {
            int idx = lane + 32 * t;
            if (idx < NT) {
                int ki = idx / NP, kj = idx - ki * NP;
                float4 pi4 = prm[ki], pj4 = prm[kj];
                float ci_ = pi4.x, si = pi4.y;
                int pi = __float_as_int(pi4.z), qi = __float_as_int(pi4.w);
                float cj = pj4.x, sj = pj4.y;
                int pj = __float_as_int(pj4.z), qj = __float_as_int(pj4.w);
                float a00 = A[pj * LDC + pi], a01 = A[qj * LDC + pi];
                float a10 = A[pj * LDC + qi], a11 = A[qj * LDC + qi];
                float r00 = fmaf(ci_, a00, -si * a10), r10 = fmaf(si, a00, ci_ * a10);
                float r01 = fmaf(ci_, a01, -si * a11), r11 = fmaf(si, a01, ci_ * a11);
                A[pj * LDC + pi] = fmaf(cj, r00, -sj * r01);
                A[qj * LDC + pi] = fmaf(sj, r00,  cj * r01);
                A[pj * LDC + qi] = fmaf(cj, r10, -sj * r11);
                A[qj * LDC + qi] = fmaf(sj, r10,  cj * r11);
            }
        }
        #pragma unroll
        for (int i = 0; i < NS; i++) {
            float rv = __shfl_sync(FULLM, v[i], prt);
            v[i] = fmaf(cc, v[i], bb * rv);
        }
        __syncwarp();
    }

    if (lane < NS) {
        float4* Vc = (float4*)(w->V + lane * LDC);
        #pragma unroll
        for (int t = 0; t < NS / 4; t++)
            Vc[t] = make_float4(v[4*t], v[4*t+1], v[4*t+2], v[4*t+3]);
    }
    __syncwarp();
}

// Paired 15x15 Jacobi: two matrices per warp (half = lane>>4, column = lane&15).
template<int SWEEPS>
__device__ void jacobi_pair15(PairWS* w, int lane) {
    constexpr int MP = 15, NPP = 8;
    int half = lane >> 4, l16 = lane & 15;
    float* A = w->buf + half * HSTRIDE;
    float4* prmh = w->prm + half * 8;

    float v[16];
    #pragma unroll
    for (int i = 0; i < 16; i++) v[i] = (i == l16) ? 1.0f : 0.0f;

    for (int sw = 0; sw < SWEEPS; sw++)
    for (int r = 0; r < MP; r++) {
        if (l16 < NPP) {
            int p, q; pair_pq(l16, r, MP, p, q);
            float apq = A[q * LDC + p];
            float c = 1.0f, s = 0.0f;
            if (fabsf(apq) > 1e-38f) {
                float app = A[p * LDC + p];
                float aqq = A[q * LDC + q];
                float tau = (aqq - app) / (2.0f * apq);
                float den = fabsf(tau) + sqrtf(fmaf(tau, tau, 1.0f));
                float tt  = (tau >= 0.0f ? 1.0f : -1.0f) / den;
                c = rsqrtf(fmaf(tt, tt, 1.0f));
                s = tt * c;
            }
            prmh[l16] = make_float4(c, s, __int_as_float(p), __int_as_float(q));
        }
        __syncwarp();
        int k, prt; float sgn;
        if (l16 == 0) {
            k = 0; prt = 1 + (MP - 1 + r) % MP; sgn = -1.0f;
        } else {
            int j = l16 - 1 - r; j %= MP; if (j < 0) j += MP;
            int kp = j + 1;
            if (kp <= NPP - 1) {
                k = kp; prt = 1 + (MP - 1 - k + r) % MP; sgn = -1.0f;
            } else {
                k = (MP + r - l16) % MP;
                prt = (k == 0) ? 0 : 1 + (k - 1 + r) % MP;
                sgn = 1.0f;
            }
        }
        float4 pk = prmh[k];
        float cc = pk.x, bb = sgn * pk.y;
        int src = (half << 4) | prt;
        #pragma unroll
        for (int t = 0; t < 4; t++) {
            int idx = lane + 32 * t;
            int h2 = idx >> 6, tile = idx & 63;
            int ki = tile >> 3, kj = tile & 7;
            const float4* prr = w->prm + h2 * 8;
            float* Ah = w->buf + h2 * HSTRIDE;
            float4 pi4 = prr[ki], pj4 = prr[kj];
            float ci_ = pi4.x, si = pi4.y;
            int pi = __float_as_int(pi4.z), qi = __float_as_int(pi4.w);
            float cj = pj4.x, sj = pj4.y;
            int pj = __float_as_int(pj4.z), qj = __float_as_int(pj4.w);
            float a00 = Ah[pj * LDC + pi], a01 = Ah[qj * LDC + pi];
            float a10 = Ah[pj * LDC + qi], a11 = Ah[qj * LDC + qi];
            float r00 = fmaf(ci_, a00, -si * a10), r10 = fmaf(si, a00, ci_ * a10);
            float r01 = fmaf(ci_, a01, -si * a11), r11 = fmaf(si, a01, ci_ * a11);
            Ah[pj * LDC + pi] = fmaf(cj, r00, -sj * r01);
            Ah[qj * LDC + pi] = fmaf(sj, r00,  cj * r01);
            Ah[pj * LDC + qi] = fmaf(cj, r10, -sj * r11);
            Ah[qj * LDC + qi] = fmaf(sj, r10,  cj * r11);
        }
        #pragma unroll
        for (int i = 0; i < 16; i++) {
            float rv = __shfl_sync(FULLM, v[i], src);
            v[i] = fmaf(cc, v[i], bb * rv);
        }
        __syncwarp();
    }

    float dg = A[l16 * LDC + l16];
    __syncwarp();
    float* auxp = (float*)w->prm;
    auxp[half * 16 + l16] = dg;
    float4* Vc = (float4*)(A + l16 * LDC);
    #pragma unroll
    for (int t = 0; t < 4; t++)
        Vc[t] = make_float4(v[4*t], v[4*t+1], v[4*t+2], v[4*t+3]);
    __syncwarp();
}

// ---------- float4 dot / axpy helpers ----------
__device__ __forceinline__ float dot20(const float* row, const float* g) {
    const float4* r4 = (const float4*)row;
    float a = 0.0f;
    #pragma unroll
    for (int t = 0; t < 5; t++) {
        float4 x = r4[t];
        a = fmaf(x.x, g[4*t+0], a); a = fmaf(x.y, g[4*t+1], a);
        a = fmaf(x.z, g[4*t+2], a); a = fmaf(x.w, g[4*t+3], a);
    }
    return a;
}
__device__ __forceinline__ float dot16(const float* row, const float* g) {
    const float4* r4 = (const float4*)row;
    float a = 0.0f;
    #pragma unroll
    for (int t = 0; t < 4; t++) {
        float4 x = r4[t];
        a = fmaf(x.x, g[4*t+0], a); a = fmaf(x.y, g[4*t+1], a);
        a = fmaf(x.z, g[4*t+2], a); a = fmaf(x.w, g[4*t+3], a);
    }
    return a;
}
__device__ __forceinline__ void axpy20(float u, const float* col, float* l) {
    const float4* c4 = (const float4*)col;
    #pragma unroll
    for (int t = 0; t < 5; t++) {
        float4 x = c4[t];
        l[4*t+0] = fmaf(u, x.x, l[4*t+0]); l[4*t+1] = fmaf(u, x.y, l[4*t+1]);
        l[4*t+2] = fmaf(u, x.z, l[4*t+2]); l[4*t+3] = fmaf(u, x.w, l[4*t+3]);
    }
}
__device__ __forceinline__ void axpy16(float u, const float* col, float* l) {
    const float4* c4 = (const float4*)col;
    #pragma unroll
    for (int t = 0; t < 4; t++) {
        float4 x = c4[t];
        l[4*t+0] = fmaf(u, x.x, l[4*t+0]); l[4*t+1] = fmaf(u, x.y, l[4*t+1]);
        l[4*t+2] = fmaf(u, x.z, l[4*t+2]); l[4*t+3] = fmaf(u, x.w, l[4*t+3]);
    }
}

// scalar recompose for tiny kernels: Out[i*N+j] = sum_k V[i,k] fw[k] V[j,k]
template<int N>
__device__ __forceinline__ void recompose_cm(const float* V, const float* fw,
                                             float* Out, int lane) {
    #pragma unroll
    for (int t = 0; t < (N * N + 31) / 32; t++) {
        int idx = lane + 32 * t;
        if (idx < N * N) {
            int i = idx / N, j = idx - i * N;
            float acc = 0.0f;
            #pragma unroll
            for (int k = 0; k < N; k++)
                acc = fmaf(V[k * LDC + i] * fw[k], V[k * LDC + j], acc);
            Out[idx] = acc;
        }
    }
}

// ============ K1: per-sample logm(X) -> g_V2 (as L scratch) ============
__global__ void __launch_bounds__(256, 3) k_logsum(const float* __restrict__ X, int B) {
    __shared__ WarpWS ws[WPB];
    int tid = threadIdx.x, warp = tid >> 5, lane = tid & 31;
    WarpWS* w = &ws[warp];
    for (int m = 0; m < MPW; m++) {
        int b = ((int)blockIdx.x * WPB + warp) * MPW + m;
        if (b >= B) continue;
        const float4* Xb4 = (const float4*)(X + (size_t)b * 400);
        for (int idx = lane; idx < 100; idx += 32) ((float4*)w->V)[idx] = Xb4[idx];
        __syncwarp();
        // pack upper triangle: lane owns column lane (entries i<=lane)
        if (lane < 20) {
            int basea = lane * (lane + 1) / 2;
            #pragma unroll
            for (int i = 0; i < 20; i++)
                if (i <= lane) w->A[basea + i] = w->V[i * 20 + lane];
        }
        jacobi_tri20<SW_AVG20>(w, lane);   // syncs internally before first read
        if (lane < 20) w->aux[lane] = logf(w->A[lane * (lane + 3) / 2]);
        __syncwarp();
        if (lane < 20) {
            float l[20];
            #pragma unroll
            for (int i = 0; i < 20; i++) l[i] = 0.0f;
            #pragma unroll
            for (int k = 0; k < 20; k++) {
                float u = w->aux[k] * w->V[k * LDC + lane];
                axpy20(u, w->V + k * LDC, l);
            }
            float4* Lb = (float4*)(g_V2 + (size_t)b * 400 + lane * 20);
            #pragma unroll
            for (int t = 0; t < 5; t++)
                Lb[t] = make_float4(l[4*t], l[4*t+1], l[4*t+2], l[4*t+3]);
        }
        __syncwarp();
    }
}

// ===== K1b: deterministic domain-segmented sum of L over samples =====
__global__ void __launch_bounds__(256) kr_dsum(const int* __restrict__ dom, int B) {
    int warp = threadIdx.x >> 5, lane = threadIdx.x & 31;
    int c = blockIdx.x & 3;
    int split = ((int)blockIdx.x >> 2) * 8 + warp;
    int per = (B + NSPLIT - 1) / NSPLIT;
    int b0 = split * per, b1 = b0 + per;
    if (b1 > B) b1 = B;
    int e = c * 128 + lane * 4;
    bool valid = e < 400;
    float4 a0 = make_float4(0,0,0,0), a1 = a0, a2 = a0, a3 = a0;
    int cnt0 = 0, cnt1 = 0, cnt2 = 0, cnt3 = 0;
    for (int b = b0; b < b1; b++) {
        int d = dom[b];
        float4 v = make_float4(0,0,0,0);
        if (valid) v = *(const float4*)(g_V2 + (size_t)b * 400 + e);
        if (d == 0)      { a0.x += v.x; a0.y += v.y; a0.z += v.z; a0.w += v.w; cnt0++; }
        else if (d == 1) { a1.x += v.x; a1.y += v.y; a1.z += v.z; a1.w += v.w; cnt1++; }
        else if (d == 2) { a2.x += v.x; a2.y += v.y; a2.z += v.z; a2.w += v.w; cnt2++; }
        else             { a3.x += v.x; a3.y += v.y; a3.z += v.z; a3.w += v.w; cnt3++; }
    }
    if (valid) {
        size_t base = (((size_t)c * NSPLIT + split) * NDOM) * 128 + lane * 4;
        *(float4*)(g_part2 + base + 0 * 128) = a0;
        *(float4*)(g_part2 + base + 1 * 128) = a1;
        *(float4*)(g_part2 + base + 2 * 128) = a2;
        *(float4*)(g_part2 + base + 3 * 128) = a3;
    }
    if (c == 0 && lane == 0) {
        g_partCnt[split * NDOM + 0] = (float)cnt0;
        g_partCnt[split * NDOM + 1] = (float)cnt1;
        g_partCnt[split * NDOM + 2] = (float)cnt2;
        g_partCnt[split * NDOM + 3] = (float)cnt3;
    }
}

// ============ K2: reduce partials -> meanL, counts; Ginv[d] = V e^{-w/2} Vt ============
__global__ void __launch_bounds__(256) k_ginv() {
    __shared__ WarpWS ws[4];
    __shared__ float meanL[NDOM * 400];
    int tid = threadIdx.x;
    if (tid < NDOM) {
        float c = 0.0f;
        for (int sp = 0; sp < NSPLIT; sp++) c += g_partCnt[sp * NDOM + tid];
        g_cnt[tid] = c;
    }
    for (int out = tid; out < NDOM * 400; out += 256) {
        int d = out / 400, e = out - d * 400;
        int c = e >> 7, i = e & 127;
        float s = 0.0f;
        for (int sp = 0; sp < NSPLIT; sp++)
            s += g_part2[(((size_t)c * NSPLIT + sp) * NDOM + d) * 128 + i];
        meanL[out] = s;
    }
    __syncthreads();
    int warp = tid >> 5, lane = tid & 31;
    if (warp < 4) {
        int d = warp;
        float inv = 1.0f / g_cnt[d];
        WarpWS* w = &ws[warp];
        for (int idx = lane; idx < 400; idx += 32)
            w->A[idx] = meanL[d * 400 + idx] * inv;
        __syncwarp();
        jacobi_cm<20, SW_SMALL>(w, lane);
        if (lane < 20) w->aux[lane] = expf(-0.5f * w->A[lane * LDC + lane]);
        __syncwarp();
        recompose_cm<20>(w->V, w->aux, g_Ginv + d * 400, lane);
    }
}

// ====== K3: M = Gi X Gi, eigh -> store V,logw; per-domain sum ||logM||^2 ======
__global__ void __launch_bounds__(256, 3) k_center(const float* __restrict__ X,
                                                   const int* __restrict__ dom, int B) {
    __shared__ float Gi[NDOM * 400];
    __shared__ float nrmAcc[WPB][NDOM];
    __shared__ WarpWS ws[WPB];
    int tid = threadIdx.x, warp = tid >> 5, lane = tid & 31;
    for (int idx = tid; idx < NDOM * 400; idx += 256) Gi[idx] = g_Ginv[idx];
    if (tid < WPB * NDOM) ((float*)nrmAcc)[tid] = 0.0f;
    __syncthreads();
    WarpWS* w = &ws[warp];
    for (int m = 0; m < MPW; m++) {
        int b = ((int)blockIdx.x * WPB + warp) * MPW + m;
        if (b < B) {
            int d = dom[b];
            const float* G = Gi + d * 400;
            const float4* Xb4 = (const float4*)(X + (size_t)b * 400);
            for (int idx = lane; idx < 100; idx += 32)
                ((float4*)w->V)[idx] = Xb4[idx];
            __syncwarp();
            float res[20];
            if (lane < 20) {
                float g[20];
                #pragma unroll
                for (int k = 0; k < 20; k++) g[k] = G[k * 20 + lane];
                float y[20];
                #pragma unroll
                for (int i = 0; i < 20; i++) y[i] = dot20(w->V + i * 20, g);
                #pragma unroll
                for (int i = 0; i < 20; i++) res[i] = dot20(G + i * 20, y);
            }
            __syncwarp();   // X reads done before jacobi spill clobbers V
            if (lane < 20) {
                int basea = lane * (lane + 1) / 2;   // column lane, entries i<=lane
                #pragma unroll
                for (int i = 0; i < 20; i++)
                    if (i <= lane) w->A[basea + i] = res[i];
            }
            jacobi_tri20<SW_PS20>(w, lane);
            if (lane < 20) w->aux[lane] = logf(w->A[lane * (lane + 3) / 2]);
            __syncwarp();
            float4* gV4 = (float4*)(g_V2 + (size_t)b * 400);
            for (int idx = lane; idx < 100; idx += 32) gV4[idx] = ((float4*)w->V)[idx];
            if (lane < 20) g_lw2[(size_t)b * 20 + lane] = w->aux[lane];
            float v = (lane < 20) ? w->aux[lane] * w->aux[lane] : 0.0f;
            #pragma unroll
            for (int off = 16; off; off >>= 1) v += __shfl_down_sync(FULLM, v, off);
            if (lane == 0) nrmAcc[warp][d] += v;
        }
    }
    __syncthreads();
    if (tid == 0) {
        float sums[NDOM] = {0.f, 0.f, 0.f, 0.f};
        for (int t = 0; t < WPB; t++)
            for (int d = 0; d < NDOM; d++) sums[d] += nrmAcc[t][d];
        for (int d = 0; d < NDOM; d++) g_partN[blockIdx.x * NDOM + d] = sums[d];
    }
}

// ============ K4: scale[d] = s / sqrt(sig2 + eps) ============
__global__ void __launch_bounds__(128) k_scale(const float* __restrict__ sptr, int NB) {
    int warp = threadIdx.x >> 5, lane = threadIdx.x & 31;
    int d = warp;
    float nsum = 0.0f;
    for (int b = lane; b < NB; b += 32) nsum += g_partN[b * NDOM + d];
    #pragma unroll
    for (int off = 16; off; off >>= 1) nsum += __shfl_down_sync(FULLM, nsum, off);
    if (lane == 0) {
        float sig2 = nsum / g_cnt[d];
        g_scale[d] = sptr[0] / sqrtf(sig2 + EPS_VAR_F);
    }
}

// ====== K5 (PAIRED eigh): Xn via eigenbasis reuse, Y = Wt Xn W, store Y, sum logm(Y) ======
__global__ void __launch_bounds__(256) k_bimap(const float* __restrict__ Wb,
                                               const int* __restrict__ dom, int B) {
    __shared__ float Ws16[320];
    __shared__ float accW[WPB * 2 * 240];
    __shared__ PairWS ws[WPB];
    int tid = threadIdx.x, warp = tid >> 5, lane = tid & 31;
    int half = lane >> 4, l16 = lane & 15;
    for (int idx = tid; idx < 320; idx += 256) {
        int i = idx >> 4, o = idx & 15;
        Ws16[idx] = (o < 15) ? Wb[i * 15 + o] : 0.0f;
    }
    __syncthreads();
    PairWS* w = &ws[warp];
    float* bufh = w->buf + half * HSTRIDE;
    int base = ((int)blockIdx.x * WPB + warp) * MPW;
    float la[15];
    #pragma unroll
    for (int i = 0; i < 15; i++) la[i] = 0.0f;

    for (int mp = 0; mp < MPW / 2; mp++) {
        for (int h = 0; h < 2; h++) {
            int b = base + mp * 2 + h;
            float* bh = w->buf + h * HSTRIDE;
            if (b < B) {
                int d = dom[b];
                float sc = g_scale[d];
                const float* gV = g_V2 + (size_t)b * 400;
                float c[16];
                if (lane < 20) {
                    float ej = expf(0.5f * sc * g_lw2[(size_t)b * 20 + lane]);
                    float z[20];
                    const float4* col4 = (const float4*)(gV + lane * 20);
                    #pragma unroll
                    for (int t = 0; t < 5; t++) {
                        float4 v = col4[t];
                        z[4*t+0] = v.x * ej; z[4*t+1] = v.y * ej;
                        z[4*t+2] = v.z * ej; z[4*t+3] = v.w * ej;
                    }
                    #pragma unroll
                    for (int o = 0; o < 16; o++) c[o] = 0.0f;
                    #pragma unroll
                    for (int i = 0; i < 20; i++) axpy16(z[i], Ws16 + i * 16, c);
                }
                __syncwarp();
                if (lane < 20) {
                    #pragma unroll
                    for (int o = 0; o < 15; o++) bh[o * 20 + lane] = c[o];
                }
                __syncwarp();
                float y[16];
                if (lane < 15) {
                    float cp[20];
                    const float4* row4 = (const float4*)(bh + lane * 20);
                    #pragma unroll
                    for (int t = 0; t < 5; t++) {
                        float4 v = row4[t];
                        cp[4*t+0] = v.x; cp[4*t+1] = v.y; cp[4*t+2] = v.z; cp[4*t+3] = v.w;
                    }
                    #pragma unroll
                    for (int o = 0; o < 15; o++) y[o] = dot20(bh + o * 20, cp);
                    y[15] = 0.0f;
                }
                __syncwarp();
                if (lane < 15) {
                    float4* Ac = (float4*)(bh + lane * LDC);
                    float4* gY4 = (float4*)(g_Y + (size_t)b * 240 + lane * 16);
                    #pragma unroll
                    for (int t = 0; t < 4; t++) {
                        float4 v = make_float4(y[4*t], y[4*t+1], y[4*t+2], y[4*t+3]);
                        Ac[t] = v;
                        gY4[t] = v;
                    }
                } else if (lane == 15) {
                    float4* Ac = (float4*)(bh + 15 * LDC);
                    #pragma unroll
                    for (int t = 0; t < 4; t++) Ac[t] = make_float4(0, 0, 0, 0);
                }
            } else {
                for (int idx = lane; idx < 320; idx += 32) bh[idx] = 0.0f;
            }
            __syncwarp();
        }
        jacobi_pair15<SW_AVG15>(w, lane);
        int bsel = base + mp * 2 + half;
        bool act = (bsel < B);
        float* auxp = (float*)w->prm;
        float dg = auxp[half * 16 + l16];
        auxp[half * 16 + l16] = act ? logf(dg) : 0.0f;
        __syncwarp();
        if (l16 < 15 && act) {
            const float* aux = auxp + half * 16;
            float l[16];
            #pragma unroll
            for (int i = 0; i < 16; i++) l[i] = 0.0f;
            #pragma unroll
            for (int k = 0; k < 15; k++) {
                float u = aux[k] * bufh[k * LDC + l16];
                axpy16(u, bufh + k * LDC, l);
            }
            #pragma unroll
            for (int i = 0; i < 15; i++) la[i] += l[i];
        }
        __syncwarp();
    }
    if (l16 < 15) {
        float* dst = accW + (warp * 2 + half) * 240;
        #pragma unroll
        for (int i = 0; i < 15; i++) dst[i * 16 + l16] = la[i];
    }
    __syncthreads();
    for (int idx = tid; idx < 225; idx += 256) {
        int i = idx / 15, j = idx - i * 15;
        float s = 0.0f;
        #pragma unroll
        for (int wp = 0; wp < WPB * 2; wp++) s += accW[wp * 240 + i * 16 + j];
        g_partLY[(size_t)blockIdx.x * 225 + idx] = s;
    }
}

// ============ K6: meanLY -> Gb = V e^{-w/2} Vt (padded 15x16) ============
__global__ void __launch_bounds__(256) k_gb(int B, int NB) {
    __shared__ float meanLY[225];
    __shared__ WarpWS ws0;
    int tid = threadIdx.x, warp = tid >> 5, lane = tid & 31;
    float invB = 1.0f / (float)B;
    for (int out = warp; out < 225; out += 8) {
        float s = 0.0f;
        for (int b = lane; b < NB; b += 32) s += g_partLY[(size_t)b * 225 + out];
        #pragma unroll
        for (int off = 16; off; off >>= 1) s += __shfl_down_sync(FULLM, s, off);
        if (lane == 0) meanLY[out] = s * invB;
    }
    __syncthreads();
    if (warp == 0) {
        for (int idx = lane; idx < 320; idx += 32) ws0.A[idx] = 0.0f;
        __syncwarp();
        for (int idx = lane; idx < 225; idx += 32) {
            int i = idx / 15, j = idx - i * 15;
            ws0.A[j * LDC + i] = meanLY[idx];
        }
        __syncwarp();
        jacobi_cm<15, SW_SMALL>(&ws0, lane);
        if (lane < 15) ws0.aux[lane] = expf(-0.5f * ws0.A[lane * LDC + lane]);
        __syncwarp();
        for (int t = 0; t < 8; t++) {
            int idx = lane + 32 * t;
            if (idx < 240) {
                int i = idx >> 4, j = idx & 15;
                float acc = 0.0f;
                if (j < 15) {
                    #pragma unroll
                    for (int k = 0; k < 15; k++)
                        acc = fmaf(ws0.V[k * LDC + i] * ws0.aux[k], ws0.V[k * LDC + j], acc);
                }
                g_Gb16[idx] = acc;
            }
        }
    }
}

// ====== K7 (PAIRED): Yn = Gb Y Gb, eigh, fused ReEig+LogEig+vec+classifier ======
__global__ void __launch_bounds__(256) k_head(const float* __restrict__ Wl,
                                              float* __restrict__ out, int B) {
    __shared__ float Gbs[240];
    __shared__ float Wf[4 * 240];
    __shared__ PairWS ws[WPB];
    int tid = threadIdx.x, warp = tid >> 5, lane = tid & 31;
    int half = lane >> 4, l16 = lane & 15;
    for (int i = tid; i < 240; i += 256) Gbs[i] = g_Gb16[i];
    for (int idx = tid; idx < 960; idx += 256) {
        int cc = idx / 240, rem = idx - cc * 240;
        int i = rem >> 4, j = rem & 15;
        float v = 0.0f;
        if (i < 15 && j < 15) {
            if (i == j) v = Wl[cc * 120 + i];
            else {
                int a = min(i, j), b2 = max(i, j);
                int off = a * 14 - a * (a - 1) / 2 + (b2 - a - 1);
                v = Wl[cc * 120 + 15 + off] * (SQRT2F * 0.5f);
            }
        }
        Wf[idx] = v;
    }
    __syncthreads();
    PairWS* w = &ws[warp];
    float* bufh = w->buf + half * HSTRIDE;
    int base = ((int)blockIdx.x * WPB + warp) * MPW;

    for (int mp = 0; mp < MPW / 2; mp++) {
        int b = base + mp * 2 + half;
        bool active = (b < B);
        if (active) {
            const float4* gY4 = (const float4*)(g_Y + (size_t)b * 240);
            for (int idx = l16; idx < 60; idx += 16) ((float4*)bufh)[idx] = gY4[idx];
        } else {
            for (int idx = l16; idx < 60; idx += 16) ((float4*)bufh)[idx] = make_float4(0,0,0,0);
        }
        __syncwarp();
        float res[16];
        if (l16 < 15) {
            float g[16];
            #pragma unroll
            for (int k = 0; k < 15; k++) g[k] = Gbs[k * 16 + l16];
            g[15] = 0.0f;
            float y[16];
            #pragma unroll
            for (int i = 0; i < 15; i++) y[i] = dot16(bufh + i * 16, g);
            y[15] = 0.0f;
            #pragma unroll
            for (int i = 0; i < 15; i++) res[i] = dot16(Gbs + i * 16, y);
            res[15] = 0.0f;
        }
        __syncwarp();
        {
            float4* Ac = (float4*)(bufh + l16 * LDC);
            if (l16 < 15) {
                #pragma unroll
                for (int t = 0; t < 4; t++)
                    Ac[t] = make_float4(res[4*t], res[4*t+1], res[4*t+2], res[4*t+3]);
            } else {
                #pragma unroll
                for (int t = 0; t < 4; t++) Ac[t] = make_float4(0, 0, 0, 0);
            }
        }
        jacobi_pair15<SW_PS15>(w, lane);
        float* auxp = (float*)w->prm;
        auxp[half * 16 + l16] = logf(fmaxf(auxp[half * 16 + l16], EPS_REEIG_F));
        __syncwarp();
        float o0 = 0.f, o1 = 0.f, o2 = 0.f, o3 = 0.f;
        if (l16 < 15) {
            const float* aux = auxp + half * 16;
            float l[16];
            #pragma unroll
            for (int i = 0; i < 16; i++) l[i] = 0.0f;
            #pragma unroll
            for (int k = 0; k < 15; k++) {
                float u = aux[k] * bufh[k * LDC + l16];
                axpy16(u, bufh + k * LDC, l);
            }
            #pragma unroll
            for (int i = 0; i < 15; i++) {
                float li = l[i];
                o0 = fmaf(Wf[0 * 240 + i * 16 + l16], li, o0);
                o1 = fmaf(Wf[1 * 240 + i * 16 + l16], li, o1);
                o2 = fmaf(Wf[2 * 240 + i * 16 + l16], li, o2);
                o3 = fmaf(Wf[3 * 240 + i * 16 + l16], li, o3);
            }
        }
        #pragma unroll
        for (int off = 8; off; off >>= 1) {
            o0 += __shfl_down_sync(FULLM, o0, off);
            o1 += __shfl_down_sync(FULLM, o1, off);
            o2 += __shfl_down_sync(FULLM, o2, off);
            o3 += __shfl_down_sync(FULLM, o3, off);
        }
        if (l16 == 0 && active) {
            float* ob = out + (size_t)b * 4;
            ob[0] = o0; ob[1] = o1; ob[2] = o2; ob[3] = o3;
        }
        __syncwarp();
    }
}

extern "C" void kernel_launch(void* const* d_in, const int* in_sizes, int n_in,
                              void* d_out, int out_size) {
    const float* X   = (const float*)d_in[0];
    const int*   dom = (const int*)d_in[1];
    const float* s   = (const float*)d_in[2];
    const float* Wb  = (const float*)d_in[3];
    const float* Wl  = (const float*)d_in[4];
    float* out = (float*)d_out;
    int B = in_sizes[0] / 400;
    if (B > MAXB) B = MAXB;
    int NB = (B + MPB - 1) / MPB;
    if (NB > NB_MAX) NB = NB_MAX;

    k_logsum<<<NB, 256>>>(X, B);
    kr_dsum<<<NCHUNK * (NSPLIT / 8), 256>>>(dom, B);
    k_ginv<<<1, 256>>>();
    k_center<<<NB, 256>>>(X, dom, B);
    k_scale<<<1, 128>>>(s, NB);
    k_bimap<<<NB, 256>>>(Wb, dom, B);
    k_gb<<<1, 256>>>(B, NB);
    k_head<<<NB, 256>>>(Wl, out, B);
}

// round 15
// speedup vs baseline: 1.3205x; 1.0143x over previous
#include <cuda_runtime.h>
#include <math.h>

#define NDOM 4
#define SQRT2F 1.41421356237309515f
#define EPS_REEIG_F 1e-4f
#define EPS_VAR_F 1e-5f

#define MAXB 32768
#define NB_MAX 1024
#define WPB 8            // warps per block
#define MPW 4            // matrices per warp
#define MPB (WPB*MPW)    // 32 matrices per block

#define LDC 20           // column stride (floats) for col-major matrices
#define SW_PS20 5        // per-sample 20x20 (k_center)
#define SW_AVG20 3       // averaged-output 20x20 (k_logsum)
#define SW_PS15 5        // per-sample 15x15 (k_head)
#define SW_AVG15 4       // averaged-output 15x15 (k_bimap)
#define SW_SMALL 7

#define NSPLIT 64        // sample splits for domain reduction
#define NCHUNK 4         // 128-float element chunks (covers 400)

#define FULLM 0xffffffffu
#define HSTRIDE 336      // per-half float offset in PairWS.buf (336 mod 32 = 16 -> bank split)

// ---------------- device scratch (static, allowed) ----------------
__device__ float g_V2[(size_t)MAXB * 400];   // k_logsum: per-sample L; later: eigenvectors of centered matrices
__device__ float g_lw2[(size_t)MAXB * 20];   // log-eigenvalues of centered matrices
__device__ float g_Y[(size_t)MAXB * 240];    // BiMap outputs, rows padded to 16
__device__ float g_part2[(size_t)NCHUNK * NSPLIT * NDOM * 128];
__device__ float g_partCnt[NSPLIT * NDOM];
__device__ float g_partN[NB_MAX * NDOM];
__device__ float g_partLY[NB_MAX * 225];
__device__ float g_cnt[NDOM];
__device__ float g_Ginv[NDOM * 400];
__device__ float g_scale[NDOM];
__device__ float g_Gb16[240];                // 15x16 padded

// ---------------- per-warp workspaces ----------------
struct WarpWS {
    __align__(16) float A[400];     // square col-major (LDC) OR triangular (210) for tri solver
    __align__(16) float V[400];     // col-major, LDC=20 (written once post-Jacobi)
    __align__(16) float4 prm[12];   // per-PAIR (c, s, p, q)
    __align__(16) float4 cinfo[20]; // per-COLUMN (c, b=±s, partner, pad) for V shfl pass
    float aux[24];
};

// paired 15x15 workspace: two matrices per warp (half = lane>>4)
struct PairWS {
    __align__(16) float buf[2 * HSTRIDE]; // per half: scratch (C or Y) -> A (16 cols x 20) -> V spill
    __align__(16) float4 prm[16];         // per half 8 pairs; reused as aux (32 floats) after jacobi
};

// round-robin tournament pair (circle method), players 0..NS-1, NS even
__device__ __forceinline__ void pair_pq(int k, int r, int M, int& p, int& q) {
    p = (k == 0) ? 0 : (1 + (k - 1 + r) % M);
    q = 1 + (M - 1 - k + r) % M;
}

// fast Jacobi rotation parameters (c, s) from app, aqq, apq.
// __fdividef + rsqrtf fast paths; tau clamped so overflow -> identity rotation.
__device__ __forceinline__ void jrot_fast(float app, float aqq, float apq,
                                          float& c, float& s) {
    c = 1.0f; s = 0.0f;
    if (fabsf(apq) > 1e-38f) {
        float tau = __fdividef(aqq - app, 2.0f * apq);
        tau = fminf(fmaxf(tau, -1e18f), 1e18f);
        float s1 = fmaf(tau, tau, 1.0f);
        float den = fabsf(tau) + s1 * rsqrtf(s1);      // |tau| + sqrt(1+tau^2)
        float tt = __fdividef((tau >= 0.0f ? 1.0f : -1.0f), den);
        c = rsqrtf(fmaf(tt, tt, 1.0f));
        s = tt * c;
    }
}

// triangular index: entry (a,b) unordered, stored at hi*(hi+1)/2 + lo
__device__ __forceinline__ int TRI(int a, int b) {
    int lo = min(a, b), hi = max(a, b);
    return hi * (hi + 1) / 2 + lo;
}

// decode linear tile index -> (ki,kj) with ki<=kj over NP=10 pairs (55 tiles)
__device__ __forceinline__ void tri_tile_decode(int idx, int& ki, int& kj) {
    ki = -1; kj = -1;
    if (idx < 10) { ki = idx; kj = idx; return; }
    if (idx >= 55) return;
    int t = idx - 10;
    #pragma unroll
    for (int r = 0; r < 9; r++) {
        int len = 9 - r;
        if (t >= 0 && t < len) { ki = r; kj = r + 1 + t; }
        t -= len;
    }
}

// one triangular tile update (diag or off-diag); A is 210-entry packed triangle
__device__ __forceinline__ void tile_tri(float* A, const float4* prm, int ki, int kj) {
    if (ki < 0) return;
    float4 Pi = prm[ki];
    float ci = Pi.x, si = Pi.y;
    int pi = __float_as_int(Pi.z), qi = __float_as_int(Pi.w);
    if (ki == kj) {
        int ipp = pi * (pi + 3) / 2, iqq = qi * (qi + 3) / 2, ipq = TRI(pi, qi);
        float app = A[ipp], apq = A[ipq], aqq = A[iqq];
        float r00 = fmaf(ci, app, -si * apq), r10 = fmaf(si, app, ci * apq);
        float r01 = fmaf(ci, apq, -si * aqq), r11 = fmaf(si, apq, ci * aqq);
        A[ipp] = fmaf(ci, r00, -si * r01);
        A[ipq] = fmaf(si, r00,  ci * r01);
        A[iqq] = fmaf(si, r10,  ci * r11);
    } else {
        float4 Pj = prm[kj];
        float cj = Pj.x, sj = Pj.y;
        int pj = __float_as_int(Pj.z), qj = __float_as_int(Pj.w);
        int i00 = TRI(pi, pj), i01 = TRI(pi, qj), i10 = TRI(qi, pj), i11 = TRI(qi, qj);
        float a00 = A[i00], a01 = A[i01], a10 = A[i10], a11 = A[i11];
        float r00 = fmaf(ci, a00, -si * a10), r10 = fmaf(si, a00, ci * a10);
        float r01 = fmaf(ci, a01, -si * a11), r11 = fmaf(si, a01, ci * a11);
        A[i00] = fmaf(cj, r00, -sj * r01);
        A[i01] = fmaf(sj, r00,  cj * r01);
        A[i10] = fmaf(cj, r10, -sj * r11);
        A[i11] = fmaf(sj, r10,  cj * r11);
    }
}

// Triangular-packed 20x20 Jacobi: A = 210-entry upper triangle in w->A,
// V register-resident (lane<20 owns column), spilled to w->V at end.
template<int SWEEPS>
__device__ void jacobi_tri20(WarpWS* w, int lane) {
    constexpr int M = 19, NP = 10;
    float* A = w->A;
    float4* prm = w->prm;
    float4* cinfo = w->cinfo;

    float v[20];
    #pragma unroll
    for (int i = 0; i < 20; i++) v[i] = (i == lane) ? 1.0f : 0.0f;

    int ki0, kj0, ki1, kj1;
    tri_tile_decode(lane, ki0, kj0);
    tri_tile_decode(lane + 32, ki1, kj1);

    __syncwarp();   // callers' A writes (other lanes) visible before first params read

    for (int sw = 0; sw < SWEEPS; sw++)
    for (int r = 0; r < M; r++) {
        if (lane < NP) {
            int p, q; pair_pq(lane, r, M, p, q);
            float c, s;
            jrot_fast(A[p * (p + 3) / 2], A[q * (q + 3) / 2], A[TRI(p, q)], c, s);
            prm[lane] = make_float4(c, s, __int_as_float(p), __int_as_float(q));
            cinfo[p] = make_float4(c, -s, __int_as_float(q), 0.0f);
            cinfo[q] = make_float4(c,  s, __int_as_float(p), 0.0f);
        }
        __syncwarp();
        float4 ci = cinfo[(lane < 20) ? lane : 0];
        float cc = (lane < 20) ? ci.x : 1.0f;
        float bb = (lane < 20) ? ci.y : 0.0f;
        int  prt = (lane < 20) ? __float_as_int(ci.z) : lane;
        tile_tri(A, prm, ki0, kj0);
        tile_tri(A, prm, ki1, kj1);
        #pragma unroll
        for (int i = 0; i < 20; i++) {
            float rv = __shfl_sync(FULLM, v[i], prt);
            v[i] = fmaf(cc, v[i], bb * rv);
        }
        __syncwarp();
    }

    if (lane < 20) {
        float4* Vc = (float4*)(w->V + lane * LDC);
        #pragma unroll
        for (int t = 0; t < 5; t++)
            Vc[t] = make_float4(v[4*t], v[4*t+1], v[4*t+2], v[4*t+3]);
    }
    __syncwarp();
}

// Warp-cooperative square Jacobi (tiny kernels: n=20 SMALL, n=15 single).
template<int N, int SWEEPS>
__device__ void jacobi_cm(WarpWS* w, int lane) {
    constexpr int NS = (N + 1) & ~1;
    constexpr int M  = NS - 1;
    constexpr int NP = NS / 2;
    constexpr int NT = NP * NP;
    float* A = w->A;
    float4* prm = w->prm;
    float4* cinfo = w->cinfo;

    float v[NS];
    #pragma unroll
    for (int i = 0; i < NS; i++) v[i] = (i == lane) ? 1.0f : 0.0f;

    for (int sw = 0; sw < SWEEPS; sw++)
    for (int r = 0; r < M; r++) {
        if (lane < NP) {
            int p, q; pair_pq(lane, r, M, p, q);
            float c, s;
            jrot_fast(A[p * LDC + p], A[q * LDC + q], A[q * LDC + p], c, s);
            prm[lane] = make_float4(c, s, __int_as_float(p), __int_as_float(q));
            cinfo[p] = make_float4(c, -s, __int_as_float(q), 0.0f);
            cinfo[q] = make_float4(c,  s, __int_as_float(p), 0.0f);
        }
        __syncwarp();
        float4 ci = cinfo[(lane < NS) ? lane : 0];
        float cc = (lane < NS) ? ci.x : 1.0f;
        float bb = (lane < NS) ? ci.y : 0.0f;
        int  prt = (lane < NS) ? __float_as_int(ci.z) : lane;
        #pragma unroll
        for (int t = 0; t < (NT + 31) / 32; t++) {
            int idx = lane + 32 * t;
            if (idx < NT) {
                int ki = idx / NP, kj = idx - ki * NP;
                float4 pi4 = prm[ki], pj4 = prm[kj];
                float ci_ = pi4.x, si = pi4.y;
                int pi = __float_as_int(pi4.z), qi = __float_as_int(pi4.w);
                float cj = pj4.x, sj = pj4.y;
                int pj = __float_as_int(pj4.z), qj = __float_as_int(pj4.w);
                float a00 = A[pj * LDC + pi], a01 = A[qj * LDC + pi];
                float a10 = A[pj * LDC + qi], a11 = A[qj * LDC + qi];
                float r00 = fmaf(ci_, a00, -si * a10), r10 = fmaf(si, a00, ci_ * a10);
                float r01 = fmaf(ci_, a01, -si * a11), r11 = fmaf(si, a01, ci_ * a11);
                A[pj * LDC + pi] = fmaf(cj, r00, -sj * r01);
                A[qj * LDC + pi] = fmaf(sj, r00,  cj * r01);
                A[pj * LDC + qi] = fmaf(cj, r10, -sj * r11);
                A[qj * LDC + qi] = fmaf(sj, r10,  cj * r11);
            }
        }
        #pragma unroll
        for (int i = 0; i < NS; i++) {
            float rv = __shfl_sync(FULLM, v[i], prt);
            v[i] = fmaf(cc, v[i], bb * rv);
        }
        __syncwarp();
    }

    if (lane < NS) {
        float4* Vc = (float4*)(w->V + lane * LDC);
        #pragma unroll
        for (int t = 0; t < NS / 4; t++)
            Vc[t] = make_float4(v[4*t], v[4*t+1], v[4*t+2], v[4*t+3]);
    }
    __syncwarp();
}

// Paired 15x15 Jacobi: two matrices per warp (half = lane>>4, column = lane&15).
template<int SWEEPS>
__device__ void jacobi_pair15(PairWS* w, int lane) {
    constexpr int MP = 15, NPP = 8;
    int half = lane >> 4, l16 = lane & 15;
    float* A = w->buf + half * HSTRIDE;
    float4* prmh = w->prm + half * 8;

    float v[16];
    #pragma unroll
    for (int i = 0; i < 16; i++) v[i] = (i == l16) ? 1.0f : 0.0f;

    for (int sw = 0; sw < SWEEPS; sw++)
    for (int r = 0; r < MP; r++) {
        if (l16 < NPP) {
            int p, q; pair_pq(l16, r, MP, p, q);
            float c, s;
            jrot_fast(A[p * LDC + p], A[q * LDC + q], A[q * LDC + p], c, s);
            prmh[l16] = make_float4(c, s, __int_as_float(p), __int_as_float(q));
        }
        __syncwarp();
        int k, prt; float sgn;
        if (l16 == 0) {
            k = 0; prt = 1 + (MP - 1 + r) % MP; sgn = -1.0f;
        } else {
            int j = l16 - 1 - r; j %= MP; if (j < 0) j += MP;
            int kp = j + 1;
            if (kp <= NPP - 1) {
                k = kp; prt = 1 + (MP - 1 - k + r) % MP; sgn = -1.0f;
            } else {
                k = (MP + r - l16) % MP;
                prt = (k == 0) ? 0 : 1 + (k - 1 + r) % MP;
                sgn = 1.0f;
            }
        }
        float4 pk = prmh[k];
        float cc = pk.x, bb = sgn * pk.y;
        int src = (half << 4) | prt;
        #pragma unroll
        for (int t = 0; t < 4; t++) {
            int idx = lane + 32 * t;
            int h2 = idx >> 6, tile = idx & 63;
            int ki = tile >> 3, kj = tile & 7;
            const float4* prr = w->prm + h2 * 8;
            float* Ah = w->buf + h2 * HSTRIDE;
            float4 pi4 = prr[ki], pj4 = prr[kj];
            float ci_ = pi4.x, si = pi4.y;
            int pi = __float_as_int(pi4.z), qi = __float_as_int(pi4.w);
            float cj = pj4.x, sj = pj4.y;
            int pj = __float_as_int(pj4.z), qj = __float_as_int(pj4.w);
            float a00 = Ah[pj * LDC + pi], a01 = Ah[qj * LDC + pi];
            float a10 = Ah[pj * LDC + qi], a11 = Ah[qj * LDC + qi];
            float r00 = fmaf(ci_, a00, -si * a10), r10 = fmaf(si, a00, ci_ * a10);
            float r01 = fmaf(ci_, a01, -si * a11), r11 = fmaf(si, a01, ci_ * a11);
            Ah[pj * LDC + pi] = fmaf(cj, r00, -sj * r01);
            Ah[qj * LDC + pi] = fmaf(sj, r00,  cj * r01);
            Ah[pj * LDC + qi] = fmaf(cj, r10, -sj * r11);
            Ah[qj * LDC + qi] = fmaf(sj, r10,  cj * r11);
        }
        #pragma unroll
        for (int i = 0; i < 16; i++) {
            float rv = __shfl_sync(FULLM, v[i], src);
            v[i] = fmaf(cc, v[i], bb * rv);
        }
        __syncwarp();
    }

    float dg = A[l16 * LDC + l16];
    __syncwarp();
    float* auxp = (float*)w->prm;
    auxp[half * 16 + l16] = dg;
    float4* Vc = (float4*)(A + l16 * LDC);
    #pragma unroll
    for (int t = 0; t < 4; t++)
        Vc[t] = make_float4(v[4*t], v[4*t+1], v[4*t+2], v[4*t+3]);
    __syncwarp();
}

// ---------- float4 dot / axpy helpers ----------
__device__ __forceinline__ float dot20(const float* row, const float* g) {
    const float4* r4 = (const float4*)row;
    float a = 0.0f;
    #pragma unroll
    for (int t = 0; t < 5; t++) {
        float4 x = r4[t];
        a = fmaf(x.x, g[4*t+0], a); a = fmaf(x.y, g[4*t+1], a);
        a = fmaf(x.z, g[4*t+2], a); a = fmaf(x.w, g[4*t+3], a);
    }
    return a;
}
__device__ __forceinline__ float dot16(const float* row, const float* g) {
    const float4* r4 = (const float4*)row;
    float a = 0.0f;
    #pragma unroll
    for (int t = 0; t < 4; t++) {
        float4 x = r4[t];
        a = fmaf(x.x, g[4*t+0], a); a = fmaf(x.y, g[4*t+1], a);
        a = fmaf(x.z, g[4*t+2], a); a = fmaf(x.w, g[4*t+3], a);
    }
    return a;
}
__device__ __forceinline__ void axpy20(float u, const float* col, float* l) {
    const float4* c4 = (const float4*)col;
    #pragma unroll
    for (int t = 0; t < 5; t++) {
        float4 x = c4[t];
        l[4*t+0] = fmaf(u, x.x, l[4*t+0]); l[4*t+1] = fmaf(u, x.y, l[4*t+1]);
        l[4*t+2] = fmaf(u, x.z, l[4*t+2]); l[4*t+3] = fmaf(u, x.w, l[4*t+3]);
    }
}
__device__ __forceinline__ void axpy16(float u, const float* col, float* l) {
    const float4* c4 = (const float4*)col;
    #pragma unroll
    for (int t = 0; t < 4; t++) {
        float4 x = c4[t];
        l[4*t+0] = fmaf(u, x.x, l[4*t+0]); l[4*t+1] = fmaf(u, x.y, l[4*t+1]);
        l[4*t+2] = fmaf(u, x.z, l[4*t+2]); l[4*t+3] = fmaf(u, x.w, l[4*t+3]);
    }
}

// scalar recompose for tiny kernels: Out[i*N+j] = sum_k V[i,k] fw[k] V[j,k]
template<int N>
__device__ __forceinline__ void recompose_cm(const float* V, const float* fw,
                                             float* Out, int lane) {
    #pragma unroll
    for (int t = 0; t < (N * N + 31) / 32; t++) {
        int idx = lane + 32 * t;
        if (idx < N * N) {
            int i = idx / N, j = idx - i * N;
            float acc = 0.0f;
            #pragma unroll
            for (int k = 0; k < N; k++)
                acc = fmaf(V[k * LDC + i] * fw[k], V[k * LDC + j], acc);
            Out[idx] = acc;
        }
    }
}

// ============ K1: per-sample logm(X) -> g_V2 (as L scratch) ============
__global__ void __launch_bounds__(256, 3) k_logsum(const float* __restrict__ X, int B) {
    __shared__ WarpWS ws[WPB];
    int tid = threadIdx.x, warp = tid >> 5, lane = tid & 31;
    WarpWS* w = &ws[warp];
    for (int m = 0; m < MPW; m++) {
        int b = ((int)blockIdx.x * WPB + warp) * MPW + m;
        if (b >= B) continue;
        const float4* Xb4 = (const float4*)(X + (size_t)b * 400);
        for (int idx = lane; idx < 100; idx += 32) ((float4*)w->V)[idx] = Xb4[idx];
        __syncwarp();
        if (lane < 20) {
            int basea = lane * (lane + 1) / 2;
            #pragma unroll
            for (int i = 0; i < 20; i++)
                if (i <= lane) w->A[basea + i] = w->V[i * 20 + lane];
        }
        jacobi_tri20<SW_AVG20>(w, lane);
        if (lane < 20) w->aux[lane] = __logf(w->A[lane * (lane + 3) / 2]);
        __syncwarp();
        if (lane < 20) {
            float l[20];
            #pragma unroll
            for (int i = 0; i < 20; i++) l[i] = 0.0f;
            #pragma unroll
            for (int k = 0; k < 20; k++) {
                float u = w->aux[k] * w->V[k * LDC + lane];
                axpy20(u, w->V + k * LDC, l);
            }
            float4* Lb = (float4*)(g_V2 + (size_t)b * 400 + lane * 20);
            #pragma unroll
            for (int t = 0; t < 5; t++)
                Lb[t] = make_float4(l[4*t], l[4*t+1], l[4*t+2], l[4*t+3]);
        }
        __syncwarp();
    }
}

// ===== K1b: deterministic domain-segmented sum of L over samples =====
__global__ void __launch_bounds__(256) kr_dsum(const int* __restrict__ dom, int B) {
    int warp = threadIdx.x >> 5, lane = threadIdx.x & 31;
    int c = blockIdx.x & 3;
    int split = ((int)blockIdx.x >> 2) * 8 + warp;
    int per = (B + NSPLIT - 1) / NSPLIT;
    int b0 = split * per, b1 = b0 + per;
    if (b1 > B) b1 = B;
    int e = c * 128 + lane * 4;
    bool valid = e < 400;
    float4 a0 = make_float4(0,0,0,0), a1 = a0, a2 = a0, a3 = a0;
    int cnt0 = 0, cnt1 = 0, cnt2 = 0, cnt3 = 0;
    for (int b = b0; b < b1; b++) {
        int d = dom[b];
        float4 v = make_float4(0,0,0,0);
        if (valid) v = *(const float4*)(g_V2 + (size_t)b * 400 + e);
        if (d == 0)      { a0.x += v.x; a0.y += v.y; a0.z += v.z; a0.w += v.w; cnt0++; }
        else if (d == 1) { a1.x += v.x; a1.y += v.y; a1.z += v.z; a1.w += v.w; cnt1++; }
        else if (d == 2) { a2.x += v.x; a2.y += v.y; a2.z += v.z; a2.w += v.w; cnt2++; }
        else             { a3.x += v.x; a3.y += v.y; a3.z += v.z; a3.w += v.w; cnt3++; }
    }
    if (valid) {
        size_t base = (((size_t)c * NSPLIT + split) * NDOM) * 128 + lane * 4;
        *(float4*)(g_part2 + base + 0 * 128) = a0;
        *(float4*)(g_part2 + base + 1 * 128) = a1;
        *(float4*)(g_part2 + base + 2 * 128) = a2;
        *(float4*)(g_part2 + base + 3 * 128) = a3;
    }
    if (c == 0 && lane == 0) {
        g_partCnt[split * NDOM + 0] = (float)cnt0;
        g_partCnt[split * NDOM + 1] = (float)cnt1;
        g_partCnt[split * NDOM + 2] = (float)cnt2;
        g_partCnt[split * NDOM + 3] = (float)cnt3;
    }
}

// ============ K2: reduce partials -> meanL, counts; Ginv[d] = V e^{-w/2} Vt ============
__global__ void __launch_bounds__(256) k_ginv() {
    __shared__ WarpWS ws[4];
    __shared__ float meanL[NDOM * 400];
    int tid = threadIdx.x;
    if (tid < NDOM) {
        float c = 0.0f;
        for (int sp = 0; sp < NSPLIT; sp++) c += g_partCnt[sp * NDOM + tid];
        g_cnt[tid] = c;
    }
    for (int out = tid; out < NDOM * 400; out += 256) {
        int d = out / 400, e = out - d * 400;
        int c = e >> 7, i = e & 127;
        float s = 0.0f;
        for (int sp = 0; sp < NSPLIT; sp++)
            s += g_part2[(((size_t)c * NSPLIT + sp) * NDOM + d) * 128 + i];
        meanL[out] = s;
    }
    __syncthreads();
    int warp = tid >> 5, lane = tid & 31;
    if (warp < 4) {
        int d = warp;
        float inv = 1.0f / g_cnt[d];
        WarpWS* w = &ws[warp];
        for (int idx = lane; idx < 400; idx += 32)
            w->A[idx] = meanL[d * 400 + idx] * inv;
        __syncwarp();
        jacobi_cm<20, SW_SMALL>(w, lane);
        if (lane < 20) w->aux[lane] = __expf(-0.5f * w->A[lane * LDC + lane]);
        __syncwarp();
        recompose_cm<20>(w->V, w->aux, g_Ginv + d * 400, lane);
    }
}

// ====== K3: M = Gi X Gi, eigh -> store V,logw; per-domain sum ||logM||^2 ======
__global__ void __launch_bounds__(256, 3) k_center(const float* __restrict__ X,
                                                   const int* __restrict__ dom, int B) {
    __shared__ float Gi[NDOM * 400];
    __shared__ float nrmAcc[WPB][NDOM];
    __shared__ WarpWS ws[WPB];
    int tid = threadIdx.x, warp = tid >> 5, lane = tid & 31;
    for (int idx = tid; idx < NDOM * 400; idx += 256) Gi[idx] = g_Ginv[idx];
    if (tid < WPB * NDOM) ((float*)nrmAcc)[tid] = 0.0f;
    __syncthreads();
    WarpWS* w = &ws[warp];
    for (int m = 0; m < MPW; m++) {
        int b = ((int)blockIdx.x * WPB + warp) * MPW + m;
        if (b < B) {
            int d = dom[b];
            const float* G = Gi + d * 400;
            const float4* Xb4 = (const float4*)(X + (size_t)b * 400);
            for (int idx = lane; idx < 100; idx += 32)
                ((float4*)w->V)[idx] = Xb4[idx];
            __syncwarp();
            float res[20];
            if (lane < 20) {
                float g[20];
                #pragma unroll
                for (int k = 0; k < 20; k++) g[k] = G[k * 20 + lane];
                float y[20];
                #pragma unroll
                for (int i = 0; i < 20; i++) y[i] = dot20(w->V + i * 20, g);
                #pragma unroll
                for (int i = 0; i < 20; i++) res[i] = dot20(G + i * 20, y);
            }
            __syncwarp();   // X reads done before jacobi spill clobbers V
            if (lane < 20) {
                int basea = lane * (lane + 1) / 2;
                #pragma unroll
                for (int i = 0; i < 20; i++)
                    if (i <= lane) w->A[basea + i] = res[i];
            }
            jacobi_tri20<SW_PS20>(w, lane);
            if (lane < 20) w->aux[lane] = __logf(w->A[lane * (lane + 3) / 2]);
            __syncwarp();
            float4* gV4 = (float4*)(g_V2 + (size_t)b * 400);
            for (int idx = lane; idx < 100; idx += 32) gV4[idx] = ((float4*)w->V)[idx];
            if (lane < 20) g_lw2[(size_t)b * 20 + lane] = w->aux[lane];
            float v = (lane < 20) ? w->aux[lane] * w->aux[lane] : 0.0f;
            #pragma unroll
            for (int off = 16; off; off >>= 1) v += __shfl_down_sync(FULLM, v, off);
            if (lane == 0) nrmAcc[warp][d] += v;
        }
    }
    __syncthreads();
    if (tid == 0) {
        float sums[NDOM] = {0.f, 0.f, 0.f, 0.f};
        for (int t = 0; t < WPB; t++)
            for (int d = 0; d < NDOM; d++) sums[d] += nrmAcc[t][d];
        for (int d = 0; d < NDOM; d++) g_partN[blockIdx.x * NDOM + d] = sums[d];
    }
}

// ============ K4: scale[d] = s / sqrt(sig2 + eps) ============
__global__ void __launch_bounds__(128) k_scale(const float* __restrict__ sptr, int NB) {
    int warp = threadIdx.x >> 5, lane = threadIdx.x & 31;
    int d = warp;
    float nsum = 0.0f;
    for (int b = lane; b < NB; b += 32) nsum += g_partN[b * NDOM + d];
    #pragma unroll
    for (int off = 16; off; off >>= 1) nsum += __shfl_down_sync(FULLM, nsum, off);
    if (lane == 0) {
        float sig2 = nsum / g_cnt[d];
        g_scale[d] = sptr[0] / sqrtf(sig2 + EPS_VAR_F);
    }
}

// ====== K5 (PAIRED eigh): Xn via eigenbasis reuse, Y = Wt Xn W, store Y, sum logm(Y) ======
__global__ void __launch_bounds__(256) k_bimap(const float* __restrict__ Wb,
                                               const int* __restrict__ dom, int B) {
    __shared__ float Ws16[320];
    __shared__ float accW[WPB * 2 * 240];
    __shared__ PairWS ws[WPB];
    int tid = threadIdx.x, warp = tid >> 5, lane = tid & 31;
    int half = lane >> 4, l16 = lane & 15;
    for (int idx = tid; idx < 320; idx += 256) {
        int i = idx >> 4, o = idx & 15;
        Ws16[idx] = (o < 15) ? Wb[i * 15 + o] : 0.0f;
    }
    __syncthreads();
    PairWS* w = &ws[warp];
    float* bufh = w->buf + half * HSTRIDE;
    int base = ((int)blockIdx.x * WPB + warp) * MPW;
    float la[15];
    #pragma unroll
    for (int i = 0; i < 15; i++) la[i] = 0.0f;

    for (int mp = 0; mp < MPW / 2; mp++) {
        for (int h = 0; h < 2; h++) {
            int b = base + mp * 2 + h;
            float* bh = w->buf + h * HSTRIDE;
            if (b < B) {
                int d = dom[b];
                float sc = g_scale[d];
                const float* gV = g_V2 + (size_t)b * 400;
                float c[16];
                if (lane < 20) {
                    float ej = __expf(0.5f * sc * g_lw2[(size_t)b * 20 + lane]);
                    float z[20];
                    const float4* col4 = (const float4*)(gV + lane * 20);
                    #pragma unroll
                    for (int t = 0; t < 5; t++) {
                        float4 v = col4[t];
                        z[4*t+0] = v.x * ej; z[4*t+1] = v.y * ej;
                        z[4*t+2] = v.z * ej; z[4*t+3] = v.w * ej;
                    }
                    #pragma unroll
                    for (int o = 0; o < 16; o++) c[o] = 0.0f;
                    #pragma unroll
                    for (int i = 0; i < 20; i++) axpy16(z[i], Ws16 + i * 16, c);
                }
                __syncwarp();
                if (lane < 20) {
                    #pragma unroll
                    for (int o = 0; o < 15; o++) bh[o * 20 + lane] = c[o];
                }
                __syncwarp();
                float y[16];
                if (lane < 15) {
                    float cp[20];
                    const float4* row4 = (const float4*)(bh + lane * 20);
                    #pragma unroll
                    for (int t = 0; t < 5; t++) {
                        float4 v = row4[t];
                        cp[4*t+0] = v.x; cp[4*t+1] = v.y; cp[4*t+2] = v.z; cp[4*t+3] = v.w;
                    }
                    #pragma unroll
                    for (int o = 0; o < 15; o++) y[o] = dot20(bh + o * 20, cp);
                    y[15] = 0.0f;
                }
                __syncwarp();
                if (lane < 15) {
                    float4* Ac = (float4*)(bh + lane * LDC);
                    float4* gY4 = (float4*)(g_Y + (size_t)b * 240 + lane * 16);
                    #pragma unroll
                    for (int t = 0; t < 4; t++) {
                        float4 v = make_float4(y[4*t], y[4*t+1], y[4*t+2], y[4*t+3]);
                        Ac[t] = v;
                        gY4[t] = v;
                    }
                } else if (lane == 15) {
                    float4* Ac = (float4*)(bh + 15 * LDC);
                    #pragma unroll
                    for (int t = 0; t < 4; t++) Ac[t] = make_float4(0, 0, 0, 0);
                }
            } else {
                for (int idx = lane; idx < 320; idx += 32) bh[idx] = 0.0f;
            }
            __syncwarp();
        }
        jacobi_pair15<SW_AVG15>(w, lane);
        int bsel = base + mp * 2 + half;
        bool act = (bsel < B);
        float* auxp = (float*)w->prm;
        float dg = auxp[half * 16 + l16];
        auxp[half * 16 + l16] = act ? __logf(dg) : 0.0f;
        __syncwarp();
        if (l16 < 15 && act) {
            const float* aux = auxp + half * 16;
            float l[16];
            #pragma unroll
            for (int i = 0; i < 16; i++) l[i] = 0.0f;
            #pragma unroll
            for (int k = 0; k < 15; k++) {
                float u = aux[k] * bufh[k * LDC + l16];
                axpy16(u, bufh + k * LDC, l);
            }
            #pragma unroll
            for (int i = 0; i < 15; i++) la[i] += l[i];
        }
        __syncwarp();
    }
    if (l16 < 15) {
        float* dst = accW + (warp * 2 + half) * 240;
        #pragma unroll
        for (int i = 0; i < 15; i++) dst[i * 16 + l16] = la[i];
    }
    __syncthreads();
    for (int idx = tid; idx < 225; idx += 256) {
        int i = idx / 15, j = idx - i * 15;
        float s = 0.0f;
        #pragma unroll
        for (int wp = 0; wp < WPB * 2; wp++) s += accW[wp * 240 + i * 16 + j];
        g_partLY[(size_t)blockIdx.x * 225 + idx] = s;
    }
}

// ============ K6: meanLY -> Gb = V e^{-w/2} Vt (padded 15x16) ============
__global__ void __launch_bounds__(256) k_gb(int B, int NB) {
    __shared__ float meanLY[225];
    __shared__ WarpWS ws0;
    int tid = threadIdx.x, warp = tid >> 5, lane = tid & 31;
    float invB = 1.0f / (float)B;
    for (int out = warp; out < 225; out += 8) {
        float s = 0.0f;
        for (int b = lane; b < NB; b += 32) s += g_partLY[(size_t)b * 225 + out];
        #pragma unroll
        for (int off = 16; off; off >>= 1) s += __shfl_down_sync(FULLM, s, off);
        if (lane == 0) meanLY[out] = s * invB;
    }
    __syncthreads();
    if (warp == 0) {
        for (int idx = lane; idx < 320; idx += 32) ws0.A[idx] = 0.0f;
        __syncwarp();
        for (int idx = lane; idx < 225; idx += 32) {
            int i = idx / 15, j = idx - i * 15;
            ws0.A[j * LDC + i] = meanLY[idx];
        }
        __syncwarp();
        jacobi_cm<15, SW_SMALL>(&ws0, lane);
        if (lane < 15) ws0.aux[lane] = __expf(-0.5f * ws0.A[lane * LDC + lane]);
        __syncwarp();
        for (int t = 0; t < 8; t++) {
            int idx = lane + 32 * t;
            if (idx < 240) {
                int i = idx >> 4, j = idx & 15;
                float acc = 0.0f;
                if (j < 15) {
                    #pragma unroll
                    for (int k = 0; k < 15; k++)
                        acc = fmaf(ws0.V[k * LDC + i] * ws0.aux[k], ws0.V[k * LDC + j], acc);
                }
                g_Gb16[idx] = acc;
            }
        }
    }
}

// ====== K7 (PAIRED): Yn = Gb Y Gb, eigh, fused ReEig+LogEig+vec+classifier ======
__global__ void __launch_bounds__(256) k_head(const float* __restrict__ Wl,
                                              float* __restrict__ out, int B) {
    __shared__ float Gbs[240];
    __shared__ float Wf[4 * 240];
    __shared__ PairWS ws[WPB];
    int tid = threadIdx.x, warp = tid >> 5, lane = tid & 31;
    int half = lane >> 4, l16 = lane & 15;
    for (int i = tid; i < 240; i += 256) Gbs[i] = g_Gb16[i];
    for (int idx = tid; idx < 960; idx += 256) {
        int cc = idx / 240, rem = idx - cc * 240;
        int i = rem >> 4, j = rem & 15;
        float v = 0.0f;
        if (i < 15 && j < 15) {
            if (i == j) v = Wl[cc * 120 + i];
            else {
                int a = min(i, j), b2 = max(i, j);
                int off = a * 14 - a * (a - 1) / 2 + (b2 - a - 1);
                v = Wl[cc * 120 + 15 + off] * (SQRT2F * 0.5f);
            }
        }
        Wf[idx] = v;
    }
    __syncthreads();
    PairWS* w = &ws[warp];
    float* bufh = w->buf + half * HSTRIDE;
    int base = ((int)blockIdx.x * WPB + warp) * MPW;

    for (int mp = 0; mp < MPW / 2; mp++) {
        int b = base + mp * 2 + half;
        bool active = (b < B);
        if (active) {
            const float4* gY4 = (const float4*)(g_Y + (size_t)b * 240);
            for (int idx = l16; idx < 60; idx += 16) ((float4*)bufh)[idx] = gY4[idx];
        } else {
            for (int idx = l16; idx < 60; idx += 16) ((float4*)bufh)[idx] = make_float4(0,0,0,0);
        }
        __syncwarp();
        float res[16];
        if (l16 < 15) {
            float g[16];
            #pragma unroll
            for (int k = 0; k < 15; k++) g[k] = Gbs[k * 16 + l16];
            g[15] = 0.0f;
            float y[16];
            #pragma unroll
            for (int i = 0; i < 15; i++) y[i] = dot16(bufh + i * 16, g);
            y[15] = 0.0f;
            #pragma unroll
            for (int i = 0; i < 15; i++) res[i] = dot16(Gbs + i * 16, y);
            res[15] = 0.0f;
        }
        __syncwarp();
        {
            float4* Ac = (float4*)(bufh + l16 * LDC);
            if (l16 < 15) {
                #pragma unroll
                for (int t = 0; t < 4; t++)
                    Ac[t] = make_float4(res[4*t], res[4*t+1], res[4*t+2], res[4*t+3]);
            } else {
                #pragma unroll
                for (int t = 0; t < 4; t++) Ac[t] = make_float4(0, 0, 0, 0);
            }
        }
        jacobi_pair15<SW_PS15>(w, lane);
        float* auxp = (float*)w->prm;
        auxp[half * 16 + l16] = __logf(fmaxf(auxp[half * 16 + l16], EPS_REEIG_F));
        __syncwarp();
        float o0 = 0.f, o1 = 0.f, o2 = 0.f, o3 = 0.f;
        if (l16 < 15) {
            const float* aux = auxp + half * 16;
            float l[16];
            #pragma unroll
            for (int i = 0; i < 16; i++) l[i] = 0.0f;
            #pragma unroll
            for (int k = 0; k < 15; k++) {
                float u = aux[k] * bufh[k * LDC + l16];
                axpy16(u, bufh + k * LDC, l);
            }
            #pragma unroll
            for (int i = 0; i < 15; i++) {
                float li = l[i];
                o0 = fmaf(Wf[0 * 240 + i * 16 + l16], li, o0);
                o1 = fmaf(Wf[1 * 240 + i * 16 + l16], li, o1);
                o2 = fmaf(Wf[2 * 240 + i * 16 + l16], li, o2);
                o3 = fmaf(Wf[3 * 240 + i * 16 + l16], li, o3);
            }
        }
        #pragma unroll
        for (int off = 8; off; off >>= 1) {
            o0 += __shfl_down_sync(FULLM, o0, off);
            o1 += __shfl_down_sync(FULLM, o1, off);
            o2 += __shfl_down_sync(FULLM, o2, off);
            o3 += __shfl_down_sync(FULLM, o3, off);
        }
        if (l16 == 0 && active) {
            float* ob = out + (size_t)b * 4;
            ob[0] = o0; ob[1] = o1; ob[2] = o2; ob[3] = o3;
        }
        __syncwarp();
    }
}

extern "C" void kernel_launch(void* const* d_in, const int* in_sizes, int n_in,
                              void* d_out, int out_size) {
    const float* X   = (const float*)d_in[0];
    const int*   dom = (const int*)d_in[1];
    const float* s   = (const float*)d_in[2];
    const float* Wb  = (const float*)d_in[3];
    const float* Wl  = (const float*)d_in[4];
    float* out = (float*)d_out;
    int B = in_sizes[0] / 400;
    if (B > MAXB) B = MAXB;
    int NB = (B + MPB - 1) / MPB;
    if (NB > NB_MAX) NB = NB_MAX;

    k_logsum<<<NB, 256>>>(X, B);
    kr_dsum<<<NCHUNK * (NSPLIT / 8), 256>>>(dom, B);
    k_ginv<<<1, 256>>>();
    k_center<<<NB, 256>>>(X, dom, B);
    k_scale<<<1, 128>>>(s, NB);
    k_bimap<<<NB, 256>>>(Wb, dom, B);
    k_gb<<<1, 256>>>(B, NB);
    k_head<<<NB, 256>>>(Wl, out, B);
}

// round 16
// speedup vs baseline: 1.3818x; 1.0465x over previous
#include <cuda_runtime.h>
#include <math.h>

#define NDOM 4
#define SQRT2F 1.41421356237309515f
#define EPS_REEIG_F 1e-4f
#define EPS_VAR_F 1e-5f

#define MAXB 32768
#define NB_MAX 1024
#define WPB 8            // warps per block
#define MPW 4            // matrices per warp
#define MPB (WPB*MPW)    // 32 matrices per block

#define LDC 20           // column stride (floats) for col-major matrices
#define SW_PS20 5        // per-sample 20x20 (k_center)
#define SW_AVG20 3       // averaged-output 20x20 (k_logsum)
#define SW_PS15 5        // per-sample 15x15 (k_head)
#define SW_AVG15 4       // averaged-output 15x15 (k_bimap)
#define SW_SMALL 7

#define NSPLIT 64        // sample splits for domain reduction
#define NCHUNK 4         // 128-float element chunks (covers 400)

#define FULLM 0xffffffffu
#define HSTRIDE 336      // per-half float offset in PairWS.buf (336 mod 32 = 16 -> bank split)

// ---------------- device scratch (static, allowed) ----------------
__device__ float g_V2[(size_t)MAXB * 400];   // k_logsum: per-sample L; later: eigenvectors of centered matrices
__device__ float g_lw2[(size_t)MAXB * 20];   // log-eigenvalues of centered matrices
__device__ float g_Y[(size_t)MAXB * 240];    // BiMap outputs, rows padded to 16
__device__ float g_part2[(size_t)NCHUNK * NSPLIT * NDOM * 128];
__device__ float g_partCnt[NSPLIT * NDOM];
__device__ float g_partN[NB_MAX * NDOM];
__device__ float g_partLY[NB_MAX * 225];
__device__ float g_cnt[NDOM];
__device__ float g_Ginv[NDOM * 400];
__device__ float g_scale[NDOM];
__device__ float g_Gb16[240];                // 15x16 padded

// ---------------- per-warp workspaces ----------------
struct WarpWS {
    __align__(16) float A[400];     // square col-major (LDC) OR lower-packed (max*20+min) for lsq solver
    __align__(16) float V[400];     // col-major, LDC=20 (written once post-Jacobi)
    __align__(16) float4 prm[12];   // per-PAIR (c, s, p, q)
    __align__(16) float4 cinfo[20]; // per-COLUMN (c, b=±s, partner, pad) for V shfl pass
    float aux[24];
};

// paired 15x15 workspace: two matrices per warp (half = lane>>4)
struct PairWS {
    __align__(16) float buf[2 * HSTRIDE]; // per half: scratch (C or Y) -> A (16 cols x 20) -> V spill
    __align__(16) float4 prm[16];         // per half 8 pairs; reused as aux (32 floats) after jacobi
};

// round-robin tournament pair (circle method), players 0..NS-1, NS even
__device__ __forceinline__ void pair_pq(int k, int r, int M, int& p, int& q) {
    p = (k == 0) ? 0 : (1 + (k - 1 + r) % M);
    q = 1 + (M - 1 - k + r) % M;
}

// fast Jacobi rotation parameters (c, s) from app, aqq, apq.
__device__ __forceinline__ void jrot_fast(float app, float aqq, float apq,
                                          float& c, float& s) {
    c = 1.0f; s = 0.0f;
    if (fabsf(apq) > 1e-38f) {
        float tau = __fdividef(aqq - app, 2.0f * apq);
        tau = fminf(fmaxf(tau, -1e18f), 1e18f);
        float s1 = fmaf(tau, tau, 1.0f);
        float den = fabsf(tau) + s1 * rsqrtf(s1);      // |tau| + sqrt(1+tau^2)
        float tt = __fdividef((tau >= 0.0f ? 1.0f : -1.0f), den);
        c = rsqrtf(fmaf(tt, tt, 1.0f));
        s = tt * c;
    }
}

// lower-square index: entry (a,b) unordered, stored at max*20+min
__device__ __forceinline__ int LSQ(int a, int b) {
    int lo = min(a, b), hi = max(a, b);
    return hi * 20 + lo;
}

// decode linear tile index -> (ki,kj) with ki<=kj over NP=10 pairs (55 tiles)
__device__ __forceinline__ void tri_tile_decode(int idx, int& ki, int& kj) {
    ki = -1; kj = -1;
    if (idx < 10) { ki = idx; kj = idx; return; }
    if (idx >= 55) return;
    int t = idx - 10;
    #pragma unroll
    for (int r = 0; r < 9; r++) {
        int len = 9 - r;
        if (t >= 0 && t < len) { ki = r; kj = r + 1 + t; }
        t -= len;
    }
}

// one lower-square tile update; pairs are sorted (p<q) so diag tiles need no min/max
__device__ __forceinline__ void tile_lsq(float* A, const float4* prm, int ki, int kj) {
    if (ki < 0) return;
    float4 Pi = prm[ki];
    float ci = Pi.x, si = Pi.y;
    int pi = __float_as_int(Pi.z), qi = __float_as_int(Pi.w);   // pi < qi
    if (ki == kj) {
        int ipp = pi * 21, ipq = qi * 20 + pi, iqq = qi * 21;
        float app = A[ipp], apq = A[ipq], aqq = A[iqq];
        float r00 = fmaf(ci, app, -si * apq), r10 = fmaf(si, app, ci * apq);
        float r01 = fmaf(ci, apq, -si * aqq), r11 = fmaf(si, apq, ci * aqq);
        A[ipp] = fmaf(ci, r00, -si * r01);
        A[ipq] = fmaf(si, r00,  ci * r01);
        A[iqq] = fmaf(si, r10,  ci * r11);
    } else {
        float4 Pj = prm[kj];
        float cj = Pj.x, sj = Pj.y;
        int pj = __float_as_int(Pj.z), qj = __float_as_int(Pj.w);
        int i00 = LSQ(pi, pj), i01 = LSQ(pi, qj), i10 = LSQ(qi, pj), i11 = LSQ(qi, qj);
        float a00 = A[i00], a01 = A[i01], a10 = A[i10], a11 = A[i11];
        float r00 = fmaf(ci, a00, -si * a10), r10 = fmaf(si, a00, ci * a10);
        float r01 = fmaf(ci, a01, -si * a11), r11 = fmaf(si, a01, ci * a11);
        A[i00] = fmaf(cj, r00, -sj * r01);
        A[i01] = fmaf(sj, r00,  cj * r01);
        A[i10] = fmaf(cj, r10, -sj * r11);
        A[i11] = fmaf(sj, r10,  cj * r11);
    }
}

// Lower-square-packed 20x20 Jacobi: A stored at (max*20+min) in w->A,
// V register-resident (lane<20 owns column), spilled to w->V at end.
// Pairs canonicalized p<q (swap + s negation: exactly equivalent rotation).
template<int SWEEPS>
__device__ void jacobi_lsq20(WarpWS* w, int lane) {
    constexpr int M = 19, NP = 10;
    float* A = w->A;
    float4* prm = w->prm;
    float4* cinfo = w->cinfo;

    float v[20];
    #pragma unroll
    for (int i = 0; i < 20; i++) v[i] = (i == lane) ? 1.0f : 0.0f;

    int ki0, kj0, ki1, kj1;
    tri_tile_decode(lane, ki0, kj0);
    tri_tile_decode(lane + 32, ki1, kj1);

    __syncwarp();   // callers' A writes (other lanes) visible before first params read

    for (int sw = 0; sw < SWEEPS; sw++)
    for (int r = 0; r < M; r++) {
        if (lane < NP) {
            int p, q; pair_pq(lane, r, M, p, q);
            if (p > q) { int t = p; p = q; q = t; }   // canonical p<q (s-sign symmetric)
            float c, s;
            jrot_fast(A[p * 21], A[q * 21], A[q * 20 + p], c, s);
            prm[lane] = make_float4(c, s, __int_as_float(p), __int_as_float(q));
            cinfo[p] = make_float4(c, -s, __int_as_float(q), 0.0f);
            cinfo[q] = make_float4(c,  s, __int_as_float(p), 0.0f);
        }
        __syncwarp();
        float4 ci = cinfo[(lane < 20) ? lane : 0];
        float cc = (lane < 20) ? ci.x : 1.0f;
        float bb = (lane < 20) ? ci.y : 0.0f;
        int  prt = (lane < 20) ? __float_as_int(ci.z) : lane;
        tile_lsq(A, prm, ki0, kj0);
        tile_lsq(A, prm, ki1, kj1);
        #pragma unroll
        for (int i = 0; i < 20; i++) {
            float rv = __shfl_sync(FULLM, v[i], prt);
            v[i] = fmaf(cc, v[i], bb * rv);
        }
        __syncwarp();
    }

    if (lane < 20) {
        float4* Vc = (float4*)(w->V + lane * LDC);
        #pragma unroll
        for (int t = 0; t < 5; t++)
            Vc[t] = make_float4(v[4*t], v[4*t+1], v[4*t+2], v[4*t+3]);
    }
    __syncwarp();
}

// Warp-cooperative square Jacobi (tiny kernels: n=20 SMALL, n=15 single).
template<int N, int SWEEPS>
__device__ void jacobi_cm(WarpWS* w, int lane) {
    constexpr int NS = (N + 1) & ~1;
    constexpr int M  = NS - 1;
    constexpr int NP = NS / 2;
    constexpr int NT = NP * NP;
    float* A = w->A;
    float4* prm = w->prm;
    float4* cinfo = w->cinfo;

    float v[NS];
    #pragma unroll
    for (int i = 0; i < NS; i++) v[i] = (i == lane) ? 1.0f : 0.0f;

    for (int sw = 0; sw < SWEEPS; sw++)
    for (int r = 0; r < M; r++) {
        if (lane < NP) {
            int p, q; pair_pq(lane, r, M, p, q);
            float c, s;
            jrot_fast(A[p * LDC + p], A[q * LDC + q], A[q * LDC + p], c, s);
            prm[lane] = make_float4(c, s, __int_as_float(p), __int_as_float(q));
            cinfo[p] = make_float4(c, -s, __int_as_float(q), 0.0f);
            cinfo[q] = make_float4(c,  s, __int_as_float(p), 0.0f);
        }
        __syncwarp();
        float4 ci = cinfo[(lane < NS) ? lane : 0];
        float cc = (lane < NS) ? ci.x : 1.0f;
        float bb = (lane < NS) ? ci.y : 0.0f;
        int  prt = (lane < NS) ? __float_as_int(ci.z) : lane;
        #pragma unroll
        for (int t = 0; t < (NT + 31) / 32; t++) {
            int idx = lane + 32 * t;
            if (idx < NT) {
                int ki = idx / NP, kj = idx - ki * NP;
                float4 pi4 = prm[ki], pj4 = prm[kj];
                float ci_ = pi4.x, si = pi4.y;
                int pi = __float_as_int(pi4.z), qi = __float_as_int(pi4.w);
                float cj = pj4.x, sj = pj4.y;
                int pj = __float_as_int(pj4.z), qj = __float_as_int(pj4.w);
                float a00 = A[pj * LDC + pi], a01 = A[qj * LDC + pi];
                float a10 = A[pj * LDC + qi], a11 = A[qj * LDC + qi];
                float r00 = fmaf(ci_, a00, -si * a10), r10 = fmaf(si, a00, ci_ * a10);
                float r01 = fmaf(ci_, a01, -si * a11), r11 = fmaf(si, a01, ci_ * a11);
                A[pj * LDC + pi] = fmaf(cj, r00, -sj * r01);
                A[qj * LDC + pi] = fmaf(sj, r00,  cj * r01);
                A[pj * LDC + qi] = fmaf(cj, r10, -sj * r11);
                A[qj * LDC + qi] = fmaf(sj, r10,  cj * r11);
            }
        }
        #pragma unroll
        for (int i = 0; i < NS; i++) {
            float rv = __shfl_sync(FULLM, v[i], prt);
            v[i] = fmaf(cc, v[i], bb * rv);
        }
        __syncwarp();
    }

    if (lane < NS) {
        float4* Vc = (float4*)(w->V + lane * LDC);
        #pragma unroll
        for (int t = 0; t < NS / 4; t++)
            Vc[t] = make_float4(v[4*t], v[4*t+1], v[4*t+2], v[4*t+3]);
    }
    __syncwarp();
}

// Paired 15x15 Jacobi: two matrices per warp (half = lane>>4, column = lane&15).
template<int SWEEPS>
__device__ void jacobi_pair15(PairWS* w, int lane) {
    constexpr int MP = 15, NPP = 8;
    int half = lane >> 4, l16 = lane & 15;
    float* A = w->buf + half * HSTRIDE;
    float4* prmh = w->prm + half * 8;

    float v[16];
    #pragma unroll
    for (int i = 0; i < 16; i++) v[i] = (i == l16) ? 1.0f : 0.0f;

    for (int sw = 0; sw < SWEEPS; sw++)
    for (int r = 0; r < MP; r++) {
        if (l16 < NPP) {
            int p, q; pair_pq(l16, r, MP, p, q);
            float c, s;
            jrot_fast(A[p * LDC + p], A[q * LDC + q], A[q * LDC + p], c, s);
            prmh[l16] = make_float4(c, s, __int_as_float(p), __int_as_float(q));
        }
        __syncwarp();
        int k, prt; float sgn;
        if (l16 == 0) {
            k = 0; prt = 1 + (MP - 1 + r) % MP; sgn = -1.0f;
        } else {
            int j = l16 - 1 - r; j %= MP; if (j < 0) j += MP;
            int kp = j + 1;
            if (kp <= NPP - 1) {
                k = kp; prt = 1 + (MP - 1 - k + r) % MP; sgn = -1.0f;
            } else {
                k = (MP + r - l16) % MP;
                prt = (k == 0) ? 0 : 1 + (k - 1 + r) % MP;
                sgn = 1.0f;
            }
        }
        float4 pk = prmh[k];
        float cc = pk.x, bb = sgn * pk.y;
        int src = (half << 4) | prt;
        #pragma unroll
        for (int t = 0; t < 4; t++) {
            int idx = lane + 32 * t;
            int h2 = idx >> 6, tile = idx & 63;
            int ki = tile >> 3, kj = tile & 7;
            const float4* prr = w->prm + h2 * 8;
            float* Ah = w->buf + h2 * HSTRIDE;
            float4 pi4 = prr[ki], pj4 = prr[kj];
            float ci_ = pi4.x, si = pi4.y;
            int pi = __float_as_int(pi4.z), qi = __float_as_int(pi4.w);
            float cj = pj4.x, sj = pj4.y;
            int pj = __float_as_int(pj4.z), qj = __float_as_int(pj4.w);
            float a00 = Ah[pj * LDC + pi], a01 = Ah[qj * LDC + pi];
            float a10 = Ah[pj * LDC + qi], a11 = Ah[qj * LDC + qi];
            float r00 = fmaf(ci_, a00, -si * a10), r10 = fmaf(si, a00, ci_ * a10);
            float r01 = fmaf(ci_, a01, -si * a11), r11 = fmaf(si, a01, ci_ * a11);
            Ah[pj * LDC + pi] = fmaf(cj, r00, -sj * r01);
            Ah[qj * LDC + pi] = fmaf(sj, r00,  cj * r01);
            Ah[pj * LDC + qi] = fmaf(cj, r10, -sj * r11);
            Ah[qj * LDC + qi] = fmaf(sj, r10,  cj * r11);
        }
        #pragma unroll
        for (int i = 0; i < 16; i++) {
            float rv = __shfl_sync(FULLM, v[i], src);
            v[i] = fmaf(cc, v[i], bb * rv);
        }
        __syncwarp();
    }

    float dg = A[l16 * LDC + l16];
    __syncwarp();
    float* auxp = (float*)w->prm;
    auxp[half * 16 + l16] = dg;
    float4* Vc = (float4*)(A + l16 * LDC);
    #pragma unroll
    for (int t = 0; t < 4; t++)
        Vc[t] = make_float4(v[4*t], v[4*t+1], v[4*t+2], v[4*t+3]);
    __syncwarp();
}

// ---------- float4 dot / axpy helpers ----------
__device__ __forceinline__ float dot20(const float* row, const float* g) {
    const float4* r4 = (const float4*)row;
    float a = 0.0f;
    #pragma unroll
    for (int t = 0; t < 5; t++) {
        float4 x = r4[t];
        a = fmaf(x.x, g[4*t+0], a); a = fmaf(x.y, g[4*t+1], a);
        a = fmaf(x.z, g[4*t+2], a); a = fmaf(x.w, g[4*t+3], a);
    }
    return a;
}
__device__ __forceinline__ float dot16(const float* row, const float* g) {
    const float4* r4 = (const float4*)row;
    float a = 0.0f;
    #pragma unroll
    for (int t = 0; t < 4; t++) {
        float4 x = r4[t];
        a = fmaf(x.x, g[4*t+0], a); a = fmaf(x.y, g[4*t+1], a);
        a = fmaf(x.z, g[4*t+2], a); a = fmaf(x.w, g[4*t+3], a);
    }
    return a;
}
__device__ __forceinline__ void axpy20(float u, const float* col, float* l) {
    const float4* c4 = (const float4*)col;
    #pragma unroll
    for (int t = 0; t < 5; t++) {
        float4 x = c4[t];
        l[4*t+0] = fmaf(u, x.x, l[4*t+0]); l[4*t+1] = fmaf(u, x.y, l[4*t+1]);
        l[4*t+2] = fmaf(u, x.z, l[4*t+2]); l[4*t+3] = fmaf(u, x.w, l[4*t+3]);
    }
}
__device__ __forceinline__ void axpy16(float u, const float* col, float* l) {
    const float4* c4 = (const float4*)col;
    #pragma unroll
    for (int t = 0; t < 4; t++) {
        float4 x = c4[t];
        l[4*t+0] = fmaf(u, x.x, l[4*t+0]); l[4*t+1] = fmaf(u, x.y, l[4*t+1]);
        l[4*t+2] = fmaf(u, x.z, l[4*t+2]); l[4*t+3] = fmaf(u, x.w, l[4*t+3]);
    }
}

// scalar recompose for tiny kernels: Out[i*N+j] = sum_k V[i,k] fw[k] V[j,k]
template<int N>
__device__ __forceinline__ void recompose_cm(const float* V, const float* fw,
                                             float* Out, int lane) {
    #pragma unroll
    for (int t = 0; t < (N * N + 31) / 32; t++) {
        int idx = lane + 32 * t;
        if (idx < N * N) {
            int i = idx / N, j = idx - i * N;
            float acc = 0.0f;
            #pragma unroll
            for (int k = 0; k < N; k++)
                acc = fmaf(V[k * LDC + i] * fw[k], V[k * LDC + j], acc);
            Out[idx] = acc;
        }
    }
}

// ============ K1: per-sample logm(X) -> g_V2 (as L scratch) ============
__global__ void __launch_bounds__(256, 3) k_logsum(const float* __restrict__ X, int B) {
    __shared__ WarpWS ws[WPB];
    int tid = threadIdx.x, warp = tid >> 5, lane = tid & 31;
    WarpWS* w = &ws[warp];
    for (int m = 0; m < MPW; m++) {
        int b = ((int)blockIdx.x * WPB + warp) * MPW + m;
        if (b >= B) continue;
        const float4* Xb4 = (const float4*)(X + (size_t)b * 400);
        for (int idx = lane; idx < 100; idx += 32) ((float4*)w->V)[idx] = Xb4[idx];
        __syncwarp();
        if (lane < 20) {
            float* Ac = w->A + lane * 20;     // lower-square: (lane, i<=lane) at lane*20+i
            #pragma unroll
            for (int i = 0; i < 20; i++)
                if (i <= lane) Ac[i] = w->V[i * 20 + lane];
        }
        jacobi_lsq20<SW_AVG20>(w, lane);
        if (lane < 20) w->aux[lane] = __logf(w->A[lane * 21]);
        __syncwarp();
        if (lane < 20) {
            float l[20];
            #pragma unroll
            for (int i = 0; i < 20; i++) l[i] = 0.0f;
            #pragma unroll
            for (int k = 0; k < 20; k++) {
                float u = w->aux[k] * w->V[k * LDC + lane];
                axpy20(u, w->V + k * LDC, l);
            }
            float4* Lb = (float4*)(g_V2 + (size_t)b * 400 + lane * 20);
            #pragma unroll
            for (int t = 0; t < 5; t++)
                Lb[t] = make_float4(l[4*t], l[4*t+1], l[4*t+2], l[4*t+3]);
        }
        __syncwarp();
    }
}

// ===== K1b: deterministic domain-segmented sum of L over samples =====
__global__ void __launch_bounds__(256) kr_dsum(const int* __restrict__ dom, int B) {
    int warp = threadIdx.x >> 5, lane = threadIdx.x & 31;
    int c = blockIdx.x & 3;
    int split = ((int)blockIdx.x >> 2) * 8 + warp;
    int per = (B + NSPLIT - 1) / NSPLIT;
    int b0 = split * per, b1 = b0 + per;
    if (b1 > B) b1 = B;
    int e = c * 128 + lane * 4;
    bool valid = e < 400;
    float4 a0 = make_float4(0,0,0,0), a1 = a0, a2 = a0, a3 = a0;
    int cnt0 = 0, cnt1 = 0, cnt2 = 0, cnt3 = 0;
    for (int b = b0; b < b1; b++) {
        int d = dom[b];
        float4 v = make_float4(0,0,0,0);
        if (valid) v = *(const float4*)(g_V2 + (size_t)b * 400 + e);
        if (d == 0)      { a0.x += v.x; a0.y += v.y; a0.z += v.z; a0.w += v.w; cnt0++; }
        else if (d == 1) { a1.x += v.x; a1.y += v.y; a1.z += v.z; a1.w += v.w; cnt1++; }
        else if (d == 2) { a2.x += v.x; a2.y += v.y; a2.z += v.z; a2.w += v.w; cnt2++; }
        else             { a3.x += v.x; a3.y += v.y; a3.z += v.z; a3.w += v.w; cnt3++; }
    }
    if (valid) {
        size_t base = (((size_t)c * NSPLIT + split) * NDOM) * 128 + lane * 4;
        *(float4*)(g_part2 + base + 0 * 128) = a0;
        *(float4*)(g_part2 + base + 1 * 128) = a1;
        *(float4*)(g_part2 + base + 2 * 128) = a2;
        *(float4*)(g_part2 + base + 3 * 128) = a3;
    }
    if (c == 0 && lane == 0) {
        g_partCnt[split * NDOM + 0] = (float)cnt0;
        g_partCnt[split * NDOM + 1] = (float)cnt1;
        g_partCnt[split * NDOM + 2] = (float)cnt2;
        g_partCnt[split * NDOM + 3] = (float)cnt3;
    }
}

// ============ K2: reduce partials -> meanL, counts; Ginv[d] = V e^{-w/2} Vt ============
__global__ void __launch_bounds__(256) k_ginv() {
    __shared__ WarpWS ws[4];
    __shared__ float meanL[NDOM * 400];
    int tid = threadIdx.x;
    if (tid < NDOM) {
        float c = 0.0f;
        for (int sp = 0; sp < NSPLIT; sp++) c += g_partCnt[sp * NDOM + tid];
        g_cnt[tid] = c;
    }
    for (int out = tid; out < NDOM * 400; out += 256) {
        int d = out / 400, e = out - d * 400;
        int c = e >> 7, i = e & 127;
        float s = 0.0f;
        for (int sp = 0; sp < NSPLIT; sp++)
            s += g_part2[(((size_t)c * NSPLIT + sp) * NDOM + d) * 128 + i];
        meanL[out] = s;
    }
    __syncthreads();
    int warp = tid >> 5, lane = tid & 31;
    if (warp < 4) {
        int d = warp;
        float inv = 1.0f / g_cnt[d];
        WarpWS* w = &ws[warp];
        for (int idx = lane; idx < 400; idx += 32)
            w->A[idx] = meanL[d * 400 + idx] * inv;
        __syncwarp();
        jacobi_cm<20, SW_SMALL>(w, lane);
        if (lane < 20) w->aux[lane] = __expf(-0.5f * w->A[lane * LDC + lane]);
        __syncwarp();
        recompose_cm<20>(w->V, w->aux, g_Ginv + d * 400, lane);
    }
}

// ====== K3: M = Gi X Gi, eigh -> store V,logw; per-domain sum ||logM||^2 ======
__global__ void __launch_bounds__(256, 3) k_center(const float* __restrict__ X,
                                                   const int* __restrict__ dom, int B) {
    __shared__ float Gi[NDOM * 400];
    __shared__ float nrmAcc[WPB][NDOM];
    __shared__ WarpWS ws[WPB];
    int tid = threadIdx.x, warp = tid >> 5, lane = tid & 31;
    for (int idx = tid; idx < NDOM * 400; idx += 256) Gi[idx] = g_Ginv[idx];
    if (tid < WPB * NDOM) ((float*)nrmAcc)[tid] = 0.0f;
    __syncthreads();
    WarpWS* w = &ws[warp];
    for (int m = 0; m < MPW; m++) {
        int b = ((int)blockIdx.x * WPB + warp) * MPW + m;
        if (b < B) {
            int d = dom[b];
            const float* G = Gi + d * 400;
            const float4* Xb4 = (const float4*)(X + (size_t)b * 400);
            for (int idx = lane; idx < 100; idx += 32)
                ((float4*)w->V)[idx] = Xb4[idx];
            __syncwarp();
            float res[20];
            if (lane < 20) {
                float g[20];
                #pragma unroll
                for (int k = 0; k < 20; k++) g[k] = G[k * 20 + lane];
                float y[20];
                #pragma unroll
                for (int i = 0; i < 20; i++) y[i] = dot20(w->V + i * 20, g);
                #pragma unroll
                for (int i = 0; i < 20; i++) res[i] = dot20(G + i * 20, y);
            }
            __syncwarp();   // X reads done before jacobi spill clobbers V
            if (lane < 20) {
                float* Ac = w->A + lane * 20;   // lower-square pack
                #pragma unroll
                for (int i = 0; i < 20; i++)
                    if (i <= lane) Ac[i] = res[i];
            }
            jacobi_lsq20<SW_PS20>(w, lane);
            if (lane < 20) w->aux[lane] = __logf(w->A[lane * 21]);
            __syncwarp();
            float4* gV4 = (float4*)(g_V2 + (size_t)b * 400);
            for (int idx = lane; idx < 100; idx += 32) gV4[idx] = ((float4*)w->V)[idx];
            if (lane < 20) g_lw2[(size_t)b * 20 + lane] = w->aux[lane];
            float v = (lane < 20) ? w->aux[lane] * w->aux[lane] : 0.0f;
            #pragma unroll
            for (int off = 16; off; off >>= 1) v += __shfl_down_sync(FULLM, v, off);
            if (lane == 0) nrmAcc[warp][d] += v;
        }
    }
    __syncthreads();
    if (tid == 0) {
        float sums[NDOM] = {0.f, 0.f, 0.f, 0.f};
        for (int t = 0; t < WPB; t++)
            for (int d = 0; d < NDOM; d++) sums[d] += nrmAcc[t][d];
        for (int d = 0; d < NDOM; d++) g_partN[blockIdx.x * NDOM + d] = sums[d];
    }
}

// ============ K4: scale[d] = s / sqrt(sig2 + eps) ============
__global__ void __launch_bounds__(128) k_scale(const float* __restrict__ sptr, int NB) {
    int warp = threadIdx.x >> 5, lane = threadIdx.x & 31;
    int d = warp;
    float nsum = 0.0f;
    for (int b = lane; b < NB; b += 32) nsum += g_partN[b * NDOM + d];
    #pragma unroll
    for (int off = 16; off; off >>= 1) nsum += __shfl_down_sync(FULLM, nsum, off);
    if (lane == 0) {
        float sig2 = nsum / g_cnt[d];
        g_scale[d] = sptr[0] / sqrtf(sig2 + EPS_VAR_F);
    }
}

// ====== K5 (PAIRED eigh): Xn via eigenbasis reuse, Y = Wt Xn W, store Y, sum logm(Y) ======
__global__ void __launch_bounds__(256) k_bimap(const float* __restrict__ Wb,
                                               const int* __restrict__ dom, int B) {
    __shared__ float Ws16[320];
    __shared__ float accW[WPB * 2 * 240];
    __shared__ PairWS ws[WPB];
    int tid = threadIdx.x, warp = tid >> 5, lane = tid & 31;
    int half = lane >> 4, l16 = lane & 15;
    for (int idx = tid; idx < 320; idx += 256) {
        int i = idx >> 4, o = idx & 15;
        Ws16[idx] = (o < 15) ? Wb[i * 15 + o] : 0.0f;
    }
    __syncthreads();
    PairWS* w = &ws[warp];
    float* bufh = w->buf + half * HSTRIDE;
    int base = ((int)blockIdx.x * WPB + warp) * MPW;
    float la[15];
    #pragma unroll
    for (int i = 0; i < 15; i++) la[i] = 0.0f;

    for (int mp = 0; mp < MPW / 2; mp++) {
        for (int h = 0; h < 2; h++) {
            int b = base + mp * 2 + h;
            float* bh = w->buf + h * HSTRIDE;
            if (b < B) {
                int d = dom[b];
                float sc = g_scale[d];
                const float* gV = g_V2 + (size_t)b * 400;
                float c[16];
                if (lane < 20) {
                    float ej = __expf(0.5f * sc * g_lw2[(size_t)b * 20 + lane]);
                    float z[20];
                    const float4* col4 = (const float4*)(gV + lane * 20);
                    #pragma unroll
                    for (int t = 0; t < 5; t++) {
                        float4 v = col4[t];
                        z[4*t+0] = v.x * ej; z[4*t+1] = v.y * ej;
                        z[4*t+2] = v.z * ej; z[4*t+3] = v.w * ej;
                    }
                    #pragma unroll
                    for (int o = 0; o < 16; o++) c[o] = 0.0f;
                    #pragma unroll
                    for (int i = 0; i < 20; i++) axpy16(z[i], Ws16 + i * 16, c);
                }
                __syncwarp();
                if (lane < 20) {
                    #pragma unroll
                    for (int o = 0; o < 15; o++) bh[o * 20 + lane] = c[o];
                }
                __syncwarp();
                float y[16];
                if (lane < 15) {
                    float cp[20];
                    const float4* row4 = (const float4*)(bh + lane * 20);
                    #pragma unroll
                    for (int t = 0; t < 5; t++) {
                        float4 v = row4[t];
                        cp[4*t+0] = v.x; cp[4*t+1] = v.y; cp[4*t+2] = v.z; cp[4*t+3] = v.w;
                    }
                    #pragma unroll
                    for (int o = 0; o < 15; o++) y[o] = dot20(bh + o * 20, cp);
                    y[15] = 0.0f;
                }
                __syncwarp();
                if (lane < 15) {
                    float4* Ac = (float4*)(bh + lane * LDC);
                    float4* gY4 = (float4*)(g_Y + (size_t)b * 240 + lane * 16);
                    #pragma unroll
                    for (int t = 0; t < 4; t++) {
                        float4 v = make_float4(y[4*t], y[4*t+1], y[4*t+2], y[4*t+3]);
                        Ac[t] = v;
                        gY4[t] = v;
                    }
                } else if (lane == 15) {
                    float4* Ac = (float4*)(bh + 15 * LDC);
                    #pragma unroll
                    for (int t = 0; t < 4; t++) Ac[t] = make_float4(0, 0, 0, 0);
                }
            } else {
                for (int idx = lane; idx < 320; idx += 32) bh[idx] = 0.0f;
            }
            __syncwarp();
        }
        jacobi_pair15<SW_AVG15>(w, lane);
        int bsel = base + mp * 2 + half;
        bool act = (bsel < B);
        float* auxp = (float*)w->prm;
        float dg = auxp[half * 16 + l16];
        auxp[half * 16 + l16] = act ? __logf(dg) : 0.0f;
        __syncwarp();
        if (l16 < 15 && act) {
            const float* aux = auxp + half * 16;
            float l[16];
            #pragma unroll
            for (int i = 0; i < 16; i++) l[i] = 0.0f;
            #pragma unroll
            for (int k = 0; k < 15; k++) {
                float u = aux[k] * bufh[k * LDC + l16];
                axpy16(u, bufh + k * LDC, l);
            }
            #pragma unroll
            for (int i = 0; i < 15; i++) la[i] += l[i];
        }
        __syncwarp();
    }
    if (l16 < 15) {
        float* dst = accW + (warp * 2 + half) * 240;
        #pragma unroll
        for (int i = 0; i < 15; i++) dst[i * 16 + l16] = la[i];
    }
    __syncthreads();
    for (int idx = tid; idx < 225; idx += 256) {
        int i = idx / 15, j = idx - i * 15;
        float s = 0.0f;
        #pragma unroll
        for (int wp = 0; wp < WPB * 2; wp++) s += accW[wp * 240 + i * 16 + j];
        g_partLY[(size_t)blockIdx.x * 225 + idx] = s;
    }
}

// ============ K6: meanLY -> Gb = V e^{-w/2} Vt (padded 15x16) ============
__global__ void __launch_bounds__(256) k_gb(int B, int NB) {
    __shared__ float meanLY[225];
    __shared__ WarpWS ws0;
    int tid = threadIdx.x, warp = tid >> 5, lane = tid & 31;
    float invB = 1.0f / (float)B;
    for (int out = warp; out < 225; out += 8) {
        float s = 0.0f;
        for (int b = lane; b < NB; b += 32) s += g_partLY[(size_t)b * 225 + out];
        #pragma unroll
        for (int off = 16; off; off >>= 1) s += __shfl_down_sync(FULLM, s, off);
        if (lane == 0) meanLY[out] = s * invB;
    }
    __syncthreads();
    if (warp == 0) {
        for (int idx = lane; idx < 320; idx += 32) ws0.A[idx] = 0.0f;
        __syncwarp();
        for (int idx = lane; idx < 225; idx += 32) {
            int i = idx / 15, j = idx - i * 15;
            ws0.A[j * LDC + i] = meanLY[idx];
        }
        __syncwarp();
        jacobi_cm<15, SW_SMALL>(&ws0, lane);
        if (lane < 15) ws0.aux[lane] = __expf(-0.5f * ws0.A[lane * LDC + lane]);
        __syncwarp();
        for (int t = 0; t < 8; t++) {
            int idx = lane + 32 * t;
            if (idx < 240) {
                int i = idx >> 4, j = idx & 15;
                float acc = 0.0f;
                if (j < 15) {
                    #pragma unroll
                    for (int k = 0; k < 15; k++)
                        acc = fmaf(ws0.V[k * LDC + i] * ws0.aux[k], ws0.V[k * LDC + j], acc);
                }
                g_Gb16[idx] = acc;
            }
        }
    }
}

// ====== K7 (PAIRED): Yn = Gb Y Gb, eigh, fused ReEig+LogEig+vec+classifier ======
__global__ void __launch_bounds__(256) k_head(const float* __restrict__ Wl,
                                              float* __restrict__ out, int B) {
    __shared__ float Gbs[240];
    __shared__ float Wf[4 * 240];
    __shared__ PairWS ws[WPB];
    int tid = threadIdx.x, warp = tid >> 5, lane = tid & 31;
    int half = lane >> 4, l16 = lane & 15;
    for (int i = tid; i < 240; i += 256) Gbs[i] = g_Gb16[i];
    for (int idx = tid; idx < 960; idx += 256) {
        int cc = idx / 240, rem = idx - cc * 240;
        int i = rem >> 4, j = rem & 15;
        float v = 0.0f;
        if (i < 15 && j < 15) {
            if (i == j) v = Wl[cc * 120 + i];
            else {
                int a = min(i, j), b2 = max(i, j);
                int off = a * 14 - a * (a - 1) / 2 + (b2 - a - 1);
                v = Wl[cc * 120 + 15 + off] * (SQRT2F * 0.5f);
            }
        }
        Wf[idx] = v;
    }
    __syncthreads();
    PairWS* w = &ws[warp];
    float* bufh = w->buf + half * HSTRIDE;
    int base = ((int)blockIdx.x * WPB + warp) * MPW;

    for (int mp = 0; mp < MPW / 2; mp++) {
        int b = base + mp * 2 + half;
        bool active = (b < B);
        if (active) {
            const float4* gY4 = (const float4*)(g_Y + (size_t)b * 240);
            for (int idx = l16; idx < 60; idx += 16) ((float4*)bufh)[idx] = gY4[idx];
        } else {
            for (int idx = l16; idx < 60; idx += 16) ((float4*)bufh)[idx] = make_float4(0,0,0,0);
        }
        __syncwarp();
        float res[16];
        if (l16 < 15) {
            float g[16];
            #pragma unroll
            for (int k = 0; k < 15; k++) g[k] = Gbs[k * 16 + l16];
            g[15] = 0.0f;
            float y[16];
            #pragma unroll
            for (int i = 0; i < 15; i++) y[i] = dot16(bufh + i * 16, g);
            y[15] = 0.0f;
            #pragma unroll
            for (int i = 0; i < 15; i++) res[i] = dot16(Gbs + i * 16, y);
            res[15] = 0.0f;
        }
        __syncwarp();
        {
            float4* Ac = (float4*)(bufh + l16 * LDC);
            if (l16 < 15) {
                #pragma unroll
                for (int t = 0; t < 4; t++)
                    Ac[t] = make_float4(res[4*t], res[4*t+1], res[4*t+2], res[4*t+3]);
            } else {
                #pragma unroll
                for (int t = 0; t < 4; t++) Ac[t] = make_float4(0, 0, 0, 0);
            }
        }
        jacobi_pair15<SW_PS15>(w, lane);
        float* auxp = (float*)w->prm;
        auxp[half * 16 + l16] = __logf(fmaxf(auxp[half * 16 + l16], EPS_REEIG_F));
        __syncwarp();
        float o0 = 0.f, o1 = 0.f, o2 = 0.f, o3 = 0.f;
        if (l16 < 15) {
            const float* aux = auxp + half * 16;
            float l[16];
            #pragma unroll
            for (int i = 0; i < 16; i++) l[i] = 0.0f;
            #pragma unroll
            for (int k = 0; k < 15; k++) {
                float u = aux[k] * bufh[k * LDC + l16];
                axpy16(u, bufh + k * LDC, l);
            }
            #pragma unroll
            for (int i = 0; i < 15; i++) {
                float li = l[i];
                o0 = fmaf(Wf[0 * 240 + i * 16 + l16], li, o0);
                o1 = fmaf(Wf[1 * 240 + i * 16 + l16], li, o1);
                o2 = fmaf(Wf[2 * 240 + i * 16 + l16], li, o2);
                o3 = fmaf(Wf[3 * 240 + i * 16 + l16], li, o3);
            }
        }
        #pragma unroll
        for (int off = 8; off; off >>= 1) {
            o0 += __shfl_down_sync(FULLM, o0, off);
            o1 += __shfl_down_sync(FULLM, o1, off);
            o2 += __shfl_down_sync(FULLM, o2, off);
            o3 += __shfl_down_sync(FULLM, o3, off);
        }
        if (l16 == 0 && active) {
            float* ob = out + (size_t)b * 4;
            ob[0] = o0; ob[1] = o1; ob[2] = o2; ob[3] = o3;
        }
        __syncwarp();
    }
}

extern "C" void kernel_launch(void* const* d_in, const int* in_sizes, int n_in,
                              void* d_out, int out_size) {
    const float* X   = (const float*)d_in[0];
    const int*   dom = (const int*)d_in[1];
    const float* s   = (const float*)d_in[2];
    const float* Wb  = (const float*)d_in[3];
    const float* Wl  = (const float*)d_in[4];
    float* out = (float*)d_out;
    int B = in_sizes[0] / 400;
    if (B > MAXB) B = MAXB;
    int NB = (B + MPB - 1) / MPB;
    if (NB > NB_MAX) NB = NB_MAX;

    k_logsum<<<NB, 256>>>(X, B);
    kr_dsum<<<NCHUNK * (NSPLIT / 8), 256>>>(dom, B);
    k_ginv<<<1, 256>>>();
    k_center<<<NB, 256>>>(X, dom, B);
    k_scale<<<1, 128>>>(s, NB);
    k_bimap<<<NB, 256>>>(Wb, dom, B);
    k_gb<<<1, 256>>>(B, NB);
    k_head<<<NB, 256>>>(Wl, out, B);
}